// round 6
// baseline (speedup 1.0000x reference)
#include <cuda_runtime.h>
#include <math.h>
#include <float.h>
#include <stdint.h>

#define N       16384
#define DIN     13
#define KNN     8
#define NBIN    1024
#define CHUNKJ  128              // j per chunk
#define NCHUNK  (N / CHUNKJ)     // 128
#define TPC     16               // 8-j tiles per chunk
#define QBLK    256              // queries per block group
#define PSPLIT  4                // chunk-parity split -> 4 partial lists
#define KTH     256

typedef unsigned long long ull;

// ---- scratch (no allocs allowed) ----
__device__ float g_x[N * 16];            // embedded points (original order)
__device__ float g_sq[N];
__device__ float g_key[N];               // last coordinate
__device__ int   g_hist[NBIN];
__device__ int   g_off[NBIN];
__device__ float g_px[N * 16];           // permuted points
__device__ float g_psq[N];
__device__ int   g_pidx[N];              // sorted pos -> original index
__device__ ulonglong2 g_pp2[(N / 2) * 8];// pair-packed permuted points
__device__ ull   g_psq2[N / 2];          // pair-packed sq
__device__ float g_tlo[N / 8], g_thi[N / 8];   // per-8j-tile key bounds
__device__ float g_clo[NCHUNK], g_chi[NCHUNK]; // per-chunk key bounds
__device__ float g_pd[N * PSPLIT * KNN];
__device__ int   g_pi[N * PSPLIT * KNN];
__device__ int   g_idx[N * KNN];
__device__ float g_feats[N * 16];

__device__ __forceinline__ float silu_f(float v) { return v / (1.0f + expf(-v)); }
__device__ __forceinline__ float silu_fast(float v) { return __fdividef(v, 1.0f + __expf(-v)); }

__device__ __forceinline__ ull pack2(float lo, float hi) {
    ull p; asm("mov.b64 %0, {%1, %2};" : "=l"(p) : "f"(lo), "f"(hi)); return p;
}
__device__ __forceinline__ ull fma2(ull a, ull b, ull c) {
    ull d; asm("fma.rn.f32x2 %0, %1, %2, %3;" : "=l"(d) : "l"(a), "l"(b), "l"(c)); return d;
}
__device__ __forceinline__ ull mul2(ull a, ull b) {
    ull d; asm("mul.rn.f32x2 %0, %1, %2;" : "=l"(d) : "l"(a), "l"(b)); return d;
}
__device__ __forceinline__ ull add2(ull a, ull b) {
    ull d; asm("add.rn.f32x2 %0, %1, %2;" : "=l"(d) : "l"(a), "l"(b)); return d;
}
__device__ __forceinline__ void unpack2(ull s, float& lo, float& hi) {
    asm("mov.b64 {%0, %1}, %2;" : "=f"(lo), "=f"(hi) : "l"(s));
}
__device__ __forceinline__ int keybin(float k) {
    int b = (int)((k + 5.0f) * (NBIN / 10.0f));
    return b < 0 ? 0 : (b > NBIN - 1 ? NBIN - 1 : b);
}

// ============================================================
// Kernel 1: per-point MLP -> x, sq, key
// ============================================================
__global__ void mlp_kernel(const float* __restrict__ xp,
                           const float* __restrict__ W1, const float* __restrict__ b1,
                           const float* __restrict__ W2, const float* __restrict__ b2,
                           const float* __restrict__ W3, const float* __restrict__ b3)
{
    __shared__ float sW1[DIN * 8], sb1[8];
    __shared__ float sW2[8 * 16],  sb2[16];
    __shared__ float sW3[16 * 15], sb3[15];

    int t = threadIdx.x;
    for (int i = t; i < DIN * 8; i += blockDim.x) sW1[i] = W1[i];
    for (int i = t; i < 8;       i += blockDim.x) sb1[i] = b1[i];
    for (int i = t; i < 8 * 16;  i += blockDim.x) sW2[i] = W2[i];
    for (int i = t; i < 16;      i += blockDim.x) sb2[i] = b2[i];
    for (int i = t; i < 16 * 15; i += blockDim.x) sW3[i] = W3[i];
    for (int i = t; i < 15;      i += blockDim.x) sb3[i] = b3[i];
    __syncthreads();

    int i = blockIdx.x * blockDim.x + t;
    if (i >= N) return;

    float in[DIN];
    #pragma unroll
    for (int d = 0; d < DIN; ++d) in[d] = xp[i * DIN + d];

    float h1[8];
    #pragma unroll
    for (int h = 0; h < 8; ++h) {
        float a = sb1[h];
        #pragma unroll
        for (int d = 0; d < DIN; ++d) a = fmaf(in[d], sW1[d * 8 + h], a);
        h1[h] = silu_f(a);
    }
    float h2[16];
    #pragma unroll
    for (int h = 0; h < 16; ++h) {
        float a = sb2[h];
        #pragma unroll
        for (int d = 0; d < 8; ++d) a = fmaf(h1[d], sW2[d * 16 + h], a);
        h2[h] = silu_f(a);
    }
    float xr[16];
    #pragma unroll
    for (int h = 0; h < 15; ++h) {
        float a = sb3[h];
        #pragma unroll
        for (int d = 0; d < 16; ++d) a = fmaf(h2[d], sW3[d * 15 + h], a);
        xr[h] = a;
    }
    xr[15] = in[DIN - 1];

    float s = 0.0f;
    #pragma unroll
    for (int k = 0; k < 16; ++k) s = fmaf(xr[k], xr[k], s);

    #pragma unroll
    for (int k = 0; k < 16; ++k) g_x[i * 16 + k] = xr[k];
    g_sq[i]  = s;
    g_key[i] = xr[15];
}

// ============================================================
// Sorting infrastructure (bucket sort by last coordinate)
// ============================================================
__global__ void zeroh_kernel() { g_hist[threadIdx.x] = 0; }

__global__ void hist_kernel() {
    int i = blockIdx.x * blockDim.x + threadIdx.x;
    atomicAdd(&g_hist[keybin(g_key[i])], 1);
}

__global__ void scan_kernel() {
    __shared__ int sh[NBIN];
    int t = threadIdx.x;
    int v = g_hist[t];
    sh[t] = v;
    __syncthreads();
    // Hillis-Steele inclusive scan
    for (int off = 1; off < NBIN; off <<= 1) {
        int add = (t >= off) ? sh[t - off] : 0;
        __syncthreads();
        sh[t] += add;
        __syncthreads();
    }
    g_off[t] = sh[t] - v;   // exclusive
}

__global__ void scatter_kernel() {
    int i = blockIdx.x * blockDim.x + threadIdx.x;
    int b = keybin(g_key[i]);
    int pos = atomicAdd(&g_off[b], 1);
    #pragma unroll
    for (int d = 0; d < 16; ++d) g_px[pos * 16 + d] = g_x[i * 16 + d];
    g_psq[pos]  = g_sq[i];
    g_pidx[pos] = i;
}

__global__ void pack_kernel() {
    int u = blockIdx.x * blockDim.x + threadIdx.x;  // 0 .. N/2*16-1
    int jp = u >> 4, d = u & 15;
    ((ull*)g_pp2)[u] = pack2(g_px[(2 * jp) * 16 + d], g_px[(2 * jp + 1) * 16 + d]);
    if (u < N / 2) g_psq2[u] = pack2(g_psq[2 * u], g_psq[2 * u + 1]);
}

__global__ void tbounds_kernel() {
    int tt = blockIdx.x * blockDim.x + threadIdx.x;   // tile id, 2048
    float lo = FLT_MAX, hi = -FLT_MAX;
    #pragma unroll
    for (int r = 0; r < 8; ++r) {
        float k = g_px[(tt * 8 + r) * 16 + 15];
        lo = fminf(lo, k); hi = fmaxf(hi, k);
    }
    g_tlo[tt] = lo; g_thi[tt] = hi;
}

__global__ void cbounds_kernel() {
    int c = threadIdx.x;   // 128
    float lo = FLT_MAX, hi = -FLT_MAX;
    #pragma unroll
    for (int r = 0; r < TPC; ++r) {
        lo = fminf(lo, g_tlo[c * TPC + r]);
        hi = fmaxf(hi, g_thi[c * TPC + r]);
    }
    g_clo[c] = lo; g_chi[c] = hi;
}

// ============================================================
// Kernel 2: pruned KNN. grid = (N/QBLK)*PSPLIT CTAs x 256 threads.
// ============================================================
__global__ void __launch_bounds__(KTH, 2) knn_kernel()
{
    __shared__ __align__(16) ull spp[64 * 16];   // 8KB: 64 pairs x 16 dims
    __shared__ ull   ssq2[64];
    __shared__ int   sjid[CHUNKJ];
    __shared__ float stlo[TPC], sthi[TPC];

    const int t      = threadIdx.x;
    const int blk    = blockIdx.x >> 2;
    const int parity = blockIdx.x & 3;
    const int p      = blk * QBLK + t;           // sorted query position

    // query (packed -2x in both lanes)
    ull xi2[16];
    float qk, sqi;
    {
        const float* xr = g_px + (size_t)p * 16;
        #pragma unroll
        for (int d = 0; d < 16; ++d) {
            float v = -2.0f * xr[d];
            xi2[d] = pack2(v, v);
        }
        qk  = xr[15];
        sqi = g_psq[p];
    }

    float td[KNN]; int ti[KNN];
    #pragma unroll
    for (int k = 0; k < KNN; ++k) { td[k] = FLT_MAX; ti[k] = 0x7fffffff; }

    const int c0 = blk * 2;   // chunk near this query block

    for (int s = 0; s < NCHUNK / PSPLIT; ++s) {
        const int c = (c0 + parity + PSPLIT * s) & (NCHUNK - 1);

        // chunk-level exact lower-bound test
        float clo = g_clo[c], chi = g_chi[c];
        float dd  = fmaxf(fmaxf(clo - qk, qk - chi), 0.0f);
        float thr = td[KNN - 1] + 1e-5f + 1e-5f * fabsf(td[KNN - 1]);
        int need  = (dd * dd - sqi) <= thr;
        if (!__syncthreads_or(need)) continue;

        // stage chunk
        {
            const ulonglong2* gp = g_pp2 + (size_t)c * 512;
            ulonglong2* sp = (ulonglong2*)spp;
            #pragma unroll
            for (int u = t; u < 512; u += KTH) sp[u] = gp[u];
            if (t < 64)  ssq2[t] = g_psq2[c * 64 + t];
            if (t < CHUNKJ) sjid[t] = g_pidx[c * CHUNKJ + t];
            if (t >= CHUNKJ && t < CHUNKJ + TPC) {
                stlo[t - CHUNKJ] = g_tlo[c * TPC + (t - CHUNKJ)];
                sthi[t - CHUNKJ] = g_thi[c * TPC + (t - CHUNKJ)];
            }
        }
        __syncthreads();

        #pragma unroll 1
        for (int nt = 0; nt < TPC; ++nt) {
            float lo = stlo[nt], hi = sthi[nt];
            float d1 = fmaxf(fmaxf(lo - qk, qk - hi), 0.0f);
            float th = td[KNN - 1] + 1e-5f + 1e-5f * fabsf(td[KNN - 1]);
            int nd = (d1 * d1 - sqi) <= th;
            if (!__any_sync(0xffffffffu, nd)) continue;

            float d2v[8];
            #pragma unroll
            for (int jp = 0; jp < 4; ++jp) {
                const ulonglong2* vp = (const ulonglong2*)(spp + (nt * 4 + jp) * 16);
                ulonglong2 v0 = vp[0], v1 = vp[1], v2 = vp[2], v3 = vp[3];
                ulonglong2 v4 = vp[4], v5 = vp[5], v6 = vp[6], v7 = vp[7];
                ull a = fma2(xi2[0],  v0.x, ssq2[nt * 4 + jp]);
                a = fma2(xi2[1],  v0.y, a);
                a = fma2(xi2[2],  v1.x, a);
                a = fma2(xi2[3],  v1.y, a);
                a = fma2(xi2[4],  v2.x, a);
                a = fma2(xi2[5],  v2.y, a);
                a = fma2(xi2[6],  v3.x, a);
                a = fma2(xi2[7],  v3.y, a);
                ull b = mul2(xi2[8],  v4.x);
                b = fma2(xi2[9],  v4.y, b);
                b = fma2(xi2[10], v5.x, b);
                b = fma2(xi2[11], v5.y, b);
                b = fma2(xi2[12], v6.x, b);
                b = fma2(xi2[13], v6.y, b);
                b = fma2(xi2[14], v7.x, b);
                b = fma2(xi2[15], v7.y, b);
                unpack2(add2(a, b), d2v[2 * jp], d2v[2 * jp + 1]);
            }

            // deferred selection: min-tree then rare insertion
            float m01 = fminf(d2v[0], d2v[1]);
            float m23 = fminf(d2v[2], d2v[3]);
            float m45 = fminf(d2v[4], d2v[5]);
            float m67 = fminf(d2v[6], d2v[7]);
            float m = fminf(fminf(m01, m23), fminf(m45, m67));
            if (m <= td[KNN - 1]) {
                #pragma unroll
                for (int e = 0; e < 8; ++e) {
                    float d = d2v[e];
                    if (d < td[KNN - 1] ||
                        (d == td[KNN - 1] && sjid[nt * 8 + e] < ti[KNN - 1])) {
                        td[KNN - 1] = d;
                        ti[KNN - 1] = sjid[nt * 8 + e];
                        #pragma unroll
                        for (int q = KNN - 1; q >= 1; --q) {
                            if (td[q] < td[q - 1] ||
                                (td[q] == td[q - 1] && ti[q] < ti[q - 1])) {
                                float tf = td[q]; td[q] = td[q-1]; td[q-1] = tf;
                                int   tn = ti[q]; ti[q] = ti[q-1]; ti[q-1] = tn;
                            }
                        }
                    }
                }
            }
        }
        __syncthreads();
    }

    // write partial list (indices already ORIGINAL)
    {
        int base = (p * PSPLIT + parity) * KNN;
        #pragma unroll
        for (int k = 0; k < KNN; ++k) {
            g_pd[base + k] = td[k];
            g_pi[base + k] = ti[k];
        }
    }
}

// ============================================================
// Kernel 3: merge PSPLIT partial lists -> final indices
// ============================================================
__global__ void merge_kernel()
{
    int p = blockIdx.x * blockDim.x + threadIdx.x;
    if (p >= N) return;

    float d[PSPLIT * KNN];
    int   ix[PSPLIT * KNN];
    #pragma unroll
    for (int u = 0; u < PSPLIT * KNN; ++u) {
        d[u]  = g_pd[p * PSPLIT * KNN + u];
        ix[u] = g_pi[p * PSPLIT * KNN + u];
    }
    int oi = g_pidx[p];
    #pragma unroll
    for (int k = 0; k < KNN; ++k) {
        float bd = FLT_MAX; int bi = 0x7fffffff; int bu = 0;
        #pragma unroll
        for (int u = 0; u < PSPLIT * KNN; ++u) {
            if (d[u] < bd || (d[u] == bd && ix[u] < bi)) {
                bd = d[u]; bi = ix[u]; bu = u;
            }
        }
        g_idx[oi * KNN + k] = bi;
        d[bu] = FLT_MAX; ix[bu] = 0x7fffffff;
    }
}

// ============================================================
// Kernel 4a: edge messages + mean (thread = (point, channel))
// ============================================================
__global__ void __launch_bounds__(256)
feats_kernel(const float* __restrict__ We, const float* __restrict__ be)
{
    __shared__ float sWd[16 * 16];
    __shared__ float sWb[16 * 16];
    __shared__ float sbe[16];
    __shared__ float sxi[16 * 16];
    __shared__ int   sj[16 * KNN];
    __shared__ float sxj[16 * KNN * 16];

    const int t  = threadIdx.x;
    const int i0 = blockIdx.x * 16;

    {
        float top = We[t];
        float bot = We[256 + t];
        sWd[t] = top - bot;
        sWb[t] = bot;
    }
    if (t < 16) sbe[t] = be[t];
    sxi[t] = g_x[i0 * 16 + t];
    if (t < 16 * KNN) sj[t] = g_idx[i0 * KNN + t];
    __syncthreads();

    {
        const float4* gx4 = (const float4*)g_x;
        float4* sxj4 = (float4*)sxj;
        #pragma unroll
        for (int u = t; u < 16 * KNN * 4; u += 256) {
            int row = u >> 2, seg = u & 3;
            sxj4[u] = gx4[sj[row] * 4 + seg];
        }
    }
    __syncthreads();

    const int pp = t >> 4;
    const int h  = t & 15;
    const int i  = i0 + pp;

    float pre = sbe[h];
    #pragma unroll
    for (int d = 0; d < 16; ++d) pre = fmaf(sxi[pp * 16 + d], sWd[d * 16 + h], pre);

    float fsum = 0.0f;
    #pragma unroll
    for (int k = 0; k < KNN; ++k) {
        const float* xj = sxj + (pp * KNN + k) * 16;
        float m = pre;
        #pragma unroll
        for (int d = 0; d < 16; ++d) m = fmaf(xj[d], sWb[d * 16 + h], m);
        fsum += silu_fast(m);
    }

    g_feats[i * 16 + h] = fsum * 0.125f;
}

// ============================================================
// Kernel 4b: final MLP + concat output
// ============================================================
__global__ void __launch_bounds__(256)
out_kernel(const float* __restrict__ xp,
           const float* __restrict__ Wf1, const float* __restrict__ bf1,
           const float* __restrict__ Wf2, const float* __restrict__ bf2,
           float* __restrict__ out)
{
    __shared__ float sWf1[16 * 32], sbf1[32];
    __shared__ float sWf2[32 * 16], sbf2[16];

    int t = threadIdx.x;
    for (int u = t; u < 16 * 32; u += 256) sWf1[u] = Wf1[u];
    for (int u = t; u < 32;      u += 256) sbf1[u] = bf1[u];
    for (int u = t; u < 32 * 16; u += 256) sWf2[u] = Wf2[u];
    for (int u = t; u < 16;      u += 256) sbf2[u] = bf2[u];
    __syncthreads();

    int i = blockIdx.x * 256 + t;
    if (i >= N) return;

    float feats[16];
    const float4* gf4 = (const float4*)g_feats;
    #pragma unroll
    for (int s = 0; s < 4; ++s) {
        float4 v = gf4[i * 4 + s];
        feats[4*s+0] = v.x; feats[4*s+1] = v.y; feats[4*s+2] = v.z; feats[4*s+3] = v.w;
    }

    float f1[32];
    #pragma unroll
    for (int h = 0; h < 32; ++h) {
        float a = sbf1[h];
        #pragma unroll
        for (int d = 0; d < 16; ++d) a = fmaf(feats[d], sWf1[d * 32 + h], a);
        f1[h] = silu_fast(a);
    }
    float f2[16];
    #pragma unroll
    for (int h = 0; h < 16; ++h) {
        float a = sbf2[h];
        #pragma unroll
        for (int d = 0; d < 32; ++d) a = fmaf(f1[d], sWf2[d * 16 + h], a);
        f2[h] = a;
    }

    float* o = out + i * (16 + DIN);
    #pragma unroll
    for (int h = 0; h < 16; ++h) o[h] = f2[h];
    #pragma unroll
    for (int d = 0; d < DIN; ++d) o[16 + d] = xp[i * DIN + d];
}

// ============================================================
extern "C" void kernel_launch(void* const* d_in, const int* in_sizes, int n_in,
                              void* d_out, int out_size)
{
    const float* xp  = (const float*)d_in[0];
    const float* W1  = (const float*)d_in[1];
    const float* b1  = (const float*)d_in[2];
    const float* W2  = (const float*)d_in[3];
    const float* b2  = (const float*)d_in[4];
    const float* W3  = (const float*)d_in[5];
    const float* b3  = (const float*)d_in[6];
    const float* We  = (const float*)d_in[7];
    const float* be  = (const float*)d_in[8];
    const float* Wf1 = (const float*)d_in[9];
    const float* bf1 = (const float*)d_in[10];
    const float* Wf2 = (const float*)d_in[11];
    const float* bf2 = (const float*)d_in[12];
    float* out = (float*)d_out;

    mlp_kernel<<<N / 256, 256>>>(xp, W1, b1, W2, b2, W3, b3);
    zeroh_kernel<<<1, NBIN>>>();
    hist_kernel<<<N / 256, 256>>>();
    scan_kernel<<<1, NBIN>>>();
    scatter_kernel<<<N / 256, 256>>>();
    pack_kernel<<<(N / 2) * 16 / 256, 256>>>();
    tbounds_kernel<<<(N / 8) / 256, 256>>>();
    cbounds_kernel<<<1, NCHUNK>>>();
    knn_kernel<<<(N / QBLK) * PSPLIT, KTH>>>();
    merge_kernel<<<N / 128, 128>>>();
    feats_kernel<<<N / 16, 256>>>(We, be);
    out_kernel<<<N / 256, 256>>>(xp, Wf1, bf1, Wf2, bf2, out);
}

// round 7
// speedup vs baseline: 1.1208x; 1.1208x over previous
#include <cuda_runtime.h>
#include <math.h>
#include <float.h>
#include <stdint.h>

#define N       16384
#define DIN     13
#define KNN     8
#define QCTA    64               // queries per CTA (4 warps x m16)
#define CHUNK   128              // j per staged chunk
#define NCHUNK  (N / CHUNK)      // 128
#define NTILE   (CHUNK / 8)      // 16 n8-tiles per chunk
#define NLIST   4                // partial lists per query

// ---- scratch (no allocs allowed) ----
__device__ float  g_x[N * 16];           // embedded points
__device__ float  g_sq[N];               // squared norms
__device__ float  g_a[N * 32];           // [ah(16)|al(16)] of -2*x
__device__ float  g_b[N * 32];           // [bh(16)|bl(16)] of  x
__device__ float4 g_bf[(N / 8) * 64];    // B in mma-fragment order (hi|lo per tile)
__device__ float  g_pd[N * NLIST * KNN]; // partial top-k surrogate distances
__device__ int    g_pi[N * NLIST * KNN];
__device__ int    g_idx[N * KNN];        // final knn indices
__device__ float  g_feats[N * 16];       // mean edge messages

__device__ __forceinline__ float silu_f(float v) { return v / (1.0f + expf(-v)); }
__device__ __forceinline__ float silu_fast(float v) { return __fdividef(v, 1.0f + __expf(-v)); }
__device__ __forceinline__ float tf32r(float v) {
    uint32_t u; asm("cvt.rna.tf32.f32 %0, %1;" : "=r"(u) : "f"(v));
    return __uint_as_float(u);
}
__device__ __forceinline__ uint32_t smem_u32(const void* p) {
    uint32_t a;
    asm("{ .reg .u64 t; cvta.to.shared.u64 t, %1; cvt.u32.u64 %0, t; }"
        : "=r"(a) : "l"(p));
    return a;
}
__device__ __forceinline__ void cp_async16(uint32_t saddr, const void* g) {
    asm volatile("cp.async.cg.shared.global [%0], [%1], 16;" :: "r"(saddr), "l"(g));
}
#define CP_COMMIT() asm volatile("cp.async.commit_group;" ::: "memory")
#define CP_WAIT0()  asm volatile("cp.async.wait_group 0;" ::: "memory")

// m16n8k8 tf32 mma (PTX sm_80+, valid under compute_103 base target)
__device__ __forceinline__ void mma_tf32(float& c0, float& c1, float& c2, float& c3,
                                         uint32_t a0, uint32_t a1, uint32_t a2, uint32_t a3,
                                         uint32_t b0, uint32_t b1) {
    asm volatile(
        "mma.sync.aligned.m16n8k8.row.col.f32.tf32.tf32.f32 "
        "{%0,%1,%2,%3}, {%4,%5,%6,%7}, {%8,%9}, {%0,%1,%2,%3};"
        : "+f"(c0), "+f"(c1), "+f"(c2), "+f"(c3)
        : "r"(a0), "r"(a1), "r"(a2), "r"(a3), "r"(b0), "r"(b1));
}

// sorted top-8 insertion (strict <, ascending j scan -> lower index wins ties)
__device__ __forceinline__ void ins8(float* td, int* ti, float d, int j) {
    if (d < td[KNN - 1]) {
        td[KNN - 1] = d; ti[KNN - 1] = j;
        #pragma unroll
        for (int s = KNN - 1; s >= 1; --s) {
            if (td[s] < td[s - 1]) {
                float tf = td[s]; td[s] = td[s-1]; td[s-1] = tf;
                int   tn = ti[s]; ti[s] = ti[s-1]; ti[s-1] = tn;
            }
        }
    }
}

// ============================================================
// Kernel 1: per-point MLP -> x, sq, tf32 hi/lo splits
// ============================================================
__global__ void mlp_kernel(const float* __restrict__ xp,
                           const float* __restrict__ W1, const float* __restrict__ b1,
                           const float* __restrict__ W2, const float* __restrict__ b2,
                           const float* __restrict__ W3, const float* __restrict__ b3)
{
    __shared__ float sW1[DIN * 8], sb1[8];
    __shared__ float sW2[8 * 16],  sb2[16];
    __shared__ float sW3[16 * 15], sb3[15];

    int t = threadIdx.x;
    for (int i = t; i < DIN * 8; i += blockDim.x) sW1[i] = W1[i];
    for (int i = t; i < 8;       i += blockDim.x) sb1[i] = b1[i];
    for (int i = t; i < 8 * 16;  i += blockDim.x) sW2[i] = W2[i];
    for (int i = t; i < 16;      i += blockDim.x) sb2[i] = b2[i];
    for (int i = t; i < 16 * 15; i += blockDim.x) sW3[i] = W3[i];
    for (int i = t; i < 15;      i += blockDim.x) sb3[i] = b3[i];
    __syncthreads();

    int i = blockIdx.x * blockDim.x + t;
    if (i >= N) return;

    float in[DIN];
    #pragma unroll
    for (int d = 0; d < DIN; ++d) in[d] = xp[i * DIN + d];

    float h1[8];
    #pragma unroll
    for (int h = 0; h < 8; ++h) {
        float a = sb1[h];
        #pragma unroll
        for (int d = 0; d < DIN; ++d) a = fmaf(in[d], sW1[d * 8 + h], a);
        h1[h] = silu_f(a);
    }
    float h2[16];
    #pragma unroll
    for (int h = 0; h < 16; ++h) {
        float a = sb2[h];
        #pragma unroll
        for (int d = 0; d < 8; ++d) a = fmaf(h1[d], sW2[d * 16 + h], a);
        h2[h] = silu_f(a);
    }
    float xr[16];
    #pragma unroll
    for (int h = 0; h < 15; ++h) {
        float a = sb3[h];
        #pragma unroll
        for (int d = 0; d < 16; ++d) a = fmaf(h2[d], sW3[d * 15 + h], a);
        xr[h] = a;
    }
    xr[15] = in[DIN - 1];

    float s = 0.0f;
    #pragma unroll
    for (int k = 0; k < 16; ++k) s = fmaf(xr[k], xr[k], s);

    #pragma unroll
    for (int k = 0; k < 16; ++k) {
        float v = xr[k];
        g_x[i * 16 + k] = v;
        float a  = -2.0f * v;
        float ah = tf32r(a);
        float al = tf32r(a - ah);
        g_a[i * 32 + k]      = ah;
        g_a[i * 32 + 16 + k] = al;
        float bh = tf32r(v);
        float bl = tf32r(v - bh);
        g_b[i * 32 + k]      = bh;
        g_b[i * 32 + 16 + k] = bl;
    }
    g_sq[i] = s;
}

// ============================================================
// Kernel 1b: reorder B into mma fragment layout
// ============================================================
__global__ void bfrag_kernel()
{
    int u = blockIdx.x * 256 + threadIdx.x;        // (T, lane)
    int T = u >> 5, l = u & 31;
    int row = T * 8 + (l >> 2);
    int c   = l & 3;
    const float* b = g_b + row * 32;
    g_bf[T * 64 + l]      = make_float4(b[c],      b[c + 4],      b[c + 8],      b[c + 12]);
    g_bf[T * 64 + 32 + l] = make_float4(b[16 + c], b[16 + c + 4], b[16 + c + 8], b[16 + c + 12]);
}

// ============================================================
// Kernel 2: distance GEMM via mma.sync tf32 + fused top-8
//   4 warps x 16 queries, 2-tile ILP, sq_j-seeded accumulators
// ============================================================
__global__ void __launch_bounds__(128, 3) knn_mma_kernel()
{
    __shared__ float4 sBf[2][NTILE * 64];   // 2 x 16KB
    __shared__ float  ssq[2][CHUNK];

    const int t    = threadIdx.x;
    const int lane = t & 31;
    const int w    = t >> 5;
    const int gid  = lane >> 2;     // query row within m16
    const int t4   = lane & 3;
    const int q0   = blockIdx.x * QCTA + w * 16;

    // persistent A fragments (tf32 hi/lo of -2x)
    uint32_t ah0[4], ah1[4], al0[4], al1[4];
    {
        const float* A0 = g_a + (size_t)(q0 + gid) * 32;
        const float* A1 = g_a + (size_t)(q0 + gid + 8) * 32;
        ah0[0] = __float_as_uint(A0[t4]);      ah0[1] = __float_as_uint(A1[t4]);
        ah0[2] = __float_as_uint(A0[t4 + 4]);  ah0[3] = __float_as_uint(A1[t4 + 4]);
        ah1[0] = __float_as_uint(A0[t4 + 8]);  ah1[1] = __float_as_uint(A1[t4 + 8]);
        ah1[2] = __float_as_uint(A0[t4 + 12]); ah1[3] = __float_as_uint(A1[t4 + 12]);
        al0[0] = __float_as_uint(A0[16 + t4]);      al0[1] = __float_as_uint(A1[16 + t4]);
        al0[2] = __float_as_uint(A0[16 + t4 + 4]);  al0[3] = __float_as_uint(A1[16 + t4 + 4]);
        al1[0] = __float_as_uint(A0[16 + t4 + 8]);  al1[1] = __float_as_uint(A1[16 + t4 + 8]);
        al1[2] = __float_as_uint(A0[16 + t4 + 12]); al1[3] = __float_as_uint(A1[16 + t4 + 12]);
    }

    float td0[KNN], td1[KNN];
    int   ti0[KNN], ti1[KNN];
    #pragma unroll
    for (int k = 0; k < KNN; ++k) {
        td0[k] = FLT_MAX; ti0[k] = 0x7fffffff;
        td1[k] = FLT_MAX; ti1[k] = 0x7fffffff;
    }

    const uint32_t sB_addr  = smem_u32(sBf);
    const uint32_t ssq_addr = smem_u32(ssq);

    // prefetch chunk 0
    {
        const float4* src = g_bf;
        for (int u = t; u < NTILE * 64; u += 128)
            cp_async16(sB_addr + (uint32_t)u * 16, src + u);
        if (t < CHUNK / 4)
            cp_async16(ssq_addr + (uint32_t)t * 16, (const float4*)g_sq + t);
        CP_COMMIT();
    }

    for (int ch = 0; ch < NCHUNK; ++ch) {
        const int buf = ch & 1;
        CP_WAIT0();
        __syncthreads();

        const int cn = ch + 1;
        if (cn < NCHUNK) {
            const int nb = cn & 1;
            const float4* src = g_bf + (size_t)cn * (NTILE * 64);
            for (int u = t; u < NTILE * 64; u += 128)
                cp_async16(sB_addr + (uint32_t)(nb * NTILE * 64 + u) * 16, src + u);
            if (t < CHUNK / 4)
                cp_async16(ssq_addr + (uint32_t)(nb * CHUNK + t * 4) * 4,
                           (const float4*)(g_sq + cn * CHUNK) + t);
            CP_COMMIT();
        }

        const uint4* btile = (const uint4*)sBf[buf];
        const float* sqv   = ssq[buf];
        const int    jch   = ch * CHUNK;

        #pragma unroll
        for (int np = 0; np < NTILE / 2; ++np) {
            const int ntA = np * 2, ntB = np * 2 + 1;
            uint4 bhA = btile[ntA * 64 + lane];
            uint4 blA = btile[ntA * 64 + 32 + lane];
            uint4 bhB = btile[ntB * 64 + lane];
            uint4 blB = btile[ntB * 64 + 32 + lane];

            float2 sA = *(const float2*)&sqv[ntA * 8 + 2 * t4];
            float2 sB = *(const float2*)&sqv[ntB * 8 + 2 * t4];

            // accumulators seeded with sq_j (cX) and 0 (cY); d = cX + cY
            float xA0 = sA.x, xA1 = sA.y, xA2 = sA.x, xA3 = sA.y;
            float yA0 = 0.f,  yA1 = 0.f,  yA2 = 0.f,  yA3 = 0.f;
            float xB0 = sB.x, xB1 = sB.y, xB2 = sB.x, xB3 = sB.y;
            float yB0 = 0.f,  yB1 = 0.f,  yB2 = 0.f,  yB3 = 0.f;

            // tile A: hi*hi + lo*hi + hi*lo (3-term split, K=16 -> 2 steps each)
            mma_tf32(xA0, xA1, xA2, xA3, ah0[0], ah0[1], ah0[2], ah0[3], bhA.x, bhA.y);
            mma_tf32(xB0, xB1, xB2, xB3, ah0[0], ah0[1], ah0[2], ah0[3], bhB.x, bhB.y);
            mma_tf32(yA0, yA1, yA2, yA3, al0[0], al0[1], al0[2], al0[3], bhA.x, bhA.y);
            mma_tf32(yB0, yB1, yB2, yB3, al0[0], al0[1], al0[2], al0[3], bhB.x, bhB.y);
            mma_tf32(xA0, xA1, xA2, xA3, ah1[0], ah1[1], ah1[2], ah1[3], bhA.z, bhA.w);
            mma_tf32(xB0, xB1, xB2, xB3, ah1[0], ah1[1], ah1[2], ah1[3], bhB.z, bhB.w);
            mma_tf32(yA0, yA1, yA2, yA3, al1[0], al1[1], al1[2], al1[3], bhA.z, bhA.w);
            mma_tf32(yB0, yB1, yB2, yB3, al1[0], al1[1], al1[2], al1[3], bhB.z, bhB.w);
            mma_tf32(xA0, xA1, xA2, xA3, ah0[0], ah0[1], ah0[2], ah0[3], blA.x, blA.y);
            mma_tf32(xB0, xB1, xB2, xB3, ah0[0], ah0[1], ah0[2], ah0[3], blB.x, blB.y);
            mma_tf32(yA0, yA1, yA2, yA3, ah1[0], ah1[1], ah1[2], ah1[3], blA.z, blA.w);
            mma_tf32(yB0, yB1, yB2, yB3, ah1[0], ah1[1], ah1[2], ah1[3], blB.z, blB.w);

            // deferred epilogue: tile A
            {
                float d0 = xA0 + yA0, d1 = xA1 + yA1;
                float d2 = xA2 + yA2, d3 = xA3 + yA3;
                const int j0 = jch + ntA * 8 + 2 * t4;
                if (fminf(d0, d1) < td0[KNN - 1]) { ins8(td0, ti0, d0, j0); ins8(td0, ti0, d1, j0 + 1); }
                if (fminf(d2, d3) < td1[KNN - 1]) { ins8(td1, ti1, d2, j0); ins8(td1, ti1, d3, j0 + 1); }
            }
            // tile B
            {
                float d0 = xB0 + yB0, d1 = xB1 + yB1;
                float d2 = xB2 + yB2, d3 = xB3 + yB3;
                const int j0 = jch + ntB * 8 + 2 * t4;
                if (fminf(d0, d1) < td0[KNN - 1]) { ins8(td0, ti0, d0, j0); ins8(td0, ti0, d1, j0 + 1); }
                if (fminf(d2, d3) < td1[KNN - 1]) { ins8(td1, ti1, d2, j0); ins8(td1, ti1, d3, j0 + 1); }
            }
        }
        __syncthreads();
    }

    {
        int base0 = ((q0 + gid) * NLIST + t4) * KNN;
        int base1 = ((q0 + gid + 8) * NLIST + t4) * KNN;
        #pragma unroll
        for (int k = 0; k < KNN; ++k) {
            g_pd[base0 + k] = td0[k];  g_pi[base0 + k] = ti0[k];
            g_pd[base1 + k] = td1[k];  g_pi[base1 + k] = ti1[k];
        }
    }
}

// ============================================================
// Kernel 3: merge NLIST partial top-8 lists -> final indices
// ============================================================
__global__ void merge_kernel()
{
    int i = blockIdx.x * blockDim.x + threadIdx.x;
    if (i >= N) return;

    float d[NLIST * KNN];
    int   ix[NLIST * KNN];
    #pragma unroll
    for (int u = 0; u < NLIST * KNN; ++u) {
        d[u]  = g_pd[i * NLIST * KNN + u];
        ix[u] = g_pi[i * NLIST * KNN + u];
    }
    #pragma unroll
    for (int k = 0; k < KNN; ++k) {
        float bd = FLT_MAX; int bi = 0x7fffffff; int bu = 0;
        #pragma unroll
        for (int u = 0; u < NLIST * KNN; ++u) {
            if (d[u] < bd || (d[u] == bd && ix[u] < bi)) {
                bd = d[u]; bi = ix[u]; bu = u;
            }
        }
        g_idx[i * KNN + k] = bi;
        d[bu] = FLT_MAX; ix[bu] = 0x7fffffff;
    }
}

// ============================================================
// Kernel 4a: edge messages + mean (thread = (point, channel))
// ============================================================
__global__ void __launch_bounds__(256)
feats_kernel(const float* __restrict__ We, const float* __restrict__ be)
{
    __shared__ float sWd[16 * 16];
    __shared__ float sWb[16 * 16];
    __shared__ float sbe[16];
    __shared__ float sxi[16 * 16];
    __shared__ int   sj[16 * KNN];
    __shared__ float sxj[16 * KNN * 16];

    const int t  = threadIdx.x;
    const int i0 = blockIdx.x * 16;

    {
        float top = We[t];
        float bot = We[256 + t];
        sWd[t] = top - bot;
        sWb[t] = bot;
    }
    if (t < 16) sbe[t] = be[t];
    sxi[t] = g_x[i0 * 16 + t];
    if (t < 16 * KNN) sj[t] = g_idx[i0 * KNN + t];
    __syncthreads();

    {
        const float4* gx4 = (const float4*)g_x;
        float4* sxj4 = (float4*)sxj;
        #pragma unroll
        for (int u = t; u < 16 * KNN * 4; u += 256) {
            int row = u >> 2, seg = u & 3;
            sxj4[u] = gx4[sj[row] * 4 + seg];
        }
    }
    __syncthreads();

    const int p = t >> 4;
    const int h = t & 15;
    const int i = i0 + p;

    float pre = sbe[h];
    #pragma unroll
    for (int d = 0; d < 16; ++d) pre = fmaf(sxi[p * 16 + d], sWd[d * 16 + h], pre);

    float fsum = 0.0f;
    #pragma unroll
    for (int k = 0; k < KNN; ++k) {
        const float* xj = sxj + (p * KNN + k) * 16;
        float m = pre;
        #pragma unroll
        for (int d = 0; d < 16; ++d) m = fmaf(xj[d], sWb[d * 16 + h], m);
        fsum += silu_fast(m);
    }

    g_feats[i * 16 + h] = fsum * 0.125f;
}

// ============================================================
// Kernel 4b: final MLP + concat output
// ============================================================
__global__ void __launch_bounds__(256)
out_kernel(const float* __restrict__ xp,
           const float* __restrict__ Wf1, const float* __restrict__ bf1,
           const float* __restrict__ Wf2, const float* __restrict__ bf2,
           float* __restrict__ out)
{
    __shared__ float sWf1[16 * 32], sbf1[32];
    __shared__ float sWf2[32 * 16], sbf2[16];

    int t = threadIdx.x;
    for (int u = t; u < 16 * 32; u += 256) sWf1[u] = Wf1[u];
    for (int u = t; u < 32;      u += 256) sbf1[u] = bf1[u];
    for (int u = t; u < 32 * 16; u += 256) sWf2[u] = Wf2[u];
    for (int u = t; u < 16;      u += 256) sbf2[u] = bf2[u];
    __syncthreads();

    int i = blockIdx.x * 256 + t;
    if (i >= N) return;

    float feats[16];
    const float4* gf4 = (const float4*)g_feats;
    #pragma unroll
    for (int s = 0; s < 4; ++s) {
        float4 v = gf4[i * 4 + s];
        feats[4*s+0] = v.x; feats[4*s+1] = v.y; feats[4*s+2] = v.z; feats[4*s+3] = v.w;
    }

    float f1[32];
    #pragma unroll
    for (int h = 0; h < 32; ++h) {
        float a = sbf1[h];
        #pragma unroll
        for (int d = 0; d < 16; ++d) a = fmaf(feats[d], sWf1[d * 32 + h], a);
        f1[h] = silu_fast(a);
    }
    float f2[16];
    #pragma unroll
    for (int h = 0; h < 16; ++h) {
        float a = sbf2[h];
        #pragma unroll
        for (int d = 0; d < 32; ++d) a = fmaf(f1[d], sWf2[d * 16 + h], a);
        f2[h] = a;
    }

    float* o = out + i * (16 + DIN);
    #pragma unroll
    for (int h = 0; h < 16; ++h) o[h] = f2[h];
    #pragma unroll
    for (int d = 0; d < DIN; ++d) o[16 + d] = xp[i * DIN + d];
}

// ============================================================
extern "C" void kernel_launch(void* const* d_in, const int* in_sizes, int n_in,
                              void* d_out, int out_size)
{
    const float* xp  = (const float*)d_in[0];
    const float* W1  = (const float*)d_in[1];
    const float* b1  = (const float*)d_in[2];
    const float* W2  = (const float*)d_in[3];
    const float* b2  = (const float*)d_in[4];
    const float* W3  = (const float*)d_in[5];
    const float* b3  = (const float*)d_in[6];
    const float* We  = (const float*)d_in[7];
    const float* be  = (const float*)d_in[8];
    const float* Wf1 = (const float*)d_in[9];
    const float* bf1 = (const float*)d_in[10];
    const float* Wf2 = (const float*)d_in[11];
    const float* bf2 = (const float*)d_in[12];
    float* out = (float*)d_out;

    mlp_kernel<<<N / 256, 256>>>(xp, W1, b1, W2, b2, W3, b3);
    bfrag_kernel<<<(N / 8) * 32 / 256, 256>>>();
    knn_mma_kernel<<<N / QCTA, 128>>>();
    merge_kernel<<<N / 128, 128>>>();
    feats_kernel<<<N / 16, 256>>>(We, be);
    out_kernel<<<N / 256, 256>>>(xp, Wf1, bf1, Wf2, bf2, out);
}

// round 8
// speedup vs baseline: 1.8241x; 1.6275x over previous
#include <cuda_runtime.h>
#include <math.h>
#include <float.h>
#include <stdint.h>

#define N       16384
#define DIN     13
#define KNN     8
#define QCTA    64               // queries per CTA (4 q-groups of 16)
#define CHUNK   128              // j per chunk (per half)
#define NCHUNK  (N / CHUNK)      // 128
#define NTILE   (CHUNK / 8)      // 16 n8-tiles per chunk
#define NLIST   8                // partial lists per query (4 t4 x 2 j-halves)

// ---- scratch (no allocs allowed) ----
__device__ float  g_x[N * 16];           // embedded points
__device__ float  g_sq[N];               // squared norms
__device__ float  g_a[N * 32];           // [ah(16)|al(16)] of -2*x
__device__ float  g_b[N * 32];           // [bh(16)|bl(16)] of  x
__device__ float4 g_bf[(N / 8) * 64];    // B in mma-fragment order (hi|lo per tile)
__device__ float  g_pd[N * NLIST * KNN]; // partial top-k surrogate distances
__device__ int    g_pi[N * NLIST * KNN];
__device__ int    g_idx[N * KNN];        // final knn indices
__device__ float  g_feats[N * 16];       // mean edge messages

__device__ __forceinline__ float silu_f(float v) { return v / (1.0f + expf(-v)); }
__device__ __forceinline__ float silu_fast(float v) { return __fdividef(v, 1.0f + __expf(-v)); }
__device__ __forceinline__ float tf32r(float v) {
    uint32_t u; asm("cvt.rna.tf32.f32 %0, %1;" : "=r"(u) : "f"(v));
    return __uint_as_float(u);
}
__device__ __forceinline__ uint32_t smem_u32(const void* p) {
    uint32_t a;
    asm("{ .reg .u64 t; cvta.to.shared.u64 t, %1; cvt.u32.u64 %0, t; }"
        : "=r"(a) : "l"(p));
    return a;
}
__device__ __forceinline__ void cp_async16(uint32_t saddr, const void* g) {
    asm volatile("cp.async.cg.shared.global [%0], [%1], 16;" :: "r"(saddr), "l"(g));
}
#define CP_COMMIT() asm volatile("cp.async.commit_group;" ::: "memory")
#define CP_WAIT0()  asm volatile("cp.async.wait_group 0;" ::: "memory")

// m16n8k8 tf32 mma (PTX sm_80+, valid under compute_103 base target)
__device__ __forceinline__ void mma_tf32(float& c0, float& c1, float& c2, float& c3,
                                         uint32_t a0, uint32_t a1, uint32_t a2, uint32_t a3,
                                         uint32_t b0, uint32_t b1) {
    asm volatile(
        "mma.sync.aligned.m16n8k8.row.col.f32.tf32.tf32.f32 "
        "{%0,%1,%2,%3}, {%4,%5,%6,%7}, {%8,%9}, {%0,%1,%2,%3};"
        : "+f"(c0), "+f"(c1), "+f"(c2), "+f"(c3)
        : "r"(a0), "r"(a1), "r"(a2), "r"(a3), "r"(b0), "r"(b1));
}

// sorted top-8 insertion (strict <, ascending j scan -> lower index wins ties)
__device__ __forceinline__ void ins8(float* td, int* ti, float d, int j) {
    if (d < td[KNN - 1]) {
        td[KNN - 1] = d; ti[KNN - 1] = j;
        #pragma unroll
        for (int s = KNN - 1; s >= 1; --s) {
            if (td[s] < td[s - 1]) {
                float tf = td[s]; td[s] = td[s-1]; td[s-1] = tf;
                int   tn = ti[s]; ti[s] = ti[s-1]; ti[s-1] = tn;
            }
        }
    }
}

// ============================================================
// Kernel 1: per-point MLP -> x, sq, tf32 hi/lo splits
// ============================================================
__global__ void mlp_kernel(const float* __restrict__ xp,
                           const float* __restrict__ W1, const float* __restrict__ b1,
                           const float* __restrict__ W2, const float* __restrict__ b2,
                           const float* __restrict__ W3, const float* __restrict__ b3)
{
    __shared__ float sW1[DIN * 8], sb1[8];
    __shared__ float sW2[8 * 16],  sb2[16];
    __shared__ float sW3[16 * 15], sb3[15];

    int t = threadIdx.x;
    for (int i = t; i < DIN * 8; i += blockDim.x) sW1[i] = W1[i];
    for (int i = t; i < 8;       i += blockDim.x) sb1[i] = b1[i];
    for (int i = t; i < 8 * 16;  i += blockDim.x) sW2[i] = W2[i];
    for (int i = t; i < 16;      i += blockDim.x) sb2[i] = b2[i];
    for (int i = t; i < 16 * 15; i += blockDim.x) sW3[i] = W3[i];
    for (int i = t; i < 15;      i += blockDim.x) sb3[i] = b3[i];
    __syncthreads();

    int i = blockIdx.x * blockDim.x + t;
    if (i >= N) return;

    float in[DIN];
    #pragma unroll
    for (int d = 0; d < DIN; ++d) in[d] = xp[i * DIN + d];

    float h1[8];
    #pragma unroll
    for (int h = 0; h < 8; ++h) {
        float a = sb1[h];
        #pragma unroll
        for (int d = 0; d < DIN; ++d) a = fmaf(in[d], sW1[d * 8 + h], a);
        h1[h] = silu_f(a);
    }
    float h2[16];
    #pragma unroll
    for (int h = 0; h < 16; ++h) {
        float a = sb2[h];
        #pragma unroll
        for (int d = 0; d < 8; ++d) a = fmaf(h1[d], sW2[d * 16 + h], a);
        h2[h] = silu_f(a);
    }
    float xr[16];
    #pragma unroll
    for (int h = 0; h < 15; ++h) {
        float a = sb3[h];
        #pragma unroll
        for (int d = 0; d < 16; ++d) a = fmaf(h2[d], sW3[d * 15 + h], a);
        xr[h] = a;
    }
    xr[15] = in[DIN - 1];

    float s = 0.0f;
    #pragma unroll
    for (int k = 0; k < 16; ++k) s = fmaf(xr[k], xr[k], s);

    #pragma unroll
    for (int k = 0; k < 16; ++k) {
        float v = xr[k];
        g_x[i * 16 + k] = v;
        float a  = -2.0f * v;
        float ah = tf32r(a);
        float al = tf32r(a - ah);
        g_a[i * 32 + k]      = ah;
        g_a[i * 32 + 16 + k] = al;
        float bh = tf32r(v);
        float bl = tf32r(v - bh);
        g_b[i * 32 + k]      = bh;
        g_b[i * 32 + 16 + k] = bl;
    }
    g_sq[i] = s;
}

// ============================================================
// Kernel 1b: reorder B into mma fragment layout
// ============================================================
__global__ void bfrag_kernel()
{
    int u = blockIdx.x * 256 + threadIdx.x;        // (T, lane)
    int T = u >> 5, l = u & 31;
    int row = T * 8 + (l >> 2);
    int c   = l & 3;
    const float* b = g_b + row * 32;
    g_bf[T * 64 + l]      = make_float4(b[c],      b[c + 4],      b[c + 8],      b[c + 12]);
    g_bf[T * 64 + 32 + l] = make_float4(b[16 + c], b[16 + c + 4], b[16 + c + 8], b[16 + c + 12]);
}

// ============================================================
// Kernel 2: distance GEMM via mma.sync tf32 + fused top-8
//   256 threads = 8 warps = 4 q-groups x 2 j-halves.
//   Each iteration stages chunk pair (2s, 2s+1); warp jh computes chunk 2s+jh.
// ============================================================
__global__ void __launch_bounds__(256) knn_mma_kernel()
{
    __shared__ float4 sBf[2][2][NTILE * 64];   // [buf][half] 32KB total
    __shared__ float  ssq[2][2][CHUNK];

    const int t    = threadIdx.x;
    const int lane = t & 31;
    const int w    = t >> 5;
    const int qg   = w & 3;         // query group 0..3
    const int jh   = w >> 2;        // j-half 0/1
    const int gid  = lane >> 2;     // query row within m16
    const int t4   = lane & 3;
    const int q0   = blockIdx.x * QCTA + qg * 16;

    // persistent A fragments (tf32 hi/lo of -2x) — layout identical to R5 (verified)
    uint32_t ah0[4], ah1[4], al0[4], al1[4];
    {
        const float* A0 = g_a + (size_t)(q0 + gid) * 32;
        const float* A1 = g_a + (size_t)(q0 + gid + 8) * 32;
        ah0[0] = __float_as_uint(A0[t4]);      ah0[1] = __float_as_uint(A1[t4]);
        ah0[2] = __float_as_uint(A0[t4 + 4]);  ah0[3] = __float_as_uint(A1[t4 + 4]);
        ah1[0] = __float_as_uint(A0[t4 + 8]);  ah1[1] = __float_as_uint(A1[t4 + 8]);
        ah1[2] = __float_as_uint(A0[t4 + 12]); ah1[3] = __float_as_uint(A1[t4 + 12]);
        al0[0] = __float_as_uint(A0[16 + t4]);      al0[1] = __float_as_uint(A1[16 + t4]);
        al0[2] = __float_as_uint(A0[16 + t4 + 4]);  al0[3] = __float_as_uint(A1[16 + t4 + 4]);
        al1[0] = __float_as_uint(A0[16 + t4 + 8]);  al1[1] = __float_as_uint(A1[16 + t4 + 8]);
        al1[2] = __float_as_uint(A0[16 + t4 + 12]); al1[3] = __float_as_uint(A1[16 + t4 + 12]);
    }

    float td0[KNN], td1[KNN];
    int   ti0[KNN], ti1[KNN];
    #pragma unroll
    for (int k = 0; k < KNN; ++k) {
        td0[k] = FLT_MAX; ti0[k] = 0x7fffffff;
        td1[k] = FLT_MAX; ti1[k] = 0x7fffffff;
    }

    // staging helper addresses
    uint32_t sB_base[2][2], sq_base[2][2];
    #pragma unroll
    for (int b = 0; b < 2; ++b)
        #pragma unroll
        for (int h = 0; h < 2; ++h) {
            sB_base[b][h] = smem_u32(&sBf[b][h][0]);
            sq_base[b][h] = smem_u32(&ssq[b][h][0]);
        }

    // prefetch chunk pair (0,1) into buf 0
    #pragma unroll
    for (int h = 0; h < 2; ++h) {
        const float4* src = g_bf + (size_t)h * (NTILE * 64);
        for (int u = t; u < NTILE * 64; u += 256)
            cp_async16(sB_base[0][h] + (uint32_t)u * 16, src + u);
        if (t < CHUNK / 4)
            cp_async16(sq_base[0][h] + (uint32_t)t * 16, (const float4*)(g_sq + h * CHUNK) + t);
    }
    CP_COMMIT();

    const int NS = NCHUNK / 2;   // 64 staging iterations
    for (int s = 0; s < NS; ++s) {
        const int buf = s & 1;
        CP_WAIT0();
        __syncthreads();

        const int sn = s + 1;
        if (sn < NS) {
            const int nb = sn & 1;
            #pragma unroll
            for (int h = 0; h < 2; ++h) {
                const int c = 2 * sn + h;
                const float4* src = g_bf + (size_t)c * (NTILE * 64);
                for (int u = t; u < NTILE * 64; u += 256)
                    cp_async16(sB_base[nb][h] + (uint32_t)u * 16, src + u);
                if (t < CHUNK / 4)
                    cp_async16(sq_base[nb][h] + (uint32_t)t * 16,
                               (const float4*)(g_sq + c * CHUNK) + t);
            }
            CP_COMMIT();
        }

        const uint4* btile = (const uint4*)&sBf[buf][jh][0];
        const float* sqv   = ssq[buf][jh];
        const int    jch   = (2 * s + jh) * CHUNK;

        #pragma unroll 2
        for (int np = 0; np < NTILE / 2; ++np) {
            const int ntA = np * 2, ntB = np * 2 + 1;
            uint4 bhA = btile[ntA * 64 + lane];
            uint4 blA = btile[ntA * 64 + 32 + lane];
            uint4 bhB = btile[ntB * 64 + lane];
            uint4 blB = btile[ntB * 64 + 32 + lane];

            float2 sA = *(const float2*)&sqv[ntA * 8 + 2 * t4];
            float2 sB = *(const float2*)&sqv[ntB * 8 + 2 * t4];

            // single accumulator set per tile, seeded with sq_j
            float cA0 = sA.x, cA1 = sA.y, cA2 = sA.x, cA3 = sA.y;
            float cB0 = sB.x, cB1 = sB.y, cB2 = sB.x, cB3 = sB.y;

            // 3-term split; two independent 6-chains interleaved
            mma_tf32(cA0, cA1, cA2, cA3, ah0[0], ah0[1], ah0[2], ah0[3], bhA.x, bhA.y);
            mma_tf32(cB0, cB1, cB2, cB3, ah0[0], ah0[1], ah0[2], ah0[3], bhB.x, bhB.y);
            mma_tf32(cA0, cA1, cA2, cA3, ah1[0], ah1[1], ah1[2], ah1[3], bhA.z, bhA.w);
            mma_tf32(cB0, cB1, cB2, cB3, ah1[0], ah1[1], ah1[2], ah1[3], bhB.z, bhB.w);
            mma_tf32(cA0, cA1, cA2, cA3, al0[0], al0[1], al0[2], al0[3], bhA.x, bhA.y);
            mma_tf32(cB0, cB1, cB2, cB3, al0[0], al0[1], al0[2], al0[3], bhB.x, bhB.y);
            mma_tf32(cA0, cA1, cA2, cA3, al1[0], al1[1], al1[2], al1[3], bhA.z, bhA.w);
            mma_tf32(cB0, cB1, cB2, cB3, al1[0], al1[1], al1[2], al1[3], bhB.z, bhB.w);
            mma_tf32(cA0, cA1, cA2, cA3, ah0[0], ah0[1], ah0[2], ah0[3], blA.x, blA.y);
            mma_tf32(cB0, cB1, cB2, cB3, ah0[0], ah0[1], ah0[2], ah0[3], blB.x, blB.y);
            mma_tf32(cA0, cA1, cA2, cA3, ah1[0], ah1[1], ah1[2], ah1[3], blA.z, blA.w);
            mma_tf32(cB0, cB1, cB2, cB3, ah1[0], ah1[1], ah1[2], ah1[3], blB.z, blB.w);

            {
                const int j0 = jch + ntA * 8 + 2 * t4;
                if (fminf(cA0, cA1) < td0[KNN - 1]) { ins8(td0, ti0, cA0, j0); ins8(td0, ti0, cA1, j0 + 1); }
                if (fminf(cA2, cA3) < td1[KNN - 1]) { ins8(td1, ti1, cA2, j0); ins8(td1, ti1, cA3, j0 + 1); }
            }
            {
                const int j0 = jch + ntB * 8 + 2 * t4;
                if (fminf(cB0, cB1) < td0[KNN - 1]) { ins8(td0, ti0, cB0, j0); ins8(td0, ti0, cB1, j0 + 1); }
                if (fminf(cB2, cB3) < td1[KNN - 1]) { ins8(td1, ti1, cB2, j0); ins8(td1, ti1, cB3, j0 + 1); }
            }
        }
        __syncthreads();
    }

    {
        const int li = jh * 4 + t4;
        int base0 = ((q0 + gid) * NLIST + li) * KNN;
        int base1 = ((q0 + gid + 8) * NLIST + li) * KNN;
        #pragma unroll
        for (int k = 0; k < KNN; ++k) {
            g_pd[base0 + k] = td0[k];  g_pi[base0 + k] = ti0[k];
            g_pd[base1 + k] = td1[k];  g_pi[base1 + k] = ti1[k];
        }
    }
}

// ============================================================
// Kernel 3: merge NLIST partial top-8 lists -> final indices
// ============================================================
__global__ void merge_kernel()
{
    int i = blockIdx.x * blockDim.x + threadIdx.x;
    if (i >= N) return;

    float d[NLIST * KNN];
    int   ix[NLIST * KNN];
    #pragma unroll
    for (int u = 0; u < NLIST * KNN; ++u) {
        d[u]  = g_pd[i * NLIST * KNN + u];
        ix[u] = g_pi[i * NLIST * KNN + u];
    }
    for (int k = 0; k < KNN; ++k) {
        float bd = FLT_MAX; int bi = 0x7fffffff; int bu = 0;
        for (int u = 0; u < NLIST * KNN; ++u) {
            if (d[u] < bd || (d[u] == bd && ix[u] < bi)) {
                bd = d[u]; bi = ix[u]; bu = u;
            }
        }
        g_idx[i * KNN + k] = bi;
        d[bu] = FLT_MAX; ix[bu] = 0x7fffffff;
    }
}

// ============================================================
// Kernel 4a: edge messages + mean (thread = (point, channel))
// ============================================================
__global__ void __launch_bounds__(256)
feats_kernel(const float* __restrict__ We, const float* __restrict__ be)
{
    __shared__ float sWd[16 * 16];
    __shared__ float sWb[16 * 16];
    __shared__ float sbe[16];
    __shared__ float sxi[16 * 16];
    __shared__ int   sj[16 * KNN];
    __shared__ float sxj[16 * KNN * 16];

    const int t  = threadIdx.x;
    const int i0 = blockIdx.x * 16;

    {
        float top = We[t];
        float bot = We[256 + t];
        sWd[t] = top - bot;
        sWb[t] = bot;
    }
    if (t < 16) sbe[t] = be[t];
    sxi[t] = g_x[i0 * 16 + t];
    if (t < 16 * KNN) sj[t] = g_idx[i0 * KNN + t];
    __syncthreads();

    {
        const float4* gx4 = (const float4*)g_x;
        float4* sxj4 = (float4*)sxj;
        #pragma unroll
        for (int u = t; u < 16 * KNN * 4; u += 256) {
            int row = u >> 2, seg = u & 3;
            sxj4[u] = gx4[sj[row] * 4 + seg];
        }
    }
    __syncthreads();

    const int p = t >> 4;
    const int h = t & 15;
    const int i = i0 + p;

    float pre = sbe[h];
    #pragma unroll
    for (int d = 0; d < 16; ++d) pre = fmaf(sxi[p * 16 + d], sWd[d * 16 + h], pre);

    float fsum = 0.0f;
    #pragma unroll
    for (int k = 0; k < KNN; ++k) {
        const float* xj = sxj + (p * KNN + k) * 16;
        float m = pre;
        #pragma unroll
        for (int d = 0; d < 16; ++d) m = fmaf(xj[d], sWb[d * 16 + h], m);
        fsum += silu_fast(m);
    }

    g_feats[i * 16 + h] = fsum * 0.125f;
}

// ============================================================
// Kernel 4b: final MLP + concat output
// ============================================================
__global__ void __launch_bounds__(256)
out_kernel(const float* __restrict__ xp,
           const float* __restrict__ Wf1, const float* __restrict__ bf1,
           const float* __restrict__ Wf2, const float* __restrict__ bf2,
           float* __restrict__ out)
{
    __shared__ float sWf1[16 * 32], sbf1[32];
    __shared__ float sWf2[32 * 16], sbf2[16];

    int t = threadIdx.x;
    for (int u = t; u < 16 * 32; u += 256) sWf1[u] = Wf1[u];
    for (int u = t; u < 32;      u += 256) sbf1[u] = bf1[u];
    for (int u = t; u < 32 * 16; u += 256) sWf2[u] = Wf2[u];
    for (int u = t; u < 16;      u += 256) sbf2[u] = bf2[u];
    __syncthreads();

    int i = blockIdx.x * 256 + t;
    if (i >= N) return;

    float feats[16];
    const float4* gf4 = (const float4*)g_feats;
    #pragma unroll
    for (int s = 0; s < 4; ++s) {
        float4 v = gf4[i * 4 + s];
        feats[4*s+0] = v.x; feats[4*s+1] = v.y; feats[4*s+2] = v.z; feats[4*s+3] = v.w;
    }

    float f1[32];
    #pragma unroll
    for (int h = 0; h < 32; ++h) {
        float a = sbf1[h];
        #pragma unroll
        for (int d = 0; d < 16; ++d) a = fmaf(feats[d], sWf1[d * 32 + h], a);
        f1[h] = silu_fast(a);
    }
    float f2[16];
    #pragma unroll
    for (int h = 0; h < 16; ++h) {
        float a = sbf2[h];
        #pragma unroll
        for (int d = 0; d < 32; ++d) a = fmaf(f1[d], sWf2[d * 16 + h], a);
        f2[h] = a;
    }

    float* o = out + i * (16 + DIN);
    #pragma unroll
    for (int h = 0; h < 16; ++h) o[h] = f2[h];
    #pragma unroll
    for (int d = 0; d < DIN; ++d) o[16 + d] = xp[i * DIN + d];
}

// ============================================================
extern "C" void kernel_launch(void* const* d_in, const int* in_sizes, int n_in,
                              void* d_out, int out_size)
{
    const float* xp  = (const float*)d_in[0];
    const float* W1  = (const float*)d_in[1];
    const float* b1  = (const float*)d_in[2];
    const float* W2  = (const float*)d_in[3];
    const float* b2  = (const float*)d_in[4];
    const float* W3  = (const float*)d_in[5];
    const float* b3  = (const float*)d_in[6];
    const float* We  = (const float*)d_in[7];
    const float* be  = (const float*)d_in[8];
    const float* Wf1 = (const float*)d_in[9];
    const float* bf1 = (const float*)d_in[10];
    const float* Wf2 = (const float*)d_in[11];
    const float* bf2 = (const float*)d_in[12];
    float* out = (float*)d_out;

    mlp_kernel<<<N / 256, 256>>>(xp, W1, b1, W2, b2, W3, b3);
    bfrag_kernel<<<(N / 8) * 32 / 256, 256>>>();
    knn_mma_kernel<<<N / QCTA, 256>>>();
    merge_kernel<<<N / 128, 128>>>();
    feats_kernel<<<N / 16, 256>>>(We, be);
    out_kernel<<<N / 256, 256>>>(xp, Wf1, bf1, Wf2, bf2, out);
}

// round 9
// speedup vs baseline: 1.9768x; 1.0837x over previous
#include <cuda_runtime.h>
#include <cuda_fp16.h>
#include <math.h>
#include <float.h>
#include <stdint.h>

#define N       16384
#define DIN     13
#define KNN     8
#define QCTA    64               // queries per CTA (4 q-groups of 16)
#define CHUNK   128              // j per chunk (per half)
#define NCHUNK  (N / CHUNK)      // 128
#define NTILE   (CHUNK / 8)      // 16 n8-tiles per chunk
#define NLIST   8                // partial lists per query (4 t4 x 2 j-halves)

// ---- scratch (no allocs allowed) ----
__device__ float  g_x[N * 16];           // embedded points
__device__ float  g_sq[N];               // squared norms
__device__ __half g_ah[N * 16];          // fp16 hi of -2*x
__device__ __half g_am[N * 16];          // fp16 mid of -2*x
__device__ uint4  g_bf[(N / 8) * 32];    // B frags: per (tile,lane) {bh0,bh1,bm0,bm1}
__device__ float  g_pd[N * NLIST * KNN]; // partial top-k surrogate distances
__device__ int    g_pi[N * NLIST * KNN];
__device__ int    g_idx[N * KNN];        // final knn indices
__device__ float  g_feats[N * 16];       // mean edge messages

__device__ __forceinline__ float silu_f(float v) { return v / (1.0f + expf(-v)); }
__device__ __forceinline__ float silu_fast(float v) { return __fdividef(v, 1.0f + __expf(-v)); }
__device__ __forceinline__ uint32_t smem_u32(const void* p) {
    uint32_t a;
    asm("{ .reg .u64 t; cvta.to.shared.u64 t, %1; cvt.u32.u64 %0, t; }"
        : "=r"(a) : "l"(p));
    return a;
}
__device__ __forceinline__ void cp_async16(uint32_t saddr, const void* g) {
    asm volatile("cp.async.cg.shared.global [%0], [%1], 16;" :: "r"(saddr), "l"(g));
}
#define CP_COMMIT() asm volatile("cp.async.commit_group;" ::: "memory")
#define CP_WAIT0()  asm volatile("cp.async.wait_group 0;" ::: "memory")

// m16n8k16 fp16 mma, fp32 accumulate (PTX sm_80+, valid under compute_103)
__device__ __forceinline__ void mma_f16(float& c0, float& c1, float& c2, float& c3,
                                        uint32_t a0, uint32_t a1, uint32_t a2, uint32_t a3,
                                        uint32_t b0, uint32_t b1) {
    asm volatile(
        "mma.sync.aligned.m16n8k16.row.col.f32.f16.f16.f32 "
        "{%0,%1,%2,%3}, {%4,%5,%6,%7}, {%8,%9}, {%0,%1,%2,%3};"
        : "+f"(c0), "+f"(c1), "+f"(c2), "+f"(c3)
        : "r"(a0), "r"(a1), "r"(a2), "r"(a3), "r"(b0), "r"(b1));
}

__device__ __forceinline__ uint32_t pack_h2(float lo, float hi) {
    __half2 h = __halves2half2(__float2half_rn(lo), __float2half_rn(hi));
    return *(uint32_t*)&h;
}

// sorted top-8 insertion (strict <, ascending j scan -> lower index wins ties)
__device__ __forceinline__ void ins8(float* td, int* ti, float d, int j) {
    if (d < td[KNN - 1]) {
        td[KNN - 1] = d; ti[KNN - 1] = j;
        #pragma unroll
        for (int s = KNN - 1; s >= 1; --s) {
            if (td[s] < td[s - 1]) {
                float tf = td[s]; td[s] = td[s-1]; td[s-1] = tf;
                int   tn = ti[s]; ti[s] = ti[s-1]; ti[s-1] = tn;
            }
        }
    }
}

// ============================================================
// Kernel 1: per-point MLP -> x, sq, fp16 hi/mid split of -2x
// ============================================================
__global__ void mlp_kernel(const float* __restrict__ xp,
                           const float* __restrict__ W1, const float* __restrict__ b1,
                           const float* __restrict__ W2, const float* __restrict__ b2,
                           const float* __restrict__ W3, const float* __restrict__ b3)
{
    __shared__ float sW1[DIN * 8], sb1[8];
    __shared__ float sW2[8 * 16],  sb2[16];
    __shared__ float sW3[16 * 15], sb3[15];

    int t = threadIdx.x;
    for (int i = t; i < DIN * 8; i += blockDim.x) sW1[i] = W1[i];
    for (int i = t; i < 8;       i += blockDim.x) sb1[i] = b1[i];
    for (int i = t; i < 8 * 16;  i += blockDim.x) sW2[i] = W2[i];
    for (int i = t; i < 16;      i += blockDim.x) sb2[i] = b2[i];
    for (int i = t; i < 16 * 15; i += blockDim.x) sW3[i] = W3[i];
    for (int i = t; i < 15;      i += blockDim.x) sb3[i] = b3[i];
    __syncthreads();

    int i = blockIdx.x * blockDim.x + t;
    if (i >= N) return;

    float in[DIN];
    #pragma unroll
    for (int d = 0; d < DIN; ++d) in[d] = xp[i * DIN + d];

    float h1[8];
    #pragma unroll
    for (int h = 0; h < 8; ++h) {
        float a = sb1[h];
        #pragma unroll
        for (int d = 0; d < DIN; ++d) a = fmaf(in[d], sW1[d * 8 + h], a);
        h1[h] = silu_f(a);
    }
    float h2[16];
    #pragma unroll
    for (int h = 0; h < 16; ++h) {
        float a = sb2[h];
        #pragma unroll
        for (int d = 0; d < 8; ++d) a = fmaf(h1[d], sW2[d * 16 + h], a);
        h2[h] = silu_f(a);
    }
    float xr[16];
    #pragma unroll
    for (int h = 0; h < 15; ++h) {
        float a = sb3[h];
        #pragma unroll
        for (int d = 0; d < 16; ++d) a = fmaf(h2[d], sW3[d * 15 + h], a);
        xr[h] = a;
    }
    xr[15] = in[DIN - 1];

    float s = 0.0f;
    #pragma unroll
    for (int k = 0; k < 16; ++k) s = fmaf(xr[k], xr[k], s);

    #pragma unroll
    for (int k = 0; k < 16; ++k) {
        float v = xr[k];
        g_x[i * 16 + k] = v;
        float a  = -2.0f * v;
        __half ah = __float2half_rn(a);
        __half am = __float2half_rn(a - __half2float(ah));
        g_ah[i * 16 + k] = ah;
        g_am[i * 16 + k] = am;
    }
    g_sq[i] = s;
}

// ============================================================
// Kernel 1b: build B fragments (fp16 hi/mid of x, m16n8k16 layout)
//   thread u = (tile T, lane l): j = 8T + (l>>2), k pairs at 2*(l&3)+{0,1} and +8
// ============================================================
__global__ void bfrag_kernel()
{
    int u = blockIdx.x * 256 + threadIdx.x;        // (T, lane)
    int T = u >> 5, l = u & 31;
    int j = T * 8 + (l >> 2);
    int c = (l & 3) * 2;
    const float* x = g_x + (size_t)j * 16;

    float v0 = x[c],     v1 = x[c + 1];
    float v2 = x[c + 8], v3 = x[c + 9];

    __half h0 = __float2half_rn(v0), h1v = __float2half_rn(v1);
    __half h2v = __float2half_rn(v2), h3 = __float2half_rn(v3);
    __half m0 = __float2half_rn(v0 - __half2float(h0));
    __half m1 = __float2half_rn(v1 - __half2float(h1v));
    __half m2 = __float2half_rn(v2 - __half2float(h2v));
    __half m3 = __float2half_rn(v3 - __half2float(h3));

    uint4 f;
    __half2 p;
    p = __halves2half2(h0, h1v);  f.x = *(uint32_t*)&p;   // bh0: k = c, c+1
    p = __halves2half2(h2v, h3);  f.y = *(uint32_t*)&p;   // bh1: k = c+8, c+9
    p = __halves2half2(m0, m1);   f.z = *(uint32_t*)&p;   // bm0
    p = __halves2half2(m2, m3);   f.w = *(uint32_t*)&p;   // bm1
    g_bf[u] = f;
}

// ============================================================
// Kernel 2: distance GEMM via mma.sync fp16 k16 (3-term split) + fused top-8
//   256 threads = 8 warps = 4 q-groups x 2 j-halves.
// ============================================================
__global__ void __launch_bounds__(256) knn_mma_kernel()
{
    __shared__ uint4 sBf[2][2][NTILE * 32];   // [buf][half] 2x2x8KB
    __shared__ float ssq[2][2][CHUNK];

    const int t    = threadIdx.x;
    const int lane = t & 31;
    const int w    = t >> 5;
    const int qg   = w & 3;         // query group 0..3
    const int jh   = w >> 2;        // j-half 0/1
    const int gid  = lane >> 2;     // row within m16 / col within n8
    const int t4   = lane & 3;
    const int q0   = blockIdx.x * QCTA + qg * 16;

    // persistent A fragments: rows q0+gid, q0+gid+8; k pairs 2t4+{0,1}, +8
    uint32_t ah[4], am[4];
    {
        const __half* A0h = g_ah + (size_t)(q0 + gid) * 16;
        const __half* A1h = g_ah + (size_t)(q0 + gid + 8) * 16;
        const __half* A0m = g_am + (size_t)(q0 + gid) * 16;
        const __half* A1m = g_am + (size_t)(q0 + gid + 8) * 16;
        ah[0] = *(const uint32_t*)&A0h[2 * t4];
        ah[1] = *(const uint32_t*)&A1h[2 * t4];
        ah[2] = *(const uint32_t*)&A0h[2 * t4 + 8];
        ah[3] = *(const uint32_t*)&A1h[2 * t4 + 8];
        am[0] = *(const uint32_t*)&A0m[2 * t4];
        am[1] = *(const uint32_t*)&A1m[2 * t4];
        am[2] = *(const uint32_t*)&A0m[2 * t4 + 8];
        am[3] = *(const uint32_t*)&A1m[2 * t4 + 8];
    }

    float td0[KNN], td1[KNN];
    int   ti0[KNN], ti1[KNN];
    #pragma unroll
    for (int k = 0; k < KNN; ++k) {
        td0[k] = FLT_MAX; ti0[k] = 0x7fffffff;
        td1[k] = FLT_MAX; ti1[k] = 0x7fffffff;
    }

    uint32_t sB_base[2][2], sq_base[2][2];
    #pragma unroll
    for (int b = 0; b < 2; ++b)
        #pragma unroll
        for (int h = 0; h < 2; ++h) {
            sB_base[b][h] = smem_u32(&sBf[b][h][0]);
            sq_base[b][h] = smem_u32(&ssq[b][h][0]);
        }

    // prefetch chunk pair (0,1) into buf 0
    #pragma unroll
    for (int h = 0; h < 2; ++h) {
        const uint4* src = g_bf + (size_t)h * (NTILE * 32);
        for (int u = t; u < NTILE * 32; u += 256)
            cp_async16(sB_base[0][h] + (uint32_t)u * 16, src + u);
        if (t < CHUNK / 4)
            cp_async16(sq_base[0][h] + (uint32_t)t * 16, (const float4*)(g_sq + h * CHUNK) + t);
    }
    CP_COMMIT();

    const int NS = NCHUNK / 2;   // 64 staging iterations
    for (int s = 0; s < NS; ++s) {
        const int buf = s & 1;
        CP_WAIT0();
        __syncthreads();

        const int sn = s + 1;
        if (sn < NS) {
            const int nb = sn & 1;
            #pragma unroll
            for (int h = 0; h < 2; ++h) {
                const int c = 2 * sn + h;
                const uint4* src = g_bf + (size_t)c * (NTILE * 32);
                for (int u = t; u < NTILE * 32; u += 256)
                    cp_async16(sB_base[nb][h] + (uint32_t)u * 16, src + u);
                if (t < CHUNK / 4)
                    cp_async16(sq_base[nb][h] + (uint32_t)t * 16,
                               (const float4*)(g_sq + c * CHUNK) + t);
            }
            CP_COMMIT();
        }

        const uint4* btile = &sBf[buf][jh][0];
        const float* sqv   = ssq[buf][jh];
        const int    jch   = (2 * s + jh) * CHUNK;

        #pragma unroll 2
        for (int np = 0; np < NTILE / 2; ++np) {
            const int ntA = np * 2, ntB = np * 2 + 1;
            uint4 fA = btile[ntA * 32 + lane];   // {bh0,bh1,bm0,bm1}
            uint4 fB = btile[ntB * 32 + lane];

            float2 sA = *(const float2*)&sqv[ntA * 8 + 2 * t4];
            float2 sB2 = *(const float2*)&sqv[ntB * 8 + 2 * t4];

            // accumulators seeded with sq_j -> d2 directly
            float cA0 = sA.x,  cA1 = sA.y,  cA2 = sA.x,  cA3 = sA.y;
            float cB0 = sB2.x, cB1 = sB2.y, cB2v = sB2.x, cB3 = sB2.y;

            // 3-term fp16 split: h*h + h*m + m*h  (each one k16 MMA)
            mma_f16(cA0, cA1, cA2, cA3, ah[0], ah[1], ah[2], ah[3], fA.x, fA.y);
            mma_f16(cB0, cB1, cB2v, cB3, ah[0], ah[1], ah[2], ah[3], fB.x, fB.y);
            mma_f16(cA0, cA1, cA2, cA3, ah[0], ah[1], ah[2], ah[3], fA.z, fA.w);
            mma_f16(cB0, cB1, cB2v, cB3, ah[0], ah[1], ah[2], ah[3], fB.z, fB.w);
            mma_f16(cA0, cA1, cA2, cA3, am[0], am[1], am[2], am[3], fA.x, fA.y);
            mma_f16(cB0, cB1, cB2v, cB3, am[0], am[1], am[2], am[3], fB.x, fB.y);

            {
                const int j0 = jch + ntA * 8 + 2 * t4;
                if (fminf(cA0, cA1) < td0[KNN - 1]) { ins8(td0, ti0, cA0, j0); ins8(td0, ti0, cA1, j0 + 1); }
                if (fminf(cA2, cA3) < td1[KNN - 1]) { ins8(td1, ti1, cA2, j0); ins8(td1, ti1, cA3, j0 + 1); }
            }
            {
                const int j0 = jch + ntB * 8 + 2 * t4;
                if (fminf(cB0, cB1) < td0[KNN - 1]) { ins8(td0, ti0, cB0, j0); ins8(td0, ti0, cB1, j0 + 1); }
                if (fminf(cB2v, cB3) < td1[KNN - 1]) { ins8(td1, ti1, cB2v, j0); ins8(td1, ti1, cB3, j0 + 1); }
            }
        }
        __syncthreads();
    }

    {
        const int li = jh * 4 + t4;
        int base0 = ((q0 + gid) * NLIST + li) * KNN;
        int base1 = ((q0 + gid + 8) * NLIST + li) * KNN;
        #pragma unroll
        for (int k = 0; k < KNN; ++k) {
            g_pd[base0 + k] = td0[k];  g_pi[base0 + k] = ti0[k];
            g_pd[base1 + k] = td1[k];  g_pi[base1 + k] = ti1[k];
        }
    }
}

// ============================================================
// Kernel 3: merge NLIST partial top-8 lists -> final indices
// ============================================================
__global__ void merge_kernel()
{
    int i = blockIdx.x * blockDim.x + threadIdx.x;
    if (i >= N) return;

    float d[NLIST * KNN];
    int   ix[NLIST * KNN];
    #pragma unroll
    for (int u = 0; u < NLIST * KNN; ++u) {
        d[u]  = g_pd[i * NLIST * KNN + u];
        ix[u] = g_pi[i * NLIST * KNN + u];
    }
    for (int k = 0; k < KNN; ++k) {
        float bd = FLT_MAX; int bi = 0x7fffffff; int bu = 0;
        for (int u = 0; u < NLIST * KNN; ++u) {
            if (d[u] < bd || (d[u] == bd && ix[u] < bi)) {
                bd = d[u]; bi = ix[u]; bu = u;
            }
        }
        g_idx[i * KNN + k] = bi;
        d[bu] = FLT_MAX; ix[bu] = 0x7fffffff;
    }
}

// ============================================================
// Kernel 4a: edge messages + mean (thread = (point, channel))
// ============================================================
__global__ void __launch_bounds__(256)
feats_kernel(const float* __restrict__ We, const float* __restrict__ be)
{
    __shared__ float sWd[16 * 16];
    __shared__ float sWb[16 * 16];
    __shared__ float sbe[16];
    __shared__ float sxi[16 * 16];
    __shared__ int   sj[16 * KNN];
    __shared__ float sxj[16 * KNN * 16];

    const int t  = threadIdx.x;
    const int i0 = blockIdx.x * 16;

    {
        float top = We[t];
        float bot = We[256 + t];
        sWd[t] = top - bot;
        sWb[t] = bot;
    }
    if (t < 16) sbe[t] = be[t];
    sxi[t] = g_x[i0 * 16 + t];
    if (t < 16 * KNN) sj[t] = g_idx[i0 * KNN + t];
    __syncthreads();

    {
        const float4* gx4 = (const float4*)g_x;
        float4* sxj4 = (float4*)sxj;
        #pragma unroll
        for (int u = t; u < 16 * KNN * 4; u += 256) {
            int row = u >> 2, seg = u & 3;
            sxj4[u] = gx4[sj[row] * 4 + seg];
        }
    }
    __syncthreads();

    const int p = t >> 4;
    const int h = t & 15;
    const int i = i0 + p;

    float pre = sbe[h];
    #pragma unroll
    for (int d = 0; d < 16; ++d) pre = fmaf(sxi[p * 16 + d], sWd[d * 16 + h], pre);

    float fsum = 0.0f;
    #pragma unroll
    for (int k = 0; k < KNN; ++k) {
        const float* xj = sxj + (p * KNN + k) * 16;
        float m = pre;
        #pragma unroll
        for (int d = 0; d < 16; ++d) m = fmaf(xj[d], sWb[d * 16 + h], m);
        fsum += silu_fast(m);
    }

    g_feats[i * 16 + h] = fsum * 0.125f;
}

// ============================================================
// Kernel 4b: final MLP + concat output
// ============================================================
__global__ void __launch_bounds__(256)
out_kernel(const float* __restrict__ xp,
           const float* __restrict__ Wf1, const float* __restrict__ bf1,
           const float* __restrict__ Wf2, const float* __restrict__ bf2,
           float* __restrict__ out)
{
    __shared__ float sWf1[16 * 32], sbf1[32];
    __shared__ float sWf2[32 * 16], sbf2[16];

    int t = threadIdx.x;
    for (int u = t; u < 16 * 32; u += 256) sWf1[u] = Wf1[u];
    for (int u = t; u < 32;      u += 256) sbf1[u] = bf1[u];
    for (int u = t; u < 32 * 16; u += 256) sWf2[u] = Wf2[u];
    for (int u = t; u < 16;      u += 256) sbf2[u] = bf2[u];
    __syncthreads();

    int i = blockIdx.x * 256 + t;
    if (i >= N) return;

    float feats[16];
    const float4* gf4 = (const float4*)g_feats;
    #pragma unroll
    for (int s = 0; s < 4; ++s) {
        float4 v = gf4[i * 4 + s];
        feats[4*s+0] = v.x; feats[4*s+1] = v.y; feats[4*s+2] = v.z; feats[4*s+3] = v.w;
    }

    float f1[32];
    #pragma unroll
    for (int h = 0; h < 32; ++h) {
        float a = sbf1[h];
        #pragma unroll
        for (int d = 0; d < 16; ++d) a = fmaf(feats[d], sWf1[d * 32 + h], a);
        f1[h] = silu_fast(a);
    }
    float f2[16];
    #pragma unroll
    for (int h = 0; h < 16; ++h) {
        float a = sbf2[h];
        #pragma unroll
        for (int d = 0; d < 32; ++d) a = fmaf(f1[d], sWf2[d * 16 + h], a);
        f2[h] = a;
    }

    float* o = out + i * (16 + DIN);
    #pragma unroll
    for (int h = 0; h < 16; ++h) o[h] = f2[h];
    #pragma unroll
    for (int d = 0; d < DIN; ++d) o[16 + d] = xp[i * DIN + d];
}

// ============================================================
extern "C" void kernel_launch(void* const* d_in, const int* in_sizes, int n_in,
                              void* d_out, int out_size)
{
    const float* xp  = (const float*)d_in[0];
    const float* W1  = (const float*)d_in[1];
    const float* b1  = (const float*)d_in[2];
    const float* W2  = (const float*)d_in[3];
    const float* b2  = (const float*)d_in[4];
    const float* W3  = (const float*)d_in[5];
    const float* b3  = (const float*)d_in[6];
    const float* We  = (const float*)d_in[7];
    const float* be  = (const float*)d_in[8];
    const float* Wf1 = (const float*)d_in[9];
    const float* bf1 = (const float*)d_in[10];
    const float* Wf2 = (const float*)d_in[11];
    const float* bf2 = (const float*)d_in[12];
    float* out = (float*)d_out;

    mlp_kernel<<<N / 256, 256>>>(xp, W1, b1, W2, b2, W3, b3);
    bfrag_kernel<<<(N / 8) * 32 / 256, 256>>>();
    knn_mma_kernel<<<N / QCTA, 256>>>();
    merge_kernel<<<N / 128, 128>>>();
    feats_kernel<<<N / 16, 256>>>(We, be);
    out_kernel<<<N / 256, 256>>>(xp, Wf1, bf1, Wf2, bf2, out);
}

// round 10
// speedup vs baseline: 6.0150x; 3.0429x over previous
#include <cuda_runtime.h>
#include <cuda_fp16.h>
#include <math.h>
#include <float.h>
#include <stdint.h>

#define N       16384
#define DIN     13
#define KNN     8
#define NBIN    1024
#define QCTA    64               // sorted queries per CTA
#define CHUNK   128              // j per chunk
#define NCHUNK  (N / CHUNK)      // 128
#define NTILE   (CHUNK / 8)      // 16 tiles per chunk
#define NLIST   8                // 4 t4-slices x 2 tile-halves
#define EPSA    1e-3f            // abs margin on d2 threshold (MMA approx)
#define SLACK   0.02f            // key slack (> bucket bin width 10/1024)

// ---- scratch (no allocs allowed) ----
__device__ float  g_x[N * 16];            // embedded points (original order)
__device__ float  g_sq[N];
__device__ float  g_key[N];
__device__ int    g_hist[NBIN];
__device__ int    g_off[NBIN];
__device__ float  g_pkey[N];              // sorted keys
__device__ float  g_psq[N];               // sorted sq
__device__ int    g_pidx[N];              // sorted pos -> original index
__device__ __half g_ah[N * 16];           // sorted fp16 hi of -2x
__device__ __half g_am[N * 16];           // sorted fp16 mid of -2x
__device__ uint4  g_bf[NCHUNK * NTILE * 32]; // sorted B fragments
__device__ float  g_clo[NCHUNK], g_chi[NCHUNK];
__device__ float  g_pd[N * NLIST * KNN];
__device__ int    g_pi[N * NLIST * KNN];
__device__ int    g_idx[N * KNN];         // final knn (original indices)
__device__ float  g_feats[N * 16];

__device__ __forceinline__ float silu_f(float v) { return v / (1.0f + expf(-v)); }
__device__ __forceinline__ float silu_fast(float v) { return __fdividef(v, 1.0f + __expf(-v)); }
__device__ __forceinline__ int keybin(float k) {
    int b = (int)((k + 5.0f) * (NBIN / 10.0f));
    return b < 0 ? 0 : (b > NBIN - 1 ? NBIN - 1 : b);
}

// m16n8k16 fp16 mma, fp32 accumulate (PTX sm_80+, valid under compute_103)
__device__ __forceinline__ void mma_f16(float& c0, float& c1, float& c2, float& c3,
                                        uint32_t a0, uint32_t a1, uint32_t a2, uint32_t a3,
                                        uint32_t b0, uint32_t b1) {
    asm volatile(
        "mma.sync.aligned.m16n8k16.row.col.f32.f16.f16.f32 "
        "{%0,%1,%2,%3}, {%4,%5,%6,%7}, {%8,%9}, {%0,%1,%2,%3};"
        : "+f"(c0), "+f"(c1), "+f"(c2), "+f"(c3)
        : "r"(a0), "r"(a1), "r"(a2), "r"(a3), "r"(b0), "r"(b1));
}

__device__ __forceinline__ void ins8(float* td, int* ti, float d, int j) {
    if (d < td[KNN - 1]) {
        td[KNN - 1] = d; ti[KNN - 1] = j;
        #pragma unroll
        for (int s = KNN - 1; s >= 1; --s) {
            if (td[s] < td[s - 1] || (td[s] == td[s - 1] && ti[s] < ti[s - 1])) {
                float tf = td[s]; td[s] = td[s-1]; td[s-1] = tf;
                int   tn = ti[s]; ti[s] = ti[s-1]; ti[s-1] = tn;
            }
        }
    }
}

// ============================================================
// Kernel 1: per-point MLP -> x, sq, key (original order)
// ============================================================
__global__ void mlp_kernel(const float* __restrict__ xp,
                           const float* __restrict__ W1, const float* __restrict__ b1,
                           const float* __restrict__ W2, const float* __restrict__ b2,
                           const float* __restrict__ W3, const float* __restrict__ b3)
{
    __shared__ float sW1[DIN * 8], sb1[8];
    __shared__ float sW2[8 * 16],  sb2[16];
    __shared__ float sW3[16 * 15], sb3[15];

    int t = threadIdx.x;
    for (int i = t; i < DIN * 8; i += blockDim.x) sW1[i] = W1[i];
    for (int i = t; i < 8;       i += blockDim.x) sb1[i] = b1[i];
    for (int i = t; i < 8 * 16;  i += blockDim.x) sW2[i] = W2[i];
    for (int i = t; i < 16;      i += blockDim.x) sb2[i] = b2[i];
    for (int i = t; i < 16 * 15; i += blockDim.x) sW3[i] = W3[i];
    for (int i = t; i < 15;      i += blockDim.x) sb3[i] = b3[i];
    __syncthreads();

    int i = blockIdx.x * blockDim.x + t;
    if (i >= N) return;

    float in[DIN];
    #pragma unroll
    for (int d = 0; d < DIN; ++d) in[d] = xp[i * DIN + d];

    float h1[8];
    #pragma unroll
    for (int h = 0; h < 8; ++h) {
        float a = sb1[h];
        #pragma unroll
        for (int d = 0; d < DIN; ++d) a = fmaf(in[d], sW1[d * 8 + h], a);
        h1[h] = silu_f(a);
    }
    float h2[16];
    #pragma unroll
    for (int h = 0; h < 16; ++h) {
        float a = sb2[h];
        #pragma unroll
        for (int d = 0; d < 8; ++d) a = fmaf(h1[d], sW2[d * 16 + h], a);
        h2[h] = silu_f(a);
    }
    float xr[16];
    #pragma unroll
    for (int h = 0; h < 15; ++h) {
        float a = sb3[h];
        #pragma unroll
        for (int d = 0; d < 16; ++d) a = fmaf(h2[d], sW3[d * 15 + h], a);
        xr[h] = a;
    }
    xr[15] = in[DIN - 1];

    float s = 0.0f;
    #pragma unroll
    for (int k = 0; k < 16; ++k) s = fmaf(xr[k], xr[k], s);

    #pragma unroll
    for (int k = 0; k < 16; ++k) g_x[i * 16 + k] = xr[k];
    g_sq[i]  = s;
    g_key[i] = xr[15];
}

// ============================================================
// Sorting by key (bucket sort)
// ============================================================
__global__ void zeroh_kernel() { g_hist[threadIdx.x] = 0; }

__global__ void hist_kernel() {
    int i = blockIdx.x * blockDim.x + threadIdx.x;
    atomicAdd(&g_hist[keybin(g_key[i])], 1);
}

__global__ void scan_kernel() {
    __shared__ int sh[NBIN];
    int t = threadIdx.x;
    int v = g_hist[t];
    sh[t] = v;
    __syncthreads();
    for (int off = 1; off < NBIN; off <<= 1) {
        int add = (t >= off) ? sh[t - off] : 0;
        __syncthreads();
        sh[t] += add;
        __syncthreads();
    }
    g_off[t] = sh[t] - v;
}

// scatter + build sorted A fp16 splits + sorted B fragments
__global__ void scatter_kernel() {
    int i = blockIdx.x * blockDim.x + threadIdx.x;
    float key = g_key[i];
    int b = keybin(key);
    int pos = atomicAdd(&g_off[b], 1);

    float xr[16];
    #pragma unroll
    for (int d = 0; d < 16; ++d) xr[d] = g_x[i * 16 + d];

    g_pkey[pos] = key;
    g_psq[pos]  = g_sq[i];
    g_pidx[pos] = i;

    #pragma unroll
    for (int k = 0; k < 16; ++k) {
        float a = -2.0f * xr[k];
        __half ah = __float2half_rn(a);
        __half am = __float2half_rn(a - __half2float(ah));
        g_ah[pos * 16 + k] = ah;
        g_am[pos * 16 + k] = am;
    }

    int T = pos >> 3, r = pos & 7;
    #pragma unroll
    for (int c = 0; c < 4; ++c) {
        int cc = 2 * c;
        float v0 = xr[cc], v1 = xr[cc + 1], v2 = xr[cc + 8], v3 = xr[cc + 9];
        __half h0 = __float2half_rn(v0), h1 = __float2half_rn(v1);
        __half h2 = __float2half_rn(v2), h3 = __float2half_rn(v3);
        __half m0 = __float2half_rn(v0 - __half2float(h0));
        __half m1 = __float2half_rn(v1 - __half2float(h1));
        __half m2 = __float2half_rn(v2 - __half2float(h2));
        __half m3 = __float2half_rn(v3 - __half2float(h3));
        uint4 f; __half2 p;
        p = __halves2half2(h0, h1); f.x = *(uint32_t*)&p;
        p = __halves2half2(h2, h3); f.y = *(uint32_t*)&p;
        p = __halves2half2(m0, m1); f.z = *(uint32_t*)&p;
        p = __halves2half2(m2, m3); f.w = *(uint32_t*)&p;
        g_bf[(size_t)T * 32 + r * 4 + c] = f;
    }
}

__global__ void cbound_kernel() {
    int c = threadIdx.x;   // 128 chunks
    float lo = FLT_MAX, hi = -FLT_MAX;
    for (int r = 0; r < CHUNK; ++r) {
        float k = g_pkey[c * CHUNK + r];
        lo = fminf(lo, k); hi = fmaxf(hi, k);
    }
    g_clo[c] = lo; g_chi[c] = hi;
}

// ============================================================
// Kernel 2: zigzag-pruned KNN via fp16 split mma.sync
//   CTA = 64 consecutive sorted queries, 256 thr = 4 q-groups x 2 tile-halves
// ============================================================
__global__ void __launch_bounds__(256) knn_zig_kernel()
{
    __shared__ uint4 sBf[NTILE * 32];   // 8KB
    __shared__ float ssq[CHUNK];
    __shared__ int   sjd[CHUNK];

    const int t    = threadIdx.x;
    const int lane = t & 31;
    const int w    = t >> 5;
    const int qg   = w & 3;
    const int jh   = w >> 2;            // tile-half 0/1
    const int gid  = lane >> 2;
    const int t4   = lane & 3;
    const int b    = blockIdx.x;
    const int p0   = b * QCTA + qg * 16 + gid;   // sorted query rows
    const int p1   = p0 + 8;

    uint32_t ah[4], am[4];
    {
        const __half* A0h = g_ah + (size_t)p0 * 16;
        const __half* A1h = g_ah + (size_t)p1 * 16;
        const __half* A0m = g_am + (size_t)p0 * 16;
        const __half* A1m = g_am + (size_t)p1 * 16;
        ah[0] = *(const uint32_t*)&A0h[2 * t4];
        ah[1] = *(const uint32_t*)&A1h[2 * t4];
        ah[2] = *(const uint32_t*)&A0h[2 * t4 + 8];
        ah[3] = *(const uint32_t*)&A1h[2 * t4 + 8];
        am[0] = *(const uint32_t*)&A0m[2 * t4];
        am[1] = *(const uint32_t*)&A1m[2 * t4];
        am[2] = *(const uint32_t*)&A0m[2 * t4 + 8];
        am[3] = *(const uint32_t*)&A1m[2 * t4 + 8];
    }
    const float qk0 = g_pkey[p0], qk1 = g_pkey[p1];
    const float sq0 = g_psq[p0],  sq1 = g_psq[p1];

    float td0[KNN], td1[KNN];
    int   ti0[KNN], ti1[KNN];
    #pragma unroll
    for (int k = 0; k < KNN; ++k) {
        td0[k] = FLT_MAX; ti0[k] = 0x7fffffff;
        td1[k] = FLT_MAX; ti1[k] = 0x7fffffff;
    }

    const int h0 = b >> 1;
    int nxtR = h0 + 1, nxtL = h0 - 1;
    int aliveR = 1, aliveL = 1, tog = 0;
    int cur = h0;

    while (cur >= 0) {
        // ---- stage chunk cur ----
        __syncthreads();
        {
            const uint4* src = g_bf + (size_t)cur * (NTILE * 32);
            sBf[t]       = src[t];
            sBf[t + 256] = src[t + 256];
            if (t < CHUNK) {
                ssq[t] = g_psq[cur * CHUNK + t];
                sjd[t] = g_pidx[cur * CHUNK + t];
            }
        }
        __syncthreads();

        // ---- compute this warp's 8 tiles ----
        #pragma unroll
        for (int nt = 0; nt < 8; ++nt) {
            const int tl = jh * 8 + nt;
            uint4 f = sBf[tl * 32 + lane];
            const int jl = tl * 8 + 2 * t4;
            float2 s2 = *(const float2*)&ssq[jl];
            float c0 = s2.x, c1 = s2.y, c2 = s2.x, c3 = s2.y;
            mma_f16(c0, c1, c2, c3, ah[0], ah[1], ah[2], ah[3], f.x, f.y);
            mma_f16(c0, c1, c2, c3, ah[0], ah[1], ah[2], ah[3], f.z, f.w);
            mma_f16(c0, c1, c2, c3, am[0], am[1], am[2], am[3], f.x, f.y);
            if (fminf(c0, c1) < td0[KNN - 1]) {
                ins8(td0, ti0, c0, sjd[jl]); ins8(td0, ti0, c1, sjd[jl + 1]);
            }
            if (fminf(c2, c3) < td1[KNN - 1]) {
                ins8(td1, ti1, c2, sjd[jl]); ins8(td1, ti1, c3, sjd[jl + 1]);
            }
        }

        // ---- select next chunk (uniform control flow, per-thread need) ----
        cur = -1;
        while (aliveR || aliveL) {
            int dir;
            if (aliveR && aliveL) { dir = tog; tog ^= 1; }
            else dir = aliveR ? 0 : 1;
            int c = (dir == 0) ? nxtR : nxtL;
            if (c < 0 || c >= NCHUNK) {
                if (dir == 0) aliveR = 0; else aliveL = 0;
                continue;
            }
            float bnd = (dir == 0) ? g_clo[c] : g_chi[c];
            float gp0 = (dir == 0) ? bnd - qk0 : qk0 - bnd;
            float gp1 = (dir == 0) ? bnd - qk1 : qk1 - bnd;
            gp0 = fmaxf(gp0 - SLACK, 0.0f);
            gp1 = fmaxf(gp1 - SLACK, 0.0f);
            float th0 = td0[KNN - 1] + sq0 + EPSA;
            float th1 = td1[KNN - 1] + sq1 + EPSA;
            int nd = (gp0 * gp0 <= th0) || (gp1 * gp1 <= th1);
            if (__syncthreads_or(nd)) {
                cur = c;
                if (dir == 0) nxtR++; else nxtL--;
                break;
            } else {
                if (dir == 0) aliveR = 0; else aliveL = 0;
            }
        }
    }

    // ---- write partial lists (original j indices) ----
    {
        const int li = jh * 4 + t4;
        int base0 = (p0 * NLIST + li) * KNN;
        int base1 = (p1 * NLIST + li) * KNN;
        #pragma unroll
        for (int k = 0; k < KNN; ++k) {
            g_pd[base0 + k] = td0[k];  g_pi[base0 + k] = ti0[k];
            g_pd[base1 + k] = td1[k];  g_pi[base1 + k] = ti1[k];
        }
    }
}

// ============================================================
// Kernel 3: merge NLIST partial lists -> final indices (original space)
// ============================================================
__global__ void merge_kernel()
{
    int p = blockIdx.x * blockDim.x + threadIdx.x;
    if (p >= N) return;

    float d[NLIST * KNN];
    int   ix[NLIST * KNN];
    #pragma unroll
    for (int u = 0; u < NLIST * KNN; ++u) {
        d[u]  = g_pd[p * NLIST * KNN + u];
        ix[u] = g_pi[p * NLIST * KNN + u];
    }
    int oi = g_pidx[p];
    for (int k = 0; k < KNN; ++k) {
        float bd = FLT_MAX; int bi = 0x7fffffff; int bu = 0;
        for (int u = 0; u < NLIST * KNN; ++u) {
            if (d[u] < bd || (d[u] == bd && ix[u] < bi)) {
                bd = d[u]; bi = ix[u]; bu = u;
            }
        }
        g_idx[oi * KNN + k] = bi;
        d[bu] = FLT_MAX; ix[bu] = 0x7fffffff;
    }
}

// ============================================================
// Kernel 4a: edge messages + mean (thread = (point, channel))
// ============================================================
__global__ void __launch_bounds__(256)
feats_kernel(const float* __restrict__ We, const float* __restrict__ be)
{
    __shared__ float sWd[16 * 16];
    __shared__ float sWb[16 * 16];
    __shared__ float sbe[16];
    __shared__ float sxi[16 * 16];
    __shared__ int   sj[16 * KNN];
    __shared__ float sxj[16 * KNN * 16];

    const int t  = threadIdx.x;
    const int i0 = blockIdx.x * 16;

    {
        float top = We[t];
        float bot = We[256 + t];
        sWd[t] = top - bot;
        sWb[t] = bot;
    }
    if (t < 16) sbe[t] = be[t];
    sxi[t] = g_x[i0 * 16 + t];
    if (t < 16 * KNN) sj[t] = g_idx[i0 * KNN + t];
    __syncthreads();

    {
        const float4* gx4 = (const float4*)g_x;
        float4* sxj4 = (float4*)sxj;
        #pragma unroll
        for (int u = t; u < 16 * KNN * 4; u += 256) {
            int row = u >> 2, seg = u & 3;
            sxj4[u] = gx4[sj[row] * 4 + seg];
        }
    }
    __syncthreads();

    const int p = t >> 4;
    const int h = t & 15;
    const int i = i0 + p;

    float pre = sbe[h];
    #pragma unroll
    for (int d = 0; d < 16; ++d) pre = fmaf(sxi[p * 16 + d], sWd[d * 16 + h], pre);

    float fsum = 0.0f;
    #pragma unroll
    for (int k = 0; k < KNN; ++k) {
        const float* xj = sxj + (p * KNN + k) * 16;
        float m = pre;
        #pragma unroll
        for (int d = 0; d < 16; ++d) m = fmaf(xj[d], sWb[d * 16 + h], m);
        fsum += silu_fast(m);
    }

    g_feats[i * 16 + h] = fsum * 0.125f;
}

// ============================================================
// Kernel 4b: final MLP + concat output
// ============================================================
__global__ void __launch_bounds__(256)
out_kernel(const float* __restrict__ xp,
           const float* __restrict__ Wf1, const float* __restrict__ bf1,
           const float* __restrict__ Wf2, const float* __restrict__ bf2,
           float* __restrict__ out)
{
    __shared__ float sWf1[16 * 32], sbf1[32];
    __shared__ float sWf2[32 * 16], sbf2[16];

    int t = threadIdx.x;
    for (int u = t; u < 16 * 32; u += 256) sWf1[u] = Wf1[u];
    for (int u = t; u < 32;      u += 256) sbf1[u] = bf1[u];
    for (int u = t; u < 32 * 16; u += 256) sWf2[u] = Wf2[u];
    for (int u = t; u < 16;      u += 256) sbf2[u] = bf2[u];
    __syncthreads();

    int i = blockIdx.x * 256 + t;
    if (i >= N) return;

    float feats[16];
    const float4* gf4 = (const float4*)g_feats;
    #pragma unroll
    for (int s = 0; s < 4; ++s) {
        float4 v = gf4[i * 4 + s];
        feats[4*s+0] = v.x; feats[4*s+1] = v.y; feats[4*s+2] = v.z; feats[4*s+3] = v.w;
    }

    float f1[32];
    #pragma unroll
    for (int h = 0; h < 32; ++h) {
        float a = sbf1[h];
        #pragma unroll
        for (int d = 0; d < 16; ++d) a = fmaf(feats[d], sWf1[d * 32 + h], a);
        f1[h] = silu_fast(a);
    }
    float f2[16];
    #pragma unroll
    for (int h = 0; h < 16; ++h) {
        float a = sbf2[h];
        #pragma unroll
        for (int d = 0; d < 32; ++d) a = fmaf(f1[d], sWf2[d * 16 + h], a);
        f2[h] = a;
    }

    float* o = out + i * (16 + DIN);
    #pragma unroll
    for (int h = 0; h < 16; ++h) o[h] = f2[h];
    #pragma unroll
    for (int d = 0; d < DIN; ++d) o[16 + d] = xp[i * DIN + d];
}

// ============================================================
extern "C" void kernel_launch(void* const* d_in, const int* in_sizes, int n_in,
                              void* d_out, int out_size)
{
    const float* xp  = (const float*)d_in[0];
    const float* W1  = (const float*)d_in[1];
    const float* b1  = (const float*)d_in[2];
    const float* W2  = (const float*)d_in[3];
    const float* b2  = (const float*)d_in[4];
    const float* W3  = (const float*)d_in[5];
    const float* b3  = (const float*)d_in[6];
    const float* We  = (const float*)d_in[7];
    const float* be  = (const float*)d_in[8];
    const float* Wf1 = (const float*)d_in[9];
    const float* bf1 = (const float*)d_in[10];
    const float* Wf2 = (const float*)d_in[11];
    const float* bf2 = (const float*)d_in[12];
    float* out = (float*)d_out;

    mlp_kernel<<<N / 256, 256>>>(xp, W1, b1, W2, b2, W3, b3);
    zeroh_kernel<<<1, NBIN>>>();
    hist_kernel<<<N / 256, 256>>>();
    scan_kernel<<<1, NBIN>>>();
    scatter_kernel<<<N / 256, 256>>>();
    cbound_kernel<<<1, NCHUNK>>>();
    knn_zig_kernel<<<N / QCTA, 256>>>();
    merge_kernel<<<N / 128, 128>>>();
    feats_kernel<<<N / 16, 256>>>(We, be);
    out_kernel<<<N / 256, 256>>>(xp, Wf1, bf1, Wf2, bf2, out);
}

// round 11
// speedup vs baseline: 6.7439x; 1.1212x over previous
#include <cuda_runtime.h>
#include <cuda_fp16.h>
#include <math.h>
#include <float.h>
#include <stdint.h>

#define N       16384
#define DIN     13
#define KNN     8
#define NBIN    1024
#define QCTA    64               // sorted queries per CTA
#define CHUNK   128              // j per chunk
#define NCHUNK  (N / CHUNK)      // 128
#define NTILE   (CHUNK / 8)      // 16 tiles per chunk
#define NLIST   8                // 4 t4-slices x 2 tile-halves
#define EPSA    1e-3f            // abs margin on d2 threshold (MMA approx)
#define SLACK   0.02f            // key slack (> bucket bin width 10/1024)

typedef unsigned long long ull;

// ---- scratch (no allocs allowed) ----
__device__ float  g_x[N * 16];            // embedded points (original order)
__device__ float  g_sq[N];
__device__ float  g_key[N];
__device__ int    g_hist[NBIN];
__device__ int    g_off[NBIN];
__device__ float  g_pkey[N];              // sorted keys
__device__ float  g_psq[N];               // sorted sq
__device__ int    g_pidx[N];              // sorted pos -> original index
__device__ __half g_ah[N * 16];           // sorted fp16 hi of -2x
__device__ __half g_am[N * 16];           // sorted fp16 mid of -2x
__device__ uint4  g_bf[NCHUNK * NTILE * 32]; // sorted B fragments
__device__ float  g_clo[NCHUNK], g_chi[NCHUNK];
__device__ ull    g_pk[N * NLIST * KNN];  // packed (flipped d | idx)
__device__ int    g_idx[N * KNN];         // final knn (original indices)

__device__ __forceinline__ float silu_f(float v) { return v / (1.0f + expf(-v)); }
__device__ __forceinline__ float silu_fast(float v) { return __fdividef(v, 1.0f + __expf(-v)); }
__device__ __forceinline__ int keybin(float k) {
    int b = (int)((k + 5.0f) * (NBIN / 10.0f));
    return b < 0 ? 0 : (b > NBIN - 1 ? NBIN - 1 : b);
}
__device__ __forceinline__ uint32_t smem_u32(const void* p) {
    uint32_t a;
    asm("{ .reg .u64 t; cvta.to.shared.u64 t, %1; cvt.u32.u64 %0, t; }"
        : "=r"(a) : "l"(p));
    return a;
}
__device__ __forceinline__ void cp_async16(uint32_t saddr, const void* g) {
    asm volatile("cp.async.cg.shared.global [%0], [%1], 16;" :: "r"(saddr), "l"(g));
}
#define CP_COMMIT() asm volatile("cp.async.commit_group;" ::: "memory")
#define CP_WAIT0()  asm volatile("cp.async.wait_group 0;" ::: "memory")

// sortable uint from float (ascending uint == ascending float, any sign)
__device__ __forceinline__ uint32_t fkey(float f) {
    uint32_t u = __float_as_uint(f);
    return u ^ ((u >> 31) ? 0xFFFFFFFFu : 0x80000000u);
}

// m16n8k16 fp16 mma, fp32 accumulate (PTX sm_80+, valid under compute_103)
__device__ __forceinline__ void mma_f16(float& c0, float& c1, float& c2, float& c3,
                                        uint32_t a0, uint32_t a1, uint32_t a2, uint32_t a3,
                                        uint32_t b0, uint32_t b1) {
    asm volatile(
        "mma.sync.aligned.m16n8k16.row.col.f32.f16.f16.f32 "
        "{%0,%1,%2,%3}, {%4,%5,%6,%7}, {%8,%9}, {%0,%1,%2,%3};"
        : "+f"(c0), "+f"(c1), "+f"(c2), "+f"(c3)
        : "r"(a0), "r"(a1), "r"(a2), "r"(a3), "r"(b0), "r"(b1));
}

__device__ __forceinline__ void ins8(float* td, int* ti, float d, int j) {
    if (d < td[KNN - 1]) {
        td[KNN - 1] = d; ti[KNN - 1] = j;
        #pragma unroll
        for (int s = KNN - 1; s >= 1; --s) {
            if (td[s] < td[s - 1] || (td[s] == td[s - 1] && ti[s] < ti[s - 1])) {
                float tf = td[s]; td[s] = td[s-1]; td[s-1] = tf;
                int   tn = ti[s]; ti[s] = ti[s-1]; ti[s-1] = tn;
            }
        }
    }
}

// ============================================================
// Kernel 1: per-point MLP -> x, sq, key (original order)
// ============================================================
__global__ void mlp_kernel(const float* __restrict__ xp,
                           const float* __restrict__ W1, const float* __restrict__ b1,
                           const float* __restrict__ W2, const float* __restrict__ b2,
                           const float* __restrict__ W3, const float* __restrict__ b3)
{
    __shared__ float sW1[DIN * 8], sb1[8];
    __shared__ float sW2[8 * 16],  sb2[16];
    __shared__ float sW3[16 * 15], sb3[15];

    int t = threadIdx.x;
    for (int i = t; i < DIN * 8; i += blockDim.x) sW1[i] = W1[i];
    for (int i = t; i < 8;       i += blockDim.x) sb1[i] = b1[i];
    for (int i = t; i < 8 * 16;  i += blockDim.x) sW2[i] = W2[i];
    for (int i = t; i < 16;      i += blockDim.x) sb2[i] = b2[i];
    for (int i = t; i < 16 * 15; i += blockDim.x) sW3[i] = W3[i];
    for (int i = t; i < 15;      i += blockDim.x) sb3[i] = b3[i];
    __syncthreads();

    int i = blockIdx.x * blockDim.x + t;
    if (i >= N) return;

    float in[DIN];
    #pragma unroll
    for (int d = 0; d < DIN; ++d) in[d] = xp[i * DIN + d];

    float h1[8];
    #pragma unroll
    for (int h = 0; h < 8; ++h) {
        float a = sb1[h];
        #pragma unroll
        for (int d = 0; d < DIN; ++d) a = fmaf(in[d], sW1[d * 8 + h], a);
        h1[h] = silu_f(a);
    }
    float h2[16];
    #pragma unroll
    for (int h = 0; h < 16; ++h) {
        float a = sb2[h];
        #pragma unroll
        for (int d = 0; d < 8; ++d) a = fmaf(h1[d], sW2[d * 16 + h], a);
        h2[h] = silu_f(a);
    }
    float xr[16];
    #pragma unroll
    for (int h = 0; h < 15; ++h) {
        float a = sb3[h];
        #pragma unroll
        for (int d = 0; d < 16; ++d) a = fmaf(h2[d], sW3[d * 15 + h], a);
        xr[h] = a;
    }
    xr[15] = in[DIN - 1];

    float s = 0.0f;
    #pragma unroll
    for (int k = 0; k < 16; ++k) s = fmaf(xr[k], xr[k], s);

    #pragma unroll
    for (int k = 0; k < 16; ++k) g_x[i * 16 + k] = xr[k];
    g_sq[i]  = s;
    g_key[i] = xr[15];
}

// ============================================================
// Sorting by key (bucket sort)
// ============================================================
__global__ void zeroh_kernel() { g_hist[threadIdx.x] = 0; }

__global__ void hist_kernel() {
    int i = blockIdx.x * blockDim.x + threadIdx.x;
    atomicAdd(&g_hist[keybin(g_key[i])], 1);
}

__global__ void scan_kernel() {
    __shared__ int sh[NBIN];
    int t = threadIdx.x;
    int v = g_hist[t];
    sh[t] = v;
    __syncthreads();
    for (int off = 1; off < NBIN; off <<= 1) {
        int add = (t >= off) ? sh[t - off] : 0;
        __syncthreads();
        sh[t] += add;
        __syncthreads();
    }
    g_off[t] = sh[t] - v;
}

// scatter + build sorted A fp16 splits + sorted B fragments
__global__ void scatter_kernel() {
    int i = blockIdx.x * blockDim.x + threadIdx.x;
    float key = g_key[i];
    int b = keybin(key);
    int pos = atomicAdd(&g_off[b], 1);

    float xr[16];
    #pragma unroll
    for (int d = 0; d < 16; ++d) xr[d] = g_x[i * 16 + d];

    g_pkey[pos] = key;
    g_psq[pos]  = g_sq[i];
    g_pidx[pos] = i;

    #pragma unroll
    for (int k = 0; k < 16; ++k) {
        float a = -2.0f * xr[k];
        __half ah = __float2half_rn(a);
        __half am = __float2half_rn(a - __half2float(ah));
        g_ah[pos * 16 + k] = ah;
        g_am[pos * 16 + k] = am;
    }

    int T = pos >> 3, r = pos & 7;
    #pragma unroll
    for (int c = 0; c < 4; ++c) {
        int cc = 2 * c;
        float v0 = xr[cc], v1 = xr[cc + 1], v2 = xr[cc + 8], v3 = xr[cc + 9];
        __half h0 = __float2half_rn(v0), h1 = __float2half_rn(v1);
        __half h2 = __float2half_rn(v2), h3 = __float2half_rn(v3);
        __half m0 = __float2half_rn(v0 - __half2float(h0));
        __half m1 = __float2half_rn(v1 - __half2float(h1));
        __half m2 = __float2half_rn(v2 - __half2float(h2));
        __half m3 = __float2half_rn(v3 - __half2float(h3));
        uint4 f; __half2 p;
        p = __halves2half2(h0, h1); f.x = *(uint32_t*)&p;
        p = __halves2half2(h2, h3); f.y = *(uint32_t*)&p;
        p = __halves2half2(m0, m1); f.z = *(uint32_t*)&p;
        p = __halves2half2(m2, m3); f.w = *(uint32_t*)&p;
        g_bf[(size_t)T * 32 + r * 4 + c] = f;
    }
}

__global__ void cbound_kernel() {
    int c = threadIdx.x;   // 128 chunks
    float lo = FLT_MAX, hi = -FLT_MAX;
    for (int r = 0; r < CHUNK; ++r) {
        float k = g_pkey[c * CHUNK + r];
        lo = fminf(lo, k); hi = fmaxf(hi, k);
    }
    g_clo[c] = lo; g_chi[c] = hi;
}

// ============================================================
// Kernel 2: zigzag-pruned KNN, speculative double-buffer prefetch
// ============================================================
__global__ void __launch_bounds__(256) knn_zig_kernel()
{
    __shared__ uint4 sBf[2][NTILE * 32];   // 2 x 8KB
    __shared__ float ssq[2][CHUNK];
    __shared__ int   sjd[2][CHUNK];

    const int t    = threadIdx.x;
    const int lane = t & 31;
    const int w    = t >> 5;
    const int qg   = w & 3;
    const int jh   = w >> 2;            // tile-half 0/1
    const int gid  = lane >> 2;
    const int t4   = lane & 3;
    const int b    = blockIdx.x;
    const int p0   = b * QCTA + qg * 16 + gid;   // sorted query rows
    const int p1   = p0 + 8;

    uint32_t ah[4], am[4];
    {
        const __half* A0h = g_ah + (size_t)p0 * 16;
        const __half* A1h = g_ah + (size_t)p1 * 16;
        const __half* A0m = g_am + (size_t)p0 * 16;
        const __half* A1m = g_am + (size_t)p1 * 16;
        ah[0] = *(const uint32_t*)&A0h[2 * t4];
        ah[1] = *(const uint32_t*)&A1h[2 * t4];
        ah[2] = *(const uint32_t*)&A0h[2 * t4 + 8];
        ah[3] = *(const uint32_t*)&A1h[2 * t4 + 8];
        am[0] = *(const uint32_t*)&A0m[2 * t4];
        am[1] = *(const uint32_t*)&A1m[2 * t4];
        am[2] = *(const uint32_t*)&A0m[2 * t4 + 8];
        am[3] = *(const uint32_t*)&A1m[2 * t4 + 8];
    }
    const float qk0 = g_pkey[p0], qk1 = g_pkey[p1];
    const float sq0 = g_psq[p0],  sq1 = g_psq[p1];

    float td0[KNN], td1[KNN];
    int   ti0[KNN], ti1[KNN];
    #pragma unroll
    for (int k = 0; k < KNN; ++k) {
        td0[k] = FLT_MAX; ti0[k] = 0x7fffffff;
        td1[k] = FLT_MAX; ti1[k] = 0x7fffffff;
    }

    uint32_t sB_addr[2], sq_addr[2], sj_addr[2];
    #pragma unroll
    for (int u = 0; u < 2; ++u) {
        sB_addr[u] = smem_u32(&sBf[u][0]);
        sq_addr[u] = smem_u32(&ssq[u][0]);
        sj_addr[u] = smem_u32(&sjd[u][0]);
    }

    // staging: 512 uint4 (2/thread) + ssq + sjd
    auto stage = [&](int bf, int c) {
        const uint4* src = g_bf + (size_t)c * (NTILE * 32);
        cp_async16(sB_addr[bf] + (uint32_t)t * 16, src + t);
        cp_async16(sB_addr[bf] + (uint32_t)(t + 256) * 16, src + t + 256);
        if (t < 32) {
            cp_async16(sq_addr[bf] + (uint32_t)t * 16, (const float4*)(g_psq + c * CHUNK) + t);
            cp_async16(sj_addr[bf] + (uint32_t)t * 16, (const int4*)(g_pidx + c * CHUNK) + t);
        }
        CP_COMMIT();
    };

    const int h0 = b >> 1;
    int nxtR = h0 + 1, nxtL = h0 - 1;
    int aliveR = 1, aliveL = 1, tog = 0;
    int cur = h0, bufA = 0;

    stage(0, h0);
    CP_WAIT0();
    __syncthreads();

    while (cur >= 0) {
        // ---- predict next chunk and prefetch into bufA^1 ----
        int pred = -1;
        {
            int aR = aliveR && (nxtR < NCHUNK);
            int aL = aliveL && (nxtL >= 0);
            if (aR && aL) pred = (tog == 0) ? nxtR : nxtL;
            else if (aR)  pred = nxtR;
            else if (aL)  pred = nxtL;
        }
        if (pred >= 0) stage(bufA ^ 1, pred);

        // ---- compute this warp's 8 tiles from bufA ----
        #pragma unroll
        for (int nt = 0; nt < 8; ++nt) {
            const int tl = jh * 8 + nt;
            uint4 f = sBf[bufA][tl * 32 + lane];
            const int jl = tl * 8 + 2 * t4;
            float2 s2 = *(const float2*)&ssq[bufA][jl];
            float c0 = s2.x, c1 = s2.y, c2 = s2.x, c3 = s2.y;
            mma_f16(c0, c1, c2, c3, ah[0], ah[1], ah[2], ah[3], f.x, f.y);
            mma_f16(c0, c1, c2, c3, ah[0], ah[1], ah[2], ah[3], f.z, f.w);
            mma_f16(c0, c1, c2, c3, am[0], am[1], am[2], am[3], f.x, f.y);
            if (fminf(c0, c1) < td0[KNN - 1]) {
                ins8(td0, ti0, c0, sjd[bufA][jl]); ins8(td0, ti0, c1, sjd[bufA][jl + 1]);
            }
            if (fminf(c2, c3) < td1[KNN - 1]) {
                ins8(td1, ti1, c2, sjd[bufA][jl]); ins8(td1, ti1, c3, sjd[bufA][jl + 1]);
            }
        }

        // ---- select next chunk (uniform control flow, per-thread need) ----
        cur = -1;
        while (aliveR || aliveL) {
            int dir;
            if (aliveR && aliveL) { dir = tog; tog ^= 1; }
            else dir = aliveR ? 0 : 1;
            int c = (dir == 0) ? nxtR : nxtL;
            if (c < 0 || c >= NCHUNK) {
                if (dir == 0) aliveR = 0; else aliveL = 0;
                continue;
            }
            float bnd = (dir == 0) ? g_clo[c] : g_chi[c];
            float gp0 = (dir == 0) ? bnd - qk0 : qk0 - bnd;
            float gp1 = (dir == 0) ? bnd - qk1 : qk1 - bnd;
            gp0 = fmaxf(gp0 - SLACK, 0.0f);
            gp1 = fmaxf(gp1 - SLACK, 0.0f);
            float th0 = td0[KNN - 1] + sq0 + EPSA;
            float th1 = td1[KNN - 1] + sq1 + EPSA;
            int nd = (gp0 * gp0 <= th0) || (gp1 * gp1 <= th1);
            if (__syncthreads_or(nd)) {
                cur = c;
                if (dir == 0) nxtR++; else nxtL--;
                break;
            } else {
                if (dir == 0) aliveR = 0; else aliveL = 0;
            }
        }

        // ---- commit prefetch or reload on mispredict ----
        if (cur >= 0) {
            CP_WAIT0();
            __syncthreads();
            if (cur != pred) {
                stage(bufA ^ 1, cur);
                CP_WAIT0();
                __syncthreads();
            }
            bufA ^= 1;
        }
    }
    CP_WAIT0();   // drain any dangling prefetch

    // ---- write packed partial lists ----
    {
        const int li = jh * 4 + t4;
        int base0 = (p0 * NLIST + li) * KNN;
        int base1 = (p1 * NLIST + li) * KNN;
        #pragma unroll
        for (int k = 0; k < KNN; ++k) {
            g_pk[base0 + k] = ((ull)fkey(td0[k]) << 32) | (uint32_t)ti0[k];
            g_pk[base1 + k] = ((ull)fkey(td1[k]) << 32) | (uint32_t)ti1[k];
        }
    }
}

// ============================================================
// Kernel 3: merge NLIST packed lists -> final indices (original space)
// ============================================================
__global__ void merge_kernel()
{
    int p = blockIdx.x * blockDim.x + threadIdx.x;
    if (p >= N) return;

    ull v[NLIST * KNN];
    #pragma unroll
    for (int u = 0; u < NLIST * KNN; ++u)
        v[u] = g_pk[p * NLIST * KNN + u];

    int oi = g_pidx[p];
    for (int k = 0; k < KNN; ++k) {
        ull best = ~0ull; int bu = 0;
        #pragma unroll
        for (int u = 0; u < NLIST * KNN; ++u) {
            if (v[u] < best) { best = v[u]; bu = u; }
        }
        g_idx[oi * KNN + k] = (int)(uint32_t)(best & 0xffffffffull);
        v[bu] = ~0ull;
    }
}

// ============================================================
// Kernel 4: fused edge messages + mean + out MLP + concat
//   block = 256 threads = 16 points x 16 channels
// ============================================================
__global__ void __launch_bounds__(256)
feats_out_kernel(const float* __restrict__ xp,
                 const float* __restrict__ We,  const float* __restrict__ be,
                 const float* __restrict__ Wf1, const float* __restrict__ bf1,
                 const float* __restrict__ Wf2, const float* __restrict__ bf2,
                 float* __restrict__ out)
{
    __shared__ float sWd[16 * 16];
    __shared__ float sWb[16 * 16];
    __shared__ float sbe[16];
    __shared__ float sWf1[16 * 32], sbf1[32];
    __shared__ float sWf2[32 * 16], sbf2[16];
    __shared__ float sxi[16 * 16];
    __shared__ int   sj[16 * KNN];
    __shared__ float sxj[16 * KNN * 16];
    __shared__ float sfe[16 * 16];
    __shared__ float sf1[16 * 32];

    const int t  = threadIdx.x;
    const int i0 = blockIdx.x * 16;

    {
        float top = We[t];
        float bot = We[256 + t];
        sWd[t] = top - bot;
        sWb[t] = bot;
    }
    if (t < 16) sbe[t] = be[t];
    for (int u = t; u < 16 * 32; u += 256) sWf1[u] = Wf1[u];
    if (t < 32) sbf1[t] = bf1[t];
    for (int u = t; u < 32 * 16; u += 256) sWf2[u] = Wf2[u];
    if (t < 16) sbf2[t] = bf2[t];
    sxi[t] = g_x[i0 * 16 + t];
    if (t < 16 * KNN) sj[t] = g_idx[i0 * KNN + t];
    __syncthreads();

    {
        const float4* gx4 = (const float4*)g_x;
        float4* sxj4 = (float4*)sxj;
        #pragma unroll
        for (int u = t; u < 16 * KNN * 4; u += 256) {
            int row = u >> 2, seg = u & 3;
            sxj4[u] = gx4[sj[row] * 4 + seg];
        }
    }
    __syncthreads();

    const int p = t >> 4;
    const int h = t & 15;
    const int i = i0 + p;

    // ---- feats ----
    float pre = sbe[h];
    #pragma unroll
    for (int d = 0; d < 16; ++d) pre = fmaf(sxi[p * 16 + d], sWd[d * 16 + h], pre);

    float fsum = 0.0f;
    #pragma unroll
    for (int k = 0; k < KNN; ++k) {
        const float* xj = sxj + (p * KNN + k) * 16;
        float m = pre;
        #pragma unroll
        for (int d = 0; d < 16; ++d) m = fmaf(xj[d], sWb[d * 16 + h], m);
        fsum += silu_fast(m);
    }
    sfe[p * 16 + h] = fsum * 0.125f;
    __syncthreads();

    // ---- f1 (each thread does channels h and h+16) ----
    {
        float a0 = sbf1[h], a1 = sbf1[h + 16];
        #pragma unroll
        for (int d = 0; d < 16; ++d) {
            float fe = sfe[p * 16 + d];
            a0 = fmaf(fe, sWf1[d * 32 + h], a0);
            a1 = fmaf(fe, sWf1[d * 32 + h + 16], a1);
        }
        sf1[p * 32 + h]      = silu_fast(a0);
        sf1[p * 32 + h + 16] = silu_fast(a1);
    }
    __syncthreads();

    // ---- f2 + output ----
    {
        float a = sbf2[h];
        #pragma unroll
        for (int d = 0; d < 32; ++d) a = fmaf(sf1[p * 32 + d], sWf2[d * 16 + h], a);
        out[i * (16 + DIN) + h] = a;
    }
    if (h < DIN)
        out[i * (16 + DIN) + 16 + h] = xp[i * DIN + h];
}

// ============================================================
extern "C" void kernel_launch(void* const* d_in, const int* in_sizes, int n_in,
                              void* d_out, int out_size)
{
    const float* xp  = (const float*)d_in[0];
    const float* W1  = (const float*)d_in[1];
    const float* b1  = (const float*)d_in[2];
    const float* W2  = (const float*)d_in[3];
    const float* b2  = (const float*)d_in[4];
    const float* W3  = (const float*)d_in[5];
    const float* b3  = (const float*)d_in[6];
    const float* We  = (const float*)d_in[7];
    const float* be  = (const float*)d_in[8];
    const float* Wf1 = (const float*)d_in[9];
    const float* bf1 = (const float*)d_in[10];
    const float* Wf2 = (const float*)d_in[11];
    const float* bf2 = (const float*)d_in[12];
    float* out = (float*)d_out;

    mlp_kernel<<<N / 256, 256>>>(xp, W1, b1, W2, b2, W3, b3);
    zeroh_kernel<<<1, NBIN>>>();
    hist_kernel<<<N / 256, 256>>>();
    scan_kernel<<<1, NBIN>>>();
    scatter_kernel<<<N / 256, 256>>>();
    cbound_kernel<<<1, NCHUNK>>>();
    knn_zig_kernel<<<N / QCTA, 256>>>();
    merge_kernel<<<N / 128, 128>>>();
    feats_out_kernel<<<N / 16, 256>>>(xp, We, be, Wf1, bf1, Wf2, bf2, out);
}

// round 12
// speedup vs baseline: 6.9292x; 1.0275x over previous
#include <cuda_runtime.h>
#include <cuda_fp16.h>
#include <math.h>
#include <float.h>
#include <stdint.h>

#define N       16384
#define DIN     13
#define KNN     8
#define NBIN    1024
#define QCTA    64               // sorted queries per CTA
#define CHUNK   128              // j per chunk
#define NCHUNK  (N / CHUNK)      // 128
#define NTILE   (CHUNK / 8)      // 16 tiles per chunk
#define NTILES  (N / 8)          // 2048 global tiles
#define NLIST   8                // 4 t4-slices x 2 tile-halves
#define EPSA    1e-3f            // abs margin on d2 threshold (MMA approx)
#define SLACK   0.02f            // key slack for chunk bounds (> bin width)

typedef unsigned long long ull;

// ---- scratch (no allocs allowed) ----
__device__ float  g_x[N * 16];            // embedded points (original order)
__device__ float  g_sq[N];
__device__ float  g_key[N];
__device__ int    g_hist[NBIN];
__device__ int    g_off[NBIN];
__device__ float  g_pkey[N];              // sorted keys
__device__ float  g_psq[N];               // sorted sq
__device__ int    g_pidx[N];              // sorted pos -> original index
__device__ __half g_ah[N * 16];           // sorted fp16 hi of -2x
__device__ __half g_am[N * 16];           // sorted fp16 mid of -2x
__device__ uint4  g_bf[NCHUNK * NTILE * 32]; // sorted B fragments
__device__ float  g_clo[NCHUNK], g_chi[NCHUNK];
__device__ float  g_tlo[NTILES], g_thi[NTILES];
__device__ ull    g_pk[N * NLIST * KNN];  // packed (flipped d | idx)
__device__ int    g_idx[N * KNN];         // final knn (original indices)

__device__ __forceinline__ float silu_f(float v) { return v / (1.0f + expf(-v)); }
__device__ __forceinline__ float silu_fast(float v) { return __fdividef(v, 1.0f + __expf(-v)); }
__device__ __forceinline__ int keybin(float k) {
    int b = (int)((k + 5.0f) * (NBIN / 10.0f));
    return b < 0 ? 0 : (b > NBIN - 1 ? NBIN - 1 : b);
}
__device__ __forceinline__ uint32_t smem_u32(const void* p) {
    uint32_t a;
    asm("{ .reg .u64 t; cvta.to.shared.u64 t, %1; cvt.u32.u64 %0, t; }"
        : "=r"(a) : "l"(p));
    return a;
}
__device__ __forceinline__ void cp_async16(uint32_t saddr, const void* g) {
    asm volatile("cp.async.cg.shared.global [%0], [%1], 16;" :: "r"(saddr), "l"(g));
}
#define CP_COMMIT() asm volatile("cp.async.commit_group;" ::: "memory")
#define CP_WAIT0()  asm volatile("cp.async.wait_group 0;" ::: "memory")

__device__ __forceinline__ void atomicMinF(float* addr, float v) {
    if (v >= 0.0f) atomicMin((int*)addr, __float_as_int(v));
    else           atomicMax((unsigned int*)addr, __float_as_uint(v));
}
__device__ __forceinline__ void atomicMaxF(float* addr, float v) {
    if (v >= 0.0f) atomicMax((int*)addr, __float_as_int(v));
    else           atomicMin((unsigned int*)addr, __float_as_uint(v));
}

// sortable uint from float (ascending uint == ascending float, any sign)
__device__ __forceinline__ uint32_t fkey(float f) {
    uint32_t u = __float_as_uint(f);
    return u ^ ((u >> 31) ? 0xFFFFFFFFu : 0x80000000u);
}

// m16n8k16 fp16 mma, fp32 accumulate (PTX sm_80+, valid under compute_103)
__device__ __forceinline__ void mma_f16(float& c0, float& c1, float& c2, float& c3,
                                        uint32_t a0, uint32_t a1, uint32_t a2, uint32_t a3,
                                        uint32_t b0, uint32_t b1) {
    asm volatile(
        "mma.sync.aligned.m16n8k16.row.col.f32.f16.f16.f32 "
        "{%0,%1,%2,%3}, {%4,%5,%6,%7}, {%8,%9}, {%0,%1,%2,%3};"
        : "+f"(c0), "+f"(c1), "+f"(c2), "+f"(c3)
        : "r"(a0), "r"(a1), "r"(a2), "r"(a3), "r"(b0), "r"(b1));
}

__device__ __forceinline__ void ins8(float* td, int* ti, float d, int j) {
    if (d < td[KNN - 1]) {
        td[KNN - 1] = d; ti[KNN - 1] = j;
        #pragma unroll
        for (int s = KNN - 1; s >= 1; --s) {
            if (td[s] < td[s - 1] || (td[s] == td[s - 1] && ti[s] < ti[s - 1])) {
                float tf = td[s]; td[s] = td[s-1]; td[s-1] = tf;
                int   tn = ti[s]; ti[s] = ti[s-1]; ti[s-1] = tn;
            }
        }
    }
}

// ============================================================
// Kernel 1: per-point MLP -> x, sq, key (original order)
// ============================================================
__global__ void mlp_kernel(const float* __restrict__ xp,
                           const float* __restrict__ W1, const float* __restrict__ b1,
                           const float* __restrict__ W2, const float* __restrict__ b2,
                           const float* __restrict__ W3, const float* __restrict__ b3)
{
    __shared__ float sW1[DIN * 8], sb1[8];
    __shared__ float sW2[8 * 16],  sb2[16];
    __shared__ float sW3[16 * 15], sb3[15];

    int t = threadIdx.x;
    for (int i = t; i < DIN * 8; i += blockDim.x) sW1[i] = W1[i];
    for (int i = t; i < 8;       i += blockDim.x) sb1[i] = b1[i];
    for (int i = t; i < 8 * 16;  i += blockDim.x) sW2[i] = W2[i];
    for (int i = t; i < 16;      i += blockDim.x) sb2[i] = b2[i];
    for (int i = t; i < 16 * 15; i += blockDim.x) sW3[i] = W3[i];
    for (int i = t; i < 15;      i += blockDim.x) sb3[i] = b3[i];
    __syncthreads();

    int i = blockIdx.x * blockDim.x + t;
    if (i >= N) return;

    float in[DIN];
    #pragma unroll
    for (int d = 0; d < DIN; ++d) in[d] = xp[i * DIN + d];

    float h1[8];
    #pragma unroll
    for (int h = 0; h < 8; ++h) {
        float a = sb1[h];
        #pragma unroll
        for (int d = 0; d < DIN; ++d) a = fmaf(in[d], sW1[d * 8 + h], a);
        h1[h] = silu_f(a);
    }
    float h2[16];
    #pragma unroll
    for (int h = 0; h < 16; ++h) {
        float a = sb2[h];
        #pragma unroll
        for (int d = 0; d < 8; ++d) a = fmaf(h1[d], sW2[d * 16 + h], a);
        h2[h] = silu_f(a);
    }
    float xr[16];
    #pragma unroll
    for (int h = 0; h < 15; ++h) {
        float a = sb3[h];
        #pragma unroll
        for (int d = 0; d < 16; ++d) a = fmaf(h2[d], sW3[d * 15 + h], a);
        xr[h] = a;
    }
    xr[15] = in[DIN - 1];

    float s = 0.0f;
    #pragma unroll
    for (int k = 0; k < 16; ++k) s = fmaf(xr[k], xr[k], s);

    #pragma unroll
    for (int k = 0; k < 16; ++k) g_x[i * 16 + k] = xr[k];
    g_sq[i]  = s;
    g_key[i] = xr[15];
}

// ============================================================
// Sorting by key (bucket sort)
// ============================================================
__global__ void zeroh_kernel() {
    int t = threadIdx.x;
    g_hist[t] = 0;
    if (t < NCHUNK) { g_clo[t] = FLT_MAX; g_chi[t] = -FLT_MAX; }
    #pragma unroll
    for (int u = t; u < NTILES; u += NBIN) { g_tlo[u] = FLT_MAX; g_thi[u] = -FLT_MAX; }
}

__global__ void hist_kernel() {
    int i = blockIdx.x * blockDim.x + threadIdx.x;
    atomicAdd(&g_hist[keybin(g_key[i])], 1);
}

__global__ void scan_kernel() {
    __shared__ int sh[NBIN];
    int t = threadIdx.x;
    int v = g_hist[t];
    sh[t] = v;
    __syncthreads();
    for (int off = 1; off < NBIN; off <<= 1) {
        int add = (t >= off) ? sh[t - off] : 0;
        __syncthreads();
        sh[t] += add;
        __syncthreads();
    }
    g_off[t] = sh[t] - v;
}

// scatter + build sorted A fp16 splits + B fragments + chunk/tile bounds
__global__ void scatter_kernel() {
    int i = blockIdx.x * blockDim.x + threadIdx.x;
    float key = g_key[i];
    int b = keybin(key);
    int pos = atomicAdd(&g_off[b], 1);

    float xr[16];
    #pragma unroll
    for (int d = 0; d < 16; ++d) xr[d] = g_x[i * 16 + d];

    g_pkey[pos] = key;
    g_psq[pos]  = g_sq[i];
    g_pidx[pos] = i;

    atomicMinF(&g_clo[pos / CHUNK], key);
    atomicMaxF(&g_chi[pos / CHUNK], key);
    atomicMinF(&g_tlo[pos >> 3], key);
    atomicMaxF(&g_thi[pos >> 3], key);

    #pragma unroll
    for (int k = 0; k < 16; ++k) {
        float a = -2.0f * xr[k];
        __half ah = __float2half_rn(a);
        __half am = __float2half_rn(a - __half2float(ah));
        g_ah[pos * 16 + k] = ah;
        g_am[pos * 16 + k] = am;
    }

    int T = pos >> 3, r = pos & 7;
    #pragma unroll
    for (int c = 0; c < 4; ++c) {
        int cc = 2 * c;
        float v0 = xr[cc], v1 = xr[cc + 1], v2 = xr[cc + 8], v3 = xr[cc + 9];
        __half h0 = __float2half_rn(v0), h1 = __float2half_rn(v1);
        __half h2 = __float2half_rn(v2), h3 = __float2half_rn(v3);
        __half m0 = __float2half_rn(v0 - __half2float(h0));
        __half m1 = __float2half_rn(v1 - __half2float(h1));
        __half m2 = __float2half_rn(v2 - __half2float(h2));
        __half m3 = __float2half_rn(v3 - __half2float(h3));
        uint4 f; __half2 p;
        p = __halves2half2(h0, h1); f.x = *(uint32_t*)&p;
        p = __halves2half2(h2, h3); f.y = *(uint32_t*)&p;
        p = __halves2half2(m0, m1); f.z = *(uint32_t*)&p;
        p = __halves2half2(m2, m3); f.w = *(uint32_t*)&p;
        g_bf[(size_t)T * 32 + r * 4 + c] = f;
    }
}

// ============================================================
// Kernel 2: zigzag-pruned KNN, prefetch + per-warp tile skipping
// ============================================================
__global__ void __launch_bounds__(256) knn_zig_kernel()
{
    __shared__ uint4 sBf[2][NTILE * 32];   // 2 x 8KB
    __shared__ float ssq[2][CHUNK];
    __shared__ int   sjd[2][CHUNK];

    const int t    = threadIdx.x;
    const int lane = t & 31;
    const int w    = t >> 5;
    const int qg   = w & 3;
    const int jh   = w >> 2;            // tile-half 0/1
    const int gid  = lane >> 2;
    const int t4   = lane & 3;
    const int b    = blockIdx.x;
    const int p0   = b * QCTA + qg * 16 + gid;   // sorted query rows
    const int p1   = p0 + 8;

    uint32_t ah[4], am[4];
    {
        const __half* A0h = g_ah + (size_t)p0 * 16;
        const __half* A1h = g_ah + (size_t)p1 * 16;
        const __half* A0m = g_am + (size_t)p0 * 16;
        const __half* A1m = g_am + (size_t)p1 * 16;
        ah[0] = *(const uint32_t*)&A0h[2 * t4];
        ah[1] = *(const uint32_t*)&A1h[2 * t4];
        ah[2] = *(const uint32_t*)&A0h[2 * t4 + 8];
        ah[3] = *(const uint32_t*)&A1h[2 * t4 + 8];
        am[0] = *(const uint32_t*)&A0m[2 * t4];
        am[1] = *(const uint32_t*)&A1m[2 * t4];
        am[2] = *(const uint32_t*)&A0m[2 * t4 + 8];
        am[3] = *(const uint32_t*)&A1m[2 * t4 + 8];
    }
    const float qk0 = g_pkey[p0], qk1 = g_pkey[p1];
    const float sq0 = g_psq[p0],  sq1 = g_psq[p1];

    float td0[KNN], td1[KNN];
    int   ti0[KNN], ti1[KNN];
    #pragma unroll
    for (int k = 0; k < KNN; ++k) {
        td0[k] = FLT_MAX; ti0[k] = 0x7fffffff;
        td1[k] = FLT_MAX; ti1[k] = 0x7fffffff;
    }

    uint32_t sB_addr[2], sq_addr[2], sj_addr[2];
    #pragma unroll
    for (int u = 0; u < 2; ++u) {
        sB_addr[u] = smem_u32(&sBf[u][0]);
        sq_addr[u] = smem_u32(&ssq[u][0]);
        sj_addr[u] = smem_u32(&sjd[u][0]);
    }

    auto stage = [&](int bf, int c) {
        const uint4* src = g_bf + (size_t)c * (NTILE * 32);
        cp_async16(sB_addr[bf] + (uint32_t)t * 16, src + t);
        cp_async16(sB_addr[bf] + (uint32_t)(t + 256) * 16, src + t + 256);
        if (t < 32) {
            cp_async16(sq_addr[bf] + (uint32_t)t * 16, (const float4*)(g_psq + c * CHUNK) + t);
            cp_async16(sj_addr[bf] + (uint32_t)t * 16, (const int4*)(g_pidx + c * CHUNK) + t);
        }
        CP_COMMIT();
    };

    const int h0 = b >> 1;
    int nxtR = h0 + 1, nxtL = h0 - 1;
    int aliveR = 1, aliveL = 1, tog = 0;
    int cur = h0, bufA = 0;

    stage(0, h0);
    CP_WAIT0();
    __syncthreads();

    while (cur >= 0) {
        // ---- predict next chunk and prefetch into bufA^1 ----
        int pred = -1;
        {
            int aR = aliveR && (nxtR < NCHUNK);
            int aL = aliveL && (nxtL >= 0);
            if (aR && aL) pred = (tog == 0) ? nxtR : nxtL;
            else if (aR)  pred = nxtR;
            else if (aL)  pred = nxtL;
        }
        if (pred >= 0) stage(bufA ^ 1, pred);

        // ---- compute this warp's 8 tiles from bufA (with tile-level skip) ----
        #pragma unroll
        for (int nt = 0; nt < 8; ++nt) {
            const int tl = jh * 8 + nt;
            const int gt = cur * NTILE + tl;

            // exact per-tile bound test (per-warp vote)
            float tlo = g_tlo[gt], thi = g_thi[gt];
            float gp0 = fmaxf(fmaxf(tlo - qk0, qk0 - thi), 0.0f);
            float gp1 = fmaxf(fmaxf(tlo - qk1, qk1 - thi), 0.0f);
            int nd = (gp0 * gp0 <= td0[KNN - 1] + sq0 + EPSA) ||
                     (gp1 * gp1 <= td1[KNN - 1] + sq1 + EPSA);
            if (!__any_sync(0xffffffffu, nd)) continue;

            uint4 f = sBf[bufA][tl * 32 + lane];
            const int jl = tl * 8 + 2 * t4;
            float2 s2 = *(const float2*)&ssq[bufA][jl];
            float c0 = s2.x, c1 = s2.y, c2 = s2.x, c3 = s2.y;
            mma_f16(c0, c1, c2, c3, ah[0], ah[1], ah[2], ah[3], f.x, f.y);
            mma_f16(c0, c1, c2, c3, ah[0], ah[1], ah[2], ah[3], f.z, f.w);
            mma_f16(c0, c1, c2, c3, am[0], am[1], am[2], am[3], f.x, f.y);
            if (fminf(c0, c1) < td0[KNN - 1]) {
                ins8(td0, ti0, c0, sjd[bufA][jl]); ins8(td0, ti0, c1, sjd[bufA][jl + 1]);
            }
            if (fminf(c2, c3) < td1[KNN - 1]) {
                ins8(td1, ti1, c2, sjd[bufA][jl]); ins8(td1, ti1, c3, sjd[bufA][jl + 1]);
            }
        }

        // ---- select next chunk (block vote) ----
        cur = -1;
        while (aliveR || aliveL) {
            int dir;
            if (aliveR && aliveL) { dir = tog; tog ^= 1; }
            else dir = aliveR ? 0 : 1;
            int c = (dir == 0) ? nxtR : nxtL;
            if (c < 0 || c >= NCHUNK) {
                if (dir == 0) aliveR = 0; else aliveL = 0;
                continue;
            }
            float bnd = (dir == 0) ? g_clo[c] : g_chi[c];
            float gp0 = (dir == 0) ? bnd - qk0 : qk0 - bnd;
            float gp1 = (dir == 0) ? bnd - qk1 : qk1 - bnd;
            gp0 = fmaxf(gp0 - SLACK, 0.0f);
            gp1 = fmaxf(gp1 - SLACK, 0.0f);
            float th0 = td0[KNN - 1] + sq0 + EPSA;
            float th1 = td1[KNN - 1] + sq1 + EPSA;
            int nd = (gp0 * gp0 <= th0) || (gp1 * gp1 <= th1);
            if (__syncthreads_or(nd)) {
                cur = c;
                if (dir == 0) nxtR++; else nxtL--;
                break;
            } else {
                if (dir == 0) aliveR = 0; else aliveL = 0;
            }
        }

        // ---- commit prefetch or reload on mispredict ----
        if (cur >= 0) {
            CP_WAIT0();
            __syncthreads();
            if (cur != pred) {
                stage(bufA ^ 1, cur);
                CP_WAIT0();
                __syncthreads();
            }
            bufA ^= 1;
        }
    }
    CP_WAIT0();

    // ---- write packed partial lists ----
    {
        const int li = jh * 4 + t4;
        int base0 = (p0 * NLIST + li) * KNN;
        int base1 = (p1 * NLIST + li) * KNN;
        #pragma unroll
        for (int k = 0; k < KNN; ++k) {
            g_pk[base0 + k] = ((ull)fkey(td0[k]) << 32) | (uint32_t)ti0[k];
            g_pk[base1 + k] = ((ull)fkey(td1[k]) << 32) | (uint32_t)ti1[k];
        }
    }
}

// ============================================================
// Kernel 3: parallel merge — 8 lanes per query, shfl min-reduce
// ============================================================
__global__ void __launch_bounds__(256) merge_kernel()
{
    int gi = blockIdx.x * 256 + threadIdx.x;
    int p  = gi >> 3;            // query (sorted position)
    int l  = gi & 7;             // list lane

    ull v[KNN];
    #pragma unroll
    for (int k = 0; k < KNN; ++k)
        v[k] = g_pk[(p * NLIST + l) * KNN + k];

    int oi = g_pidx[p];

    #pragma unroll
    for (int k = 0; k < KNN; ++k) {
        // local min over live entries
        ull m = v[0];
        #pragma unroll
        for (int u = 1; u < KNN; ++u) m = (v[u] < m) ? v[u] : m;
        // reduce across the 8-lane group
        #pragma unroll
        for (int off = 1; off < 8; off <<= 1) {
            ull o = __shfl_xor_sync(0xffffffffu, m, off, 8);
            m = (o < m) ? o : m;
        }
        if (l == 0)
            g_idx[oi * KNN + k] = (int)(uint32_t)(m & 0xffffffffull);
        // remove winner (values unique across lists)
        #pragma unroll
        for (int u = 0; u < KNN; ++u)
            if (v[u] == m) v[u] = ~0ull;
    }
}

// ============================================================
// Kernel 4: fused edge messages + mean + out MLP + concat
// ============================================================
__global__ void __launch_bounds__(256)
feats_out_kernel(const float* __restrict__ xp,
                 const float* __restrict__ We,  const float* __restrict__ be,
                 const float* __restrict__ Wf1, const float* __restrict__ bf1,
                 const float* __restrict__ Wf2, const float* __restrict__ bf2,
                 float* __restrict__ out)
{
    __shared__ float sWd[16 * 16];
    __shared__ float sWb[16 * 16];
    __shared__ float sbe[16];
    __shared__ float sWf1[16 * 32], sbf1[32];
    __shared__ float sWf2[32 * 16], sbf2[16];
    __shared__ float sxi[16 * 16];
    __shared__ int   sj[16 * KNN];
    __shared__ float sxj[16 * KNN * 16];
    __shared__ float sfe[16 * 16];
    __shared__ float sf1[16 * 32];

    const int t  = threadIdx.x;
    const int i0 = blockIdx.x * 16;

    {
        float top = We[t];
        float bot = We[256 + t];
        sWd[t] = top - bot;
        sWb[t] = bot;
    }
    if (t < 16) sbe[t] = be[t];
    for (int u = t; u < 16 * 32; u += 256) sWf1[u] = Wf1[u];
    if (t < 32) sbf1[t] = bf1[t];
    for (int u = t; u < 32 * 16; u += 256) sWf2[u] = Wf2[u];
    if (t < 16) sbf2[t] = bf2[t];
    sxi[t] = g_x[i0 * 16 + t];
    if (t < 16 * KNN) sj[t] = g_idx[i0 * KNN + t];
    __syncthreads();

    {
        const float4* gx4 = (const float4*)g_x;
        float4* sxj4 = (float4*)sxj;
        #pragma unroll
        for (int u = t; u < 16 * KNN * 4; u += 256) {
            int row = u >> 2, seg = u & 3;
            sxj4[u] = gx4[sj[row] * 4 + seg];
        }
    }
    __syncthreads();

    const int p = t >> 4;
    const int h = t & 15;
    const int i = i0 + p;

    float pre = sbe[h];
    #pragma unroll
    for (int d = 0; d < 16; ++d) pre = fmaf(sxi[p * 16 + d], sWd[d * 16 + h], pre);

    float fsum = 0.0f;
    #pragma unroll
    for (int k = 0; k < KNN; ++k) {
        const float* xj = sxj + (p * KNN + k) * 16;
        float m = pre;
        #pragma unroll
        for (int d = 0; d < 16; ++d) m = fmaf(xj[d], sWb[d * 16 + h], m);
        fsum += silu_fast(m);
    }
    sfe[p * 16 + h] = fsum * 0.125f;
    __syncthreads();

    {
        float a0 = sbf1[h], a1 = sbf1[h + 16];
        #pragma unroll
        for (int d = 0; d < 16; ++d) {
            float fe = sfe[p * 16 + d];
            a0 = fmaf(fe, sWf1[d * 32 + h], a0);
            a1 = fmaf(fe, sWf1[d * 32 + h + 16], a1);
        }
        sf1[p * 32 + h]      = silu_fast(a0);
        sf1[p * 32 + h + 16] = silu_fast(a1);
    }
    __syncthreads();

    {
        float a = sbf2[h];
        #pragma unroll
        for (int d = 0; d < 32; ++d) a = fmaf(sf1[p * 32 + d], sWf2[d * 16 + h], a);
        out[i * (16 + DIN) + h] = a;
    }
    if (h < DIN)
        out[i * (16 + DIN) + 16 + h] = xp[i * DIN + h];
}

// ============================================================
extern "C" void kernel_launch(void* const* d_in, const int* in_sizes, int n_in,
                              void* d_out, int out_size)
{
    const float* xp  = (const float*)d_in[0];
    const float* W1  = (const float*)d_in[1];
    const float* b1  = (const float*)d_in[2];
    const float* W2  = (const float*)d_in[3];
    const float* b2  = (const float*)d_in[4];
    const float* W3  = (const float*)d_in[5];
    const float* b3  = (const float*)d_in[6];
    const float* We  = (const float*)d_in[7];
    const float* be  = (const float*)d_in[8];
    const float* Wf1 = (const float*)d_in[9];
    const float* bf1 = (const float*)d_in[10];
    const float* Wf2 = (const float*)d_in[11];
    const float* bf2 = (const float*)d_in[12];
    float* out = (float*)d_out;

    mlp_kernel<<<N / 256, 256>>>(xp, W1, b1, W2, b2, W3, b3);
    zeroh_kernel<<<1, NBIN>>>();
    hist_kernel<<<N / 256, 256>>>();
    scan_kernel<<<1, NBIN>>>();
    scatter_kernel<<<N / 256, 256>>>();
    knn_zig_kernel<<<N / QCTA, 256>>>();
    merge_kernel<<<(N * 8) / 256, 256>>>();
    feats_out_kernel<<<N / 16, 256>>>(xp, We, be, Wf1, bf1, Wf2, bf2, out);
}

// round 13
// speedup vs baseline: 7.0632x; 1.0193x over previous
#include <cuda_runtime.h>
#include <cuda_fp16.h>
#include <math.h>
#include <float.h>
#include <stdint.h>

#define N       16384
#define DIN     13
#define KNN     8
#define NBIN    1024
#define QCTA    64               // sorted queries per CTA
#define CHUNK   128              // j per chunk
#define NCHUNK  (N / CHUNK)      // 128
#define NTILE   (CHUNK / 8)      // 16 tiles per chunk
#define NTILES  (N / 8)          // 2048 global tiles
#define NLIST   8                // 4 t4-slices x 2 tile-halves
#define EPSA    1e-3f            // abs margin on d2 threshold (MMA approx)
#define SLACK   0.02f            // key slack for chunk bounds (> bin width)

typedef unsigned long long ull;

// ---- scratch (no allocs allowed) ----
__device__ float  g_x[N * 16];            // embedded points (original order)
__device__ float  g_sq[N];
__device__ float  g_key[N];
__device__ int    g_hist[NBIN];
__device__ int    g_off[NBIN];
__device__ float  g_pkey[N];              // sorted keys
__device__ float  g_psq[N];               // sorted sq
__device__ int    g_pidx[N];              // sorted pos -> original index
__device__ __half g_ah[N * 16];           // sorted fp16 hi of -2x
__device__ __half g_am[N * 16];           // sorted fp16 mid of -2x
__device__ uint4  g_bf[NCHUNK * NTILE * 32]; // sorted B fragments
__device__ float  g_clo[NCHUNK], g_chi[NCHUNK];
__device__ float  g_tlo[NTILES], g_thi[NTILES];
__device__ int    g_idx[N * KNN];         // final knn (original indices)

__device__ __forceinline__ float silu_f(float v) { return v / (1.0f + expf(-v)); }
__device__ __forceinline__ float silu_fast(float v) { return __fdividef(v, 1.0f + __expf(-v)); }
__device__ __forceinline__ int keybin(float k) {
    int b = (int)((k + 5.0f) * (NBIN / 10.0f));
    return b < 0 ? 0 : (b > NBIN - 1 ? NBIN - 1 : b);
}
__device__ __forceinline__ uint32_t smem_u32(const void* p) {
    uint32_t a;
    asm("{ .reg .u64 t; cvta.to.shared.u64 t, %1; cvt.u32.u64 %0, t; }"
        : "=r"(a) : "l"(p));
    return a;
}
__device__ __forceinline__ void cp_async16(uint32_t saddr, const void* g) {
    asm volatile("cp.async.cg.shared.global [%0], [%1], 16;" :: "r"(saddr), "l"(g));
}
#define CP_COMMIT() asm volatile("cp.async.commit_group;" ::: "memory")
#define CP_WAIT0()  asm volatile("cp.async.wait_group 0;" ::: "memory")

__device__ __forceinline__ void atomicMinF(float* addr, float v) {
    if (v >= 0.0f) atomicMin((int*)addr, __float_as_int(v));
    else           atomicMax((unsigned int*)addr, __float_as_uint(v));
}
__device__ __forceinline__ void atomicMaxF(float* addr, float v) {
    if (v >= 0.0f) atomicMax((int*)addr, __float_as_int(v));
    else           atomicMin((unsigned int*)addr, __float_as_uint(v));
}

// sortable uint from float (ascending uint == ascending float, any sign)
__device__ __forceinline__ uint32_t fkey(float f) {
    uint32_t u = __float_as_uint(f);
    return u ^ ((u >> 31) ? 0xFFFFFFFFu : 0x80000000u);
}

// m16n8k16 fp16 mma, fp32 accumulate (PTX sm_80+, valid under compute_103)
__device__ __forceinline__ void mma_f16(float& c0, float& c1, float& c2, float& c3,
                                        uint32_t a0, uint32_t a1, uint32_t a2, uint32_t a3,
                                        uint32_t b0, uint32_t b1) {
    asm volatile(
        "mma.sync.aligned.m16n8k16.row.col.f32.f16.f16.f32 "
        "{%0,%1,%2,%3}, {%4,%5,%6,%7}, {%8,%9}, {%0,%1,%2,%3};"
        : "+f"(c0), "+f"(c1), "+f"(c2), "+f"(c3)
        : "r"(a0), "r"(a1), "r"(a2), "r"(a3), "r"(b0), "r"(b1));
}

__device__ __forceinline__ void ins8(float* td, int* ti, float d, int j) {
    if (d < td[KNN - 1]) {
        td[KNN - 1] = d; ti[KNN - 1] = j;
        #pragma unroll
        for (int s = KNN - 1; s >= 1; --s) {
            if (td[s] < td[s - 1] || (td[s] == td[s - 1] && ti[s] < ti[s - 1])) {
                float tf = td[s]; td[s] = td[s-1]; td[s-1] = tf;
                int   tn = ti[s]; ti[s] = ti[s-1]; ti[s-1] = tn;
            }
        }
    }
}

// ============================================================
// Kernel 0: zero hist + bound arrays
// ============================================================
__global__ void zeroh_kernel() {
    int t = threadIdx.x;
    g_hist[t] = 0;
    if (t < NCHUNK) { g_clo[t] = FLT_MAX; g_chi[t] = -FLT_MAX; }
    #pragma unroll
    for (int u = t; u < NTILES; u += NBIN) { g_tlo[u] = FLT_MAX; g_thi[u] = -FLT_MAX; }
}

// ============================================================
// Kernel 1: per-point MLP -> x, sq, key + histogram (fused)
// ============================================================
__global__ void mlp_kernel(const float* __restrict__ xp,
                           const float* __restrict__ W1, const float* __restrict__ b1,
                           const float* __restrict__ W2, const float* __restrict__ b2,
                           const float* __restrict__ W3, const float* __restrict__ b3)
{
    __shared__ float sW1[DIN * 8], sb1[8];
    __shared__ float sW2[8 * 16],  sb2[16];
    __shared__ float sW3[16 * 15], sb3[15];

    int t = threadIdx.x;
    for (int i = t; i < DIN * 8; i += blockDim.x) sW1[i] = W1[i];
    for (int i = t; i < 8;       i += blockDim.x) sb1[i] = b1[i];
    for (int i = t; i < 8 * 16;  i += blockDim.x) sW2[i] = W2[i];
    for (int i = t; i < 16;      i += blockDim.x) sb2[i] = b2[i];
    for (int i = t; i < 16 * 15; i += blockDim.x) sW3[i] = W3[i];
    for (int i = t; i < 15;      i += blockDim.x) sb3[i] = b3[i];
    __syncthreads();

    int i = blockIdx.x * blockDim.x + t;
    if (i >= N) return;

    float in[DIN];
    #pragma unroll
    for (int d = 0; d < DIN; ++d) in[d] = xp[i * DIN + d];

    float h1[8];
    #pragma unroll
    for (int h = 0; h < 8; ++h) {
        float a = sb1[h];
        #pragma unroll
        for (int d = 0; d < DIN; ++d) a = fmaf(in[d], sW1[d * 8 + h], a);
        h1[h] = silu_f(a);
    }
    float h2[16];
    #pragma unroll
    for (int h = 0; h < 16; ++h) {
        float a = sb2[h];
        #pragma unroll
        for (int d = 0; d < 8; ++d) a = fmaf(h1[d], sW2[d * 16 + h], a);
        h2[h] = silu_f(a);
    }
    float xr[16];
    #pragma unroll
    for (int h = 0; h < 15; ++h) {
        float a = sb3[h];
        #pragma unroll
        for (int d = 0; d < 16; ++d) a = fmaf(h2[d], sW3[d * 15 + h], a);
        xr[h] = a;
    }
    xr[15] = in[DIN - 1];

    float s = 0.0f;
    #pragma unroll
    for (int k = 0; k < 16; ++k) s = fmaf(xr[k], xr[k], s);

    #pragma unroll
    for (int k = 0; k < 16; ++k) g_x[i * 16 + k] = xr[k];
    g_sq[i]  = s;
    g_key[i] = xr[15];
    atomicAdd(&g_hist[keybin(xr[15])], 1);
}

// ============================================================
// Kernel 2: single-warp exclusive scan of 1024 bins
// ============================================================
__global__ void scan_kernel() {
    int lane = threadIdx.x;     // 32 threads
    int base = lane * 32;
    int vals[32];
    int sum = 0;
    #pragma unroll
    for (int i = 0; i < 32; ++i) { vals[i] = g_hist[base + i]; sum += vals[i]; }
    int inc = sum;
    #pragma unroll
    for (int d = 1; d < 32; d <<= 1) {
        int o = __shfl_up_sync(0xffffffffu, inc, d);
        if (lane >= d) inc += o;
    }
    int run = inc - sum;   // exclusive offset of this lane's block
    #pragma unroll
    for (int i = 0; i < 32; ++i) { g_off[base + i] = run; run += vals[i]; }
}

// ============================================================
// Kernel 3: scatter + sorted A splits + B fragments + bounds
// ============================================================
__global__ void scatter_kernel() {
    int i = blockIdx.x * blockDim.x + threadIdx.x;
    float key = g_key[i];
    int b = keybin(key);
    int pos = atomicAdd(&g_off[b], 1);

    float xr[16];
    #pragma unroll
    for (int d = 0; d < 16; ++d) xr[d] = g_x[i * 16 + d];

    g_pkey[pos] = key;
    g_psq[pos]  = g_sq[i];
    g_pidx[pos] = i;

    atomicMinF(&g_clo[pos / CHUNK], key);
    atomicMaxF(&g_chi[pos / CHUNK], key);
    atomicMinF(&g_tlo[pos >> 3], key);
    atomicMaxF(&g_thi[pos >> 3], key);

    #pragma unroll
    for (int k = 0; k < 16; ++k) {
        float a = -2.0f * xr[k];
        __half ah = __float2half_rn(a);
        __half am = __float2half_rn(a - __half2float(ah));
        g_ah[pos * 16 + k] = ah;
        g_am[pos * 16 + k] = am;
    }

    int T = pos >> 3, r = pos & 7;
    #pragma unroll
    for (int c = 0; c < 4; ++c) {
        int cc = 2 * c;
        float v0 = xr[cc], v1 = xr[cc + 1], v2 = xr[cc + 8], v3 = xr[cc + 9];
        __half h0 = __float2half_rn(v0), h1 = __float2half_rn(v1);
        __half h2 = __float2half_rn(v2), h3 = __float2half_rn(v3);
        __half m0 = __float2half_rn(v0 - __half2float(h0));
        __half m1 = __float2half_rn(v1 - __half2float(h1));
        __half m2 = __float2half_rn(v2 - __half2float(h2));
        __half m3 = __float2half_rn(v3 - __half2float(h3));
        uint4 f; __half2 p;
        p = __halves2half2(h0, h1); f.x = *(uint32_t*)&p;
        p = __halves2half2(h2, h3); f.y = *(uint32_t*)&p;
        p = __halves2half2(m0, m1); f.z = *(uint32_t*)&p;
        p = __halves2half2(m2, m3); f.w = *(uint32_t*)&p;
        g_bf[(size_t)T * 32 + r * 4 + c] = f;
    }
}

// ============================================================
// Kernel 4: zigzag-pruned KNN + in-CTA merge
// ============================================================
__global__ void __launch_bounds__(256) knn_zig_kernel()
{
    __shared__ uint4 sBf[2][NTILE * 32];   // 2 x 8KB
    __shared__ float ssq[2][CHUNK];
    __shared__ int   sjd[2][CHUNK];
    __shared__ ull   smg[QCTA * NLIST];    // 4KB per merge pass slot? -> full 64x8
    // full merge buffer: 64 queries x 8 lists x 8 entries = 32KB
    __shared__ ull   smerge[QCTA * NLIST * KNN];

    const int t    = threadIdx.x;
    const int lane = t & 31;
    const int w    = t >> 5;
    const int qg   = w & 3;
    const int jh   = w >> 2;            // tile-half 0/1
    const int gid  = lane >> 2;
    const int t4   = lane & 3;
    const int b    = blockIdx.x;
    const int p0   = b * QCTA + qg * 16 + gid;   // sorted query rows
    const int p1   = p0 + 8;

    uint32_t ah[4], am[4];
    {
        const __half* A0h = g_ah + (size_t)p0 * 16;
        const __half* A1h = g_ah + (size_t)p1 * 16;
        const __half* A0m = g_am + (size_t)p0 * 16;
        const __half* A1m = g_am + (size_t)p1 * 16;
        ah[0] = *(const uint32_t*)&A0h[2 * t4];
        ah[1] = *(const uint32_t*)&A1h[2 * t4];
        ah[2] = *(const uint32_t*)&A0h[2 * t4 + 8];
        ah[3] = *(const uint32_t*)&A1h[2 * t4 + 8];
        am[0] = *(const uint32_t*)&A0m[2 * t4];
        am[1] = *(const uint32_t*)&A1m[2 * t4];
        am[2] = *(const uint32_t*)&A0m[2 * t4 + 8];
        am[3] = *(const uint32_t*)&A1m[2 * t4 + 8];
    }
    const float qk0 = g_pkey[p0], qk1 = g_pkey[p1];
    const float sq0 = g_psq[p0],  sq1 = g_psq[p1];

    float td0[KNN], td1[KNN];
    int   ti0[KNN], ti1[KNN];
    #pragma unroll
    for (int k = 0; k < KNN; ++k) {
        td0[k] = FLT_MAX; ti0[k] = 0x7fffffff;
        td1[k] = FLT_MAX; ti1[k] = 0x7fffffff;
    }

    uint32_t sB_addr[2], sq_addr[2], sj_addr[2];
    #pragma unroll
    for (int u = 0; u < 2; ++u) {
        sB_addr[u] = smem_u32(&sBf[u][0]);
        sq_addr[u] = smem_u32(&ssq[u][0]);
        sj_addr[u] = smem_u32(&sjd[u][0]);
    }

    auto stage = [&](int bf, int c) {
        const uint4* src = g_bf + (size_t)c * (NTILE * 32);
        cp_async16(sB_addr[bf] + (uint32_t)t * 16, src + t);
        cp_async16(sB_addr[bf] + (uint32_t)(t + 256) * 16, src + t + 256);
        if (t < 32) {
            cp_async16(sq_addr[bf] + (uint32_t)t * 16, (const float4*)(g_psq + c * CHUNK) + t);
            cp_async16(sj_addr[bf] + (uint32_t)t * 16, (const int4*)(g_pidx + c * CHUNK) + t);
        }
        CP_COMMIT();
    };

    const int h0 = b >> 1;
    int nxtR = h0 + 1, nxtL = h0 - 1;
    int aliveR = 1, aliveL = 1, tog = 0;
    int cur = h0, bufA = 0;

    stage(0, h0);
    CP_WAIT0();
    __syncthreads();

    while (cur >= 0) {
        int pred = -1;
        {
            int aR = aliveR && (nxtR < NCHUNK);
            int aL = aliveL && (nxtL >= 0);
            if (aR && aL) pred = (tog == 0) ? nxtR : nxtL;
            else if (aR)  pred = nxtR;
            else if (aL)  pred = nxtL;
        }
        if (pred >= 0) stage(bufA ^ 1, pred);

        #pragma unroll
        for (int nt = 0; nt < 8; ++nt) {
            const int tl = jh * 8 + nt;
            const int gt = cur * NTILE + tl;

            float tlo = g_tlo[gt], thi = g_thi[gt];
            float gp0 = fmaxf(fmaxf(tlo - qk0, qk0 - thi), 0.0f);
            float gp1 = fmaxf(fmaxf(tlo - qk1, qk1 - thi), 0.0f);
            int nd = (gp0 * gp0 <= td0[KNN - 1] + sq0 + EPSA) ||
                     (gp1 * gp1 <= td1[KNN - 1] + sq1 + EPSA);
            if (!__any_sync(0xffffffffu, nd)) continue;

            uint4 f = sBf[bufA][tl * 32 + lane];
            const int jl = tl * 8 + 2 * t4;
            float2 s2 = *(const float2*)&ssq[bufA][jl];
            float c0 = s2.x, c1 = s2.y, c2 = s2.x, c3 = s2.y;
            mma_f16(c0, c1, c2, c3, ah[0], ah[1], ah[2], ah[3], f.x, f.y);
            mma_f16(c0, c1, c2, c3, ah[0], ah[1], ah[2], ah[3], f.z, f.w);
            mma_f16(c0, c1, c2, c3, am[0], am[1], am[2], am[3], f.x, f.y);
            if (fminf(c0, c1) < td0[KNN - 1]) {
                ins8(td0, ti0, c0, sjd[bufA][jl]); ins8(td0, ti0, c1, sjd[bufA][jl + 1]);
            }
            if (fminf(c2, c3) < td1[KNN - 1]) {
                ins8(td1, ti1, c2, sjd[bufA][jl]); ins8(td1, ti1, c3, sjd[bufA][jl + 1]);
            }
        }

        cur = -1;
        while (aliveR || aliveL) {
            int dir;
            if (aliveR && aliveL) { dir = tog; tog ^= 1; }
            else dir = aliveR ? 0 : 1;
            int c = (dir == 0) ? nxtR : nxtL;
            if (c < 0 || c >= NCHUNK) {
                if (dir == 0) aliveR = 0; else aliveL = 0;
                continue;
            }
            float bnd = (dir == 0) ? g_clo[c] : g_chi[c];
            float gp0 = (dir == 0) ? bnd - qk0 : qk0 - bnd;
            float gp1 = (dir == 0) ? bnd - qk1 : qk1 - bnd;
            gp0 = fmaxf(gp0 - SLACK, 0.0f);
            gp1 = fmaxf(gp1 - SLACK, 0.0f);
            float th0 = td0[KNN - 1] + sq0 + EPSA;
            float th1 = td1[KNN - 1] + sq1 + EPSA;
            int nd = (gp0 * gp0 <= th0) || (gp1 * gp1 <= th1);
            if (__syncthreads_or(nd)) {
                cur = c;
                if (dir == 0) nxtR++; else nxtL--;
                break;
            } else {
                if (dir == 0) aliveR = 0; else aliveL = 0;
            }
        }

        if (cur >= 0) {
            CP_WAIT0();
            __syncthreads();
            if (cur != pred) {
                stage(bufA ^ 1, cur);
                CP_WAIT0();
                __syncthreads();
            }
            bufA ^= 1;
        }
    }
    CP_WAIT0();

    // ---- in-CTA merge: write packed lists to smem ----
    {
        const int li = jh * 4 + t4;
        const int q0l = qg * 16 + gid;        // local query 0..15 of group
        const int q1l = q0l + 8;
        #pragma unroll
        for (int k = 0; k < KNN; ++k) {
            smerge[(q0l * NLIST + li) * KNN + k] = ((ull)fkey(td0[k]) << 32) | (uint32_t)ti0[k];
            smerge[(q1l * NLIST + li) * KNN + k] = ((ull)fkey(td1[k]) << 32) | (uint32_t)ti1[k];
        }
    }
    __syncthreads();

    // 512 (query,list) units on 256 threads: 2 passes, 8-lane shfl merge
    #pragma unroll
    for (int pass = 0; pass < 2; ++pass) {
        int u  = pass * 256 + t;
        int q  = u >> 3;          // local query 0..63
        int l  = u & 7;
        ull v[KNN];
        #pragma unroll
        for (int k = 0; k < KNN; ++k)
            v[k] = smerge[(q * NLIST + l) * KNN + k];
        int oi = g_pidx[b * QCTA + q];
        #pragma unroll
        for (int k = 0; k < KNN; ++k) {
            ull m = v[0];
            #pragma unroll
            for (int x = 1; x < KNN; ++x) m = (v[x] < m) ? v[x] : m;
            #pragma unroll
            for (int off = 1; off < 8; off <<= 1) {
                ull o = __shfl_xor_sync(0xffffffffu, m, off, 8);
                m = (o < m) ? o : m;
            }
            if (l == 0)
                g_idx[oi * KNN + k] = (int)(uint32_t)(m & 0xffffffffull);
            #pragma unroll
            for (int x = 0; x < KNN; ++x)
                if (v[x] == m) v[x] = ~0ull;
        }
    }
    (void)smg;
}

// ============================================================
// Kernel 5: fused edge messages + mean + out MLP + concat
// ============================================================
__global__ void __launch_bounds__(256)
feats_out_kernel(const float* __restrict__ xp,
                 const float* __restrict__ We,  const float* __restrict__ be,
                 const float* __restrict__ Wf1, const float* __restrict__ bf1,
                 const float* __restrict__ Wf2, const float* __restrict__ bf2,
                 float* __restrict__ out)
{
    __shared__ float sWd[16 * 16];
    __shared__ float sWb[16 * 16];
    __shared__ float sbe[16];
    __shared__ float sWf1[16 * 32], sbf1[32];
    __shared__ float sWf2[32 * 16], sbf2[16];
    __shared__ float sxi[16 * 16];
    __shared__ int   sj[16 * KNN];
    __shared__ float sxj[16 * KNN * 16];
    __shared__ float sfe[16 * 16];
    __shared__ float sf1[16 * 32];

    const int t  = threadIdx.x;
    const int i0 = blockIdx.x * 16;

    {
        float top = We[t];
        float bot = We[256 + t];
        sWd[t] = top - bot;
        sWb[t] = bot;
    }
    if (t < 16) sbe[t] = be[t];
    for (int u = t; u < 16 * 32; u += 256) sWf1[u] = Wf1[u];
    if (t < 32) sbf1[t] = bf1[t];
    for (int u = t; u < 32 * 16; u += 256) sWf2[u] = Wf2[u];
    if (t < 16) sbf2[t] = bf2[t];
    sxi[t] = g_x[i0 * 16 + t];
    if (t < 16 * KNN) sj[t] = g_idx[i0 * KNN + t];
    __syncthreads();

    {
        const float4* gx4 = (const float4*)g_x;
        float4* sxj4 = (float4*)sxj;
        #pragma unroll
        for (int u = t; u < 16 * KNN * 4; u += 256) {
            int row = u >> 2, seg = u & 3;
            sxj4[u] = gx4[sj[row] * 4 + seg];
        }
    }
    __syncthreads();

    const int p = t >> 4;
    const int h = t & 15;
    const int i = i0 + p;

    float pre = sbe[h];
    #pragma unroll
    for (int d = 0; d < 16; ++d) pre = fmaf(sxi[p * 16 + d], sWd[d * 16 + h], pre);

    float fsum = 0.0f;
    #pragma unroll
    for (int k = 0; k < KNN; ++k) {
        const float* xj = sxj + (p * KNN + k) * 16;
        float m = pre;
        #pragma unroll
        for (int d = 0; d < 16; ++d) m = fmaf(xj[d], sWb[d * 16 + h], m);
        fsum += silu_fast(m);
    }
    sfe[p * 16 + h] = fsum * 0.125f;
    __syncthreads();

    {
        float a0 = sbf1[h], a1 = sbf1[h + 16];
        #pragma unroll
        for (int d = 0; d < 16; ++d) {
            float fe = sfe[p * 16 + d];
            a0 = fmaf(fe, sWf1[d * 32 + h], a0);
            a1 = fmaf(fe, sWf1[d * 32 + h + 16], a1);
        }
        sf1[p * 32 + h]      = silu_fast(a0);
        sf1[p * 32 + h + 16] = silu_fast(a1);
    }
    __syncthreads();

    {
        float a = sbf2[h];
        #pragma unroll
        for (int d = 0; d < 32; ++d) a = fmaf(sf1[p * 32 + d], sWf2[d * 16 + h], a);
        out[i * (16 + DIN) + h] = a;
    }
    if (h < DIN)
        out[i * (16 + DIN) + 16 + h] = xp[i * DIN + h];
}

// ============================================================
extern "C" void kernel_launch(void* const* d_in, const int* in_sizes, int n_in,
                              void* d_out, int out_size)
{
    const float* xp  = (const float*)d_in[0];
    const float* W1  = (const float*)d_in[1];
    const float* b1  = (const float*)d_in[2];
    const float* W2  = (const float*)d_in[3];
    const float* b2  = (const float*)d_in[4];
    const float* W3  = (const float*)d_in[5];
    const float* b3  = (const float*)d_in[6];
    const float* We  = (const float*)d_in[7];
    const float* be  = (const float*)d_in[8];
    const float* Wf1 = (const float*)d_in[9];
    const float* bf1 = (const float*)d_in[10];
    const float* Wf2 = (const float*)d_in[11];
    const float* bf2 = (const float*)d_in[12];
    float* out = (float*)d_out;

    zeroh_kernel<<<1, NBIN>>>();
    mlp_kernel<<<N / 256, 256>>>(xp, W1, b1, W2, b2, W3, b3);
    scan_kernel<<<1, 32>>>();
    scatter_kernel<<<N / 256, 256>>>();
    knn_zig_kernel<<<N / QCTA, 256>>>();
    feats_out_kernel<<<N / 16, 256>>>(xp, We, be, Wf1, bf1, Wf2, bf2, out);
}

// round 14
// speedup vs baseline: 7.3759x; 1.0443x over previous
#include <cuda_runtime.h>
#include <cuda_fp16.h>
#include <math.h>
#include <float.h>
#include <stdint.h>

#define N       16384
#define DIN     13
#define KNN     8
#define NBIN    1024
#define QCTA    64               // sorted queries per CTA
#define CHUNK   128              // j per chunk
#define NCHUNK  (N / CHUNK)      // 128
#define NTILE   (CHUNK / 8)      // 16 tiles per chunk
#define NTILES  (N / 8)          // 2048 global tiles
#define NLIST   8                // 4 t4-slices x 2 tile-halves
#define EPSA    1e-3f            // abs margin on d2 threshold (MMA approx)
#define SLACK   0.02f            // key slack for chunk bounds (> bin width)

typedef unsigned long long ull;

// ---- scratch (no allocs allowed) ----
__device__ float  g_x[N * 16];            // embedded points (original order)
__device__ float  g_sq[N];
__device__ float  g_key[N];
__device__ int    g_hist[NBIN];
__device__ int    g_off[NBIN];
__device__ float  g_pkey[N];              // sorted keys
__device__ float  g_psq[N];               // sorted sq
__device__ int    g_pidx[N];              // sorted pos -> original index
__device__ __half g_ah[N * 16];           // sorted fp16 hi of -2x
__device__ __half g_am[N * 16];           // sorted fp16 mid of -2x
__device__ uint4  g_bf[NCHUNK * NTILE * 32]; // sorted B fragments
__device__ float  g_clo[NCHUNK], g_chi[NCHUNK];
__device__ float  g_tlo[NTILES], g_thi[NTILES];
__device__ int    g_idx[N * KNN];         // final knn (original indices)

__device__ __forceinline__ float silu_f(float v) { return v / (1.0f + expf(-v)); }
__device__ __forceinline__ float silu_fast(float v) { return __fdividef(v, 1.0f + __expf(-v)); }
__device__ __forceinline__ int keybin(float k) {
    int b = (int)((k + 5.0f) * (NBIN / 10.0f));
    return b < 0 ? 0 : (b > NBIN - 1 ? NBIN - 1 : b);
}
__device__ __forceinline__ uint32_t smem_u32(const void* p) {
    uint32_t a;
    asm("{ .reg .u64 t; cvta.to.shared.u64 t, %1; cvt.u32.u64 %0, t; }"
        : "=r"(a) : "l"(p));
    return a;
}
__device__ __forceinline__ void cp_async16(uint32_t saddr, const void* g) {
    asm volatile("cp.async.cg.shared.global [%0], [%1], 16;" :: "r"(saddr), "l"(g));
}
#define CP_COMMIT() asm volatile("cp.async.commit_group;" ::: "memory")
#define CP_WAIT0()  asm volatile("cp.async.wait_group 0;" ::: "memory")

// sortable uint from float (ascending uint == ascending float, any sign)
__device__ __forceinline__ uint32_t fkey(float f) {
    uint32_t u = __float_as_uint(f);
    return u ^ ((u >> 31) ? 0xFFFFFFFFu : 0x80000000u);
}

// m16n8k16 fp16 mma, fp32 accumulate (PTX sm_80+, valid under compute_103)
__device__ __forceinline__ void mma_f16(float& c0, float& c1, float& c2, float& c3,
                                        uint32_t a0, uint32_t a1, uint32_t a2, uint32_t a3,
                                        uint32_t b0, uint32_t b1) {
    asm volatile(
        "mma.sync.aligned.m16n8k16.row.col.f32.f16.f16.f32 "
        "{%0,%1,%2,%3}, {%4,%5,%6,%7}, {%8,%9}, {%0,%1,%2,%3};"
        : "+f"(c0), "+f"(c1), "+f"(c2), "+f"(c3)
        : "r"(a0), "r"(a1), "r"(a2), "r"(a3), "r"(b0), "r"(b1));
}

__device__ __forceinline__ void ins8(float* td, int* ti, float d, int j) {
    if (d < td[KNN - 1]) {
        td[KNN - 1] = d; ti[KNN - 1] = j;
        #pragma unroll
        for (int s = KNN - 1; s >= 1; --s) {
            if (td[s] < td[s - 1] || (td[s] == td[s - 1] && ti[s] < ti[s - 1])) {
                float tf = td[s]; td[s] = td[s-1]; td[s-1] = tf;
                int   tn = ti[s]; ti[s] = ti[s-1]; ti[s-1] = tn;
            }
        }
    }
}

// ============================================================
// Kernel 0: zero histogram
// ============================================================
__global__ void zeroh_kernel() { g_hist[threadIdx.x] = 0; }

// ============================================================
// Kernel 1: per-point MLP -> x, sq, key + histogram (fused)
// ============================================================
__global__ void mlp_kernel(const float* __restrict__ xp,
                           const float* __restrict__ W1, const float* __restrict__ b1,
                           const float* __restrict__ W2, const float* __restrict__ b2,
                           const float* __restrict__ W3, const float* __restrict__ b3)
{
    __shared__ float sW1[DIN * 8], sb1[8];
    __shared__ float sW2[8 * 16],  sb2[16];
    __shared__ float sW3[16 * 15], sb3[15];

    int t = threadIdx.x;
    for (int i = t; i < DIN * 8; i += blockDim.x) sW1[i] = W1[i];
    for (int i = t; i < 8;       i += blockDim.x) sb1[i] = b1[i];
    for (int i = t; i < 8 * 16;  i += blockDim.x) sW2[i] = W2[i];
    for (int i = t; i < 16;      i += blockDim.x) sb2[i] = b2[i];
    for (int i = t; i < 16 * 15; i += blockDim.x) sW3[i] = W3[i];
    for (int i = t; i < 15;      i += blockDim.x) sb3[i] = b3[i];
    __syncthreads();

    int i = blockIdx.x * blockDim.x + t;
    if (i >= N) return;

    float in[DIN];
    #pragma unroll
    for (int d = 0; d < DIN; ++d) in[d] = xp[i * DIN + d];

    float h1[8];
    #pragma unroll
    for (int h = 0; h < 8; ++h) {
        float a = sb1[h];
        #pragma unroll
        for (int d = 0; d < DIN; ++d) a = fmaf(in[d], sW1[d * 8 + h], a);
        h1[h] = silu_f(a);
    }
    float h2[16];
    #pragma unroll
    for (int h = 0; h < 16; ++h) {
        float a = sb2[h];
        #pragma unroll
        for (int d = 0; d < 8; ++d) a = fmaf(h1[d], sW2[d * 16 + h], a);
        h2[h] = silu_f(a);
    }
    float xr[16];
    #pragma unroll
    for (int h = 0; h < 15; ++h) {
        float a = sb3[h];
        #pragma unroll
        for (int d = 0; d < 16; ++d) a = fmaf(h2[d], sW3[d * 15 + h], a);
        xr[h] = a;
    }
    xr[15] = in[DIN - 1];

    float s = 0.0f;
    #pragma unroll
    for (int k = 0; k < 16; ++k) s = fmaf(xr[k], xr[k], s);

    #pragma unroll
    for (int k = 0; k < 16; ++k) g_x[i * 16 + k] = xr[k];
    g_sq[i]  = s;
    g_key[i] = xr[15];
    atomicAdd(&g_hist[keybin(xr[15])], 1);
}

// ============================================================
// Kernel 2: single-warp exclusive scan of 1024 bins
// ============================================================
__global__ void scan_kernel() {
    int lane = threadIdx.x;     // 32 threads
    int base = lane * 32;
    int vals[32];
    int sum = 0;
    #pragma unroll
    for (int i = 0; i < 32; ++i) { vals[i] = g_hist[base + i]; sum += vals[i]; }
    int inc = sum;
    #pragma unroll
    for (int d = 1; d < 32; d <<= 1) {
        int o = __shfl_up_sync(0xffffffffu, inc, d);
        if (lane >= d) inc += o;
    }
    int run = inc - sum;   // exclusive offset of this lane's block
    #pragma unroll
    for (int i = 0; i < 32; ++i) { g_off[base + i] = run; run += vals[i]; }
}

// ============================================================
// Kernel 3: scatter + sorted A splits (vectorized) + B fragments
// ============================================================
__global__ void scatter_kernel() {
    int i = blockIdx.x * blockDim.x + threadIdx.x;
    float key = g_key[i];
    int b = keybin(key);
    int pos = atomicAdd(&g_off[b], 1);

    float xr[16];
    #pragma unroll
    for (int d = 0; d < 16; ++d) xr[d] = g_x[i * 16 + d];

    g_pkey[pos] = key;
    g_psq[pos]  = g_sq[i];
    g_pidx[pos] = i;

    // fp16 splits of -2x, built in registers, stored as 2+2 uint4
    __half ahv[16], amv[16];
    #pragma unroll
    for (int k = 0; k < 16; ++k) {
        float a = -2.0f * xr[k];
        __half ah = __float2half_rn(a);
        ahv[k] = ah;
        amv[k] = __float2half_rn(a - __half2float(ah));
    }
    {
        const uint4* av = (const uint4*)ahv;
        const uint4* mv = (const uint4*)amv;
        uint4* dsta = (uint4*)&g_ah[(size_t)pos * 16];
        uint4* dstm = (uint4*)&g_am[(size_t)pos * 16];
        dsta[0] = av[0]; dsta[1] = av[1];
        dstm[0] = mv[0]; dstm[1] = mv[1];
    }

    int T = pos >> 3, r = pos & 7;
    #pragma unroll
    for (int c = 0; c < 4; ++c) {
        int cc = 2 * c;
        float v0 = xr[cc], v1 = xr[cc + 1], v2 = xr[cc + 8], v3 = xr[cc + 9];
        __half h0 = __float2half_rn(v0), h1 = __float2half_rn(v1);
        __half h2 = __float2half_rn(v2), h3 = __float2half_rn(v3);
        __half m0 = __float2half_rn(v0 - __half2float(h0));
        __half m1 = __float2half_rn(v1 - __half2float(h1));
        __half m2 = __float2half_rn(v2 - __half2float(h2));
        __half m3 = __float2half_rn(v3 - __half2float(h3));
        uint4 f; __half2 p;
        p = __halves2half2(h0, h1); f.x = *(uint32_t*)&p;
        p = __halves2half2(h2, h3); f.y = *(uint32_t*)&p;
        p = __halves2half2(m0, m1); f.z = *(uint32_t*)&p;
        p = __halves2half2(m2, m3); f.w = *(uint32_t*)&p;
        g_bf[(size_t)T * 32 + r * 4 + c] = f;
    }
}

// ============================================================
// Kernel 3b: tile + chunk key bounds from sorted keys (one block)
// ============================================================
__global__ void bounds_kernel() {
    int t = threadIdx.x;   // 1024
    #pragma unroll
    for (int u = t; u < NTILES; u += 1024) {
        const float* k = g_pkey + (size_t)u * 8;
        float lo = k[0], hi = k[0];
        #pragma unroll
        for (int r = 1; r < 8; ++r) { lo = fminf(lo, k[r]); hi = fmaxf(hi, k[r]); }
        g_tlo[u] = lo; g_thi[u] = hi;
    }
    __syncthreads();
    if (t < NCHUNK) {
        float lo = FLT_MAX, hi = -FLT_MAX;
        #pragma unroll
        for (int r = 0; r < NTILE; ++r) {
            lo = fminf(lo, g_tlo[t * NTILE + r]);
            hi = fmaxf(hi, g_thi[t * NTILE + r]);
        }
        g_clo[t] = lo; g_chi[t] = hi;
    }
}

// ============================================================
// Kernel 4: zigzag-pruned KNN + in-CTA merge
// ============================================================
__global__ void __launch_bounds__(256) knn_zig_kernel()
{
    __shared__ uint4 sBf[2][NTILE * 32];   // 2 x 8KB
    __shared__ float ssq[2][CHUNK];
    __shared__ int   sjd[2][CHUNK];
    __shared__ ull   smerge[QCTA * NLIST * KNN];   // 32KB

    const int t    = threadIdx.x;
    const int lane = t & 31;
    const int w    = t >> 5;
    const int qg   = w & 3;
    const int jh   = w >> 2;            // tile-half 0/1
    const int gid  = lane >> 2;
    const int t4   = lane & 3;
    const int b    = blockIdx.x;
    const int p0   = b * QCTA + qg * 16 + gid;   // sorted query rows
    const int p1   = p0 + 8;

    uint32_t ah[4], am[4];
    {
        const __half* A0h = g_ah + (size_t)p0 * 16;
        const __half* A1h = g_ah + (size_t)p1 * 16;
        const __half* A0m = g_am + (size_t)p0 * 16;
        const __half* A1m = g_am + (size_t)p1 * 16;
        ah[0] = *(const uint32_t*)&A0h[2 * t4];
        ah[1] = *(const uint32_t*)&A1h[2 * t4];
        ah[2] = *(const uint32_t*)&A0h[2 * t4 + 8];
        ah[3] = *(const uint32_t*)&A1h[2 * t4 + 8];
        am[0] = *(const uint32_t*)&A0m[2 * t4];
        am[1] = *(const uint32_t*)&A1m[2 * t4];
        am[2] = *(const uint32_t*)&A0m[2 * t4 + 8];
        am[3] = *(const uint32_t*)&A1m[2 * t4 + 8];
    }
    const float qk0 = g_pkey[p0], qk1 = g_pkey[p1];
    const float sq0 = g_psq[p0],  sq1 = g_psq[p1];

    float td0[KNN], td1[KNN];
    int   ti0[KNN], ti1[KNN];
    #pragma unroll
    for (int k = 0; k < KNN; ++k) {
        td0[k] = FLT_MAX; ti0[k] = 0x7fffffff;
        td1[k] = FLT_MAX; ti1[k] = 0x7fffffff;
    }

    uint32_t sB_addr[2], sq_addr[2], sj_addr[2];
    #pragma unroll
    for (int u = 0; u < 2; ++u) {
        sB_addr[u] = smem_u32(&sBf[u][0]);
        sq_addr[u] = smem_u32(&ssq[u][0]);
        sj_addr[u] = smem_u32(&sjd[u][0]);
    }

    auto stage = [&](int bf, int c) {
        const uint4* src = g_bf + (size_t)c * (NTILE * 32);
        cp_async16(sB_addr[bf] + (uint32_t)t * 16, src + t);
        cp_async16(sB_addr[bf] + (uint32_t)(t + 256) * 16, src + t + 256);
        if (t < 32) {
            cp_async16(sq_addr[bf] + (uint32_t)t * 16, (const float4*)(g_psq + c * CHUNK) + t);
            cp_async16(sj_addr[bf] + (uint32_t)t * 16, (const int4*)(g_pidx + c * CHUNK) + t);
        }
        CP_COMMIT();
    };

    const int h0 = b >> 1;
    int nxtR = h0 + 1, nxtL = h0 - 1;
    int aliveR = 1, aliveL = 1, tog = 0;
    int cur = h0, bufA = 0;

    stage(0, h0);
    CP_WAIT0();
    __syncthreads();

    while (cur >= 0) {
        int pred = -1;
        {
            int aR = aliveR && (nxtR < NCHUNK);
            int aL = aliveL && (nxtL >= 0);
            if (aR && aL) pred = (tog == 0) ? nxtR : nxtL;
            else if (aR)  pred = nxtR;
            else if (aL)  pred = nxtL;
        }
        if (pred >= 0) stage(bufA ^ 1, pred);

        #pragma unroll
        for (int nt = 0; nt < 8; ++nt) {
            const int tl = jh * 8 + nt;
            const int gt = cur * NTILE + tl;

            float tlo = g_tlo[gt], thi = g_thi[gt];
            float gp0 = fmaxf(fmaxf(tlo - qk0, qk0 - thi), 0.0f);
            float gp1 = fmaxf(fmaxf(tlo - qk1, qk1 - thi), 0.0f);
            int nd = (gp0 * gp0 <= td0[KNN - 1] + sq0 + EPSA) ||
                     (gp1 * gp1 <= td1[KNN - 1] + sq1 + EPSA);
            if (!__any_sync(0xffffffffu, nd)) continue;

            uint4 f = sBf[bufA][tl * 32 + lane];
            const int jl = tl * 8 + 2 * t4;
            float2 s2 = *(const float2*)&ssq[bufA][jl];
            float c0 = s2.x, c1 = s2.y, c2 = s2.x, c3 = s2.y;
            mma_f16(c0, c1, c2, c3, ah[0], ah[1], ah[2], ah[3], f.x, f.y);
            mma_f16(c0, c1, c2, c3, ah[0], ah[1], ah[2], ah[3], f.z, f.w);
            mma_f16(c0, c1, c2, c3, am[0], am[1], am[2], am[3], f.x, f.y);
            if (fminf(c0, c1) < td0[KNN - 1]) {
                ins8(td0, ti0, c0, sjd[bufA][jl]); ins8(td0, ti0, c1, sjd[bufA][jl + 1]);
            }
            if (fminf(c2, c3) < td1[KNN - 1]) {
                ins8(td1, ti1, c2, sjd[bufA][jl]); ins8(td1, ti1, c3, sjd[bufA][jl + 1]);
            }
        }

        cur = -1;
        while (aliveR || aliveL) {
            int dir;
            if (aliveR && aliveL) { dir = tog; tog ^= 1; }
            else dir = aliveR ? 0 : 1;
            int c = (dir == 0) ? nxtR : nxtL;
            if (c < 0 || c >= NCHUNK) {
                if (dir == 0) aliveR = 0; else aliveL = 0;
                continue;
            }
            float bnd = (dir == 0) ? g_clo[c] : g_chi[c];
            float gp0 = (dir == 0) ? bnd - qk0 : qk0 - bnd;
            float gp1 = (dir == 0) ? bnd - qk1 : qk1 - bnd;
            gp0 = fmaxf(gp0 - SLACK, 0.0f);
            gp1 = fmaxf(gp1 - SLACK, 0.0f);
            float th0 = td0[KNN - 1] + sq0 + EPSA;
            float th1 = td1[KNN - 1] + sq1 + EPSA;
            int nd = (gp0 * gp0 <= th0) || (gp1 * gp1 <= th1);
            if (__syncthreads_or(nd)) {
                cur = c;
                if (dir == 0) nxtR++; else nxtL--;
                break;
            } else {
                if (dir == 0) aliveR = 0; else aliveL = 0;
            }
        }

        if (cur >= 0) {
            CP_WAIT0();
            __syncthreads();
            if (cur != pred) {
                stage(bufA ^ 1, cur);
                CP_WAIT0();
                __syncthreads();
            }
            bufA ^= 1;
        }
    }
    CP_WAIT0();

    // ---- in-CTA merge ----
    {
        const int li = jh * 4 + t4;
        const int q0l = qg * 16 + gid;
        const int q1l = q0l + 8;
        #pragma unroll
        for (int k = 0; k < KNN; ++k) {
            smerge[(q0l * NLIST + li) * KNN + k] = ((ull)fkey(td0[k]) << 32) | (uint32_t)ti0[k];
            smerge[(q1l * NLIST + li) * KNN + k] = ((ull)fkey(td1[k]) << 32) | (uint32_t)ti1[k];
        }
    }
    __syncthreads();

    #pragma unroll
    for (int pass = 0; pass < 2; ++pass) {
        int u  = pass * 256 + t;
        int q  = u >> 3;
        int l  = u & 7;
        ull v[KNN];
        #pragma unroll
        for (int k = 0; k < KNN; ++k)
            v[k] = smerge[(q * NLIST + l) * KNN + k];
        int oi = g_pidx[b * QCTA + q];
        #pragma unroll
        for (int k = 0; k < KNN; ++k) {
            ull m = v[0];
            #pragma unroll
            for (int x = 1; x < KNN; ++x) m = (v[x] < m) ? v[x] : m;
            #pragma unroll
            for (int off = 1; off < 8; off <<= 1) {
                ull o = __shfl_xor_sync(0xffffffffu, m, off, 8);
                m = (o < m) ? o : m;
            }
            if (l == 0)
                g_idx[oi * KNN + k] = (int)(uint32_t)(m & 0xffffffffull);
            #pragma unroll
            for (int x = 0; x < KNN; ++x)
                if (v[x] == m) v[x] = ~0ull;
        }
    }
}

// ============================================================
// Kernel 5: fused edge messages + mean + out MLP + concat
// ============================================================
__global__ void __launch_bounds__(256)
feats_out_kernel(const float* __restrict__ xp,
                 const float* __restrict__ We,  const float* __restrict__ be,
                 const float* __restrict__ Wf1, const float* __restrict__ bf1,
                 const float* __restrict__ Wf2, const float* __restrict__ bf2,
                 float* __restrict__ out)
{
    __shared__ float sWd[16 * 16];
    __shared__ float sWb[16 * 16];
    __shared__ float sbe[16];
    __shared__ float sWf1[16 * 32], sbf1[32];
    __shared__ float sWf2[32 * 16], sbf2[16];
    __shared__ float sxi[16 * 16];
    __shared__ int   sj[16 * KNN];
    __shared__ float sxj[16 * KNN * 16];
    __shared__ float sfe[16 * 16];
    __shared__ float sf1[16 * 32];

    const int t  = threadIdx.x;
    const int i0 = blockIdx.x * 16;

    {
        float top = We[t];
        float bot = We[256 + t];
        sWd[t] = top - bot;
        sWb[t] = bot;
    }
    if (t < 16) sbe[t] = be[t];
    for (int u = t; u < 16 * 32; u += 256) sWf1[u] = Wf1[u];
    if (t < 32) sbf1[t] = bf1[t];
    for (int u = t; u < 32 * 16; u += 256) sWf2[u] = Wf2[u];
    if (t < 16) sbf2[t] = bf2[t];
    sxi[t] = g_x[i0 * 16 + t];
    if (t < 16 * KNN) sj[t] = g_idx[i0 * KNN + t];
    __syncthreads();

    {
        const float4* gx4 = (const float4*)g_x;
        float4* sxj4 = (float4*)sxj;
        #pragma unroll
        for (int u = t; u < 16 * KNN * 4; u += 256) {
            int row = u >> 2, seg = u & 3;
            sxj4[u] = gx4[sj[row] * 4 + seg];
        }
    }
    __syncthreads();

    const int p = t >> 4;
    const int h = t & 15;
    const int i = i0 + p;

    float pre = sbe[h];
    #pragma unroll
    for (int d = 0; d < 16; ++d) pre = fmaf(sxi[p * 16 + d], sWd[d * 16 + h], pre);

    float fsum = 0.0f;
    #pragma unroll
    for (int k = 0; k < KNN; ++k) {
        const float* xj = sxj + (p * KNN + k) * 16;
        float m = pre;
        #pragma unroll
        for (int d = 0; d < 16; ++d) m = fmaf(xj[d], sWb[d * 16 + h], m);
        fsum += silu_fast(m);
    }
    sfe[p * 16 + h] = fsum * 0.125f;
    __syncthreads();

    {
        float a0 = sbf1[h], a1 = sbf1[h + 16];
        #pragma unroll
        for (int d = 0; d < 16; ++d) {
            float fe = sfe[p * 16 + d];
            a0 = fmaf(fe, sWf1[d * 32 + h], a0);
            a1 = fmaf(fe, sWf1[d * 32 + h + 16], a1);
        }
        sf1[p * 32 + h]      = silu_fast(a0);
        sf1[p * 32 + h + 16] = silu_fast(a1);
    }
    __syncthreads();

    {
        float a = sbf2[h];
        #pragma unroll
        for (int d = 0; d < 32; ++d) a = fmaf(sf1[p * 32 + d], sWf2[d * 16 + h], a);
        out[i * (16 + DIN) + h] = a;
    }
    if (h < DIN)
        out[i * (16 + DIN) + 16 + h] = xp[i * DIN + h];
}

// ============================================================
extern "C" void kernel_launch(void* const* d_in, const int* in_sizes, int n_in,
                              void* d_out, int out_size)
{
    const float* xp  = (const float*)d_in[0];
    const float* W1  = (const float*)d_in[1];
    const float* b1  = (const float*)d_in[2];
    const float* W2  = (const float*)d_in[3];
    const float* b2  = (const float*)d_in[4];
    const float* W3  = (const float*)d_in[5];
    const float* b3  = (const float*)d_in[6];
    const float* We  = (const float*)d_in[7];
    const float* be  = (const float*)d_in[8];
    const float* Wf1 = (const float*)d_in[9];
    const float* bf1 = (const float*)d_in[10];
    const float* Wf2 = (const float*)d_in[11];
    const float* bf2 = (const float*)d_in[12];
    float* out = (float*)d_out;

    zeroh_kernel<<<1, NBIN>>>();
    mlp_kernel<<<N / 256, 256>>>(xp, W1, b1, W2, b2, W3, b3);
    scan_kernel<<<1, 32>>>();
    scatter_kernel<<<N / 256, 256>>>();
    bounds_kernel<<<1, 1024>>>();
    knn_zig_kernel<<<N / QCTA, 256>>>();
    feats_out_kernel<<<N / 16, 256>>>(xp, We, be, Wf1, bf1, Wf2, bf2, out);
}